// round 2
// baseline (speedup 1.0000x reference)
#include <cuda_runtime.h>
#include <cuda_bf16.h>
#include <math.h>

#define BB 16
#define CC 192
#define HALF 96
#define TLEN 2048
#define FF 256
#define NB 10
#define NJ 29        // 3*NB - 1
#define OUTCH (HALF*NJ)
#define CHG 8        // half-channels per proj block
#define NPAIR (CHG*NJ)   // 232

// Scratch (allocation-free rule: __device__ globals). Layout: [b][t][f].
__device__ float g_h[(size_t)BB*TLEN*FF];
__device__ float g_y[(size_t)BB*TLEN*FF];

__device__ __forceinline__ float gelu_exact(float v){
    return 0.5f * v * (1.f + erff(v * 0.70710678118654752f));
}
__device__ __forceinline__ float softplusf(float v){
    return v > 20.f ? v : log1pf(expf(v));
}

// ---------------------------------------------------------------------------
// Kernel 0: copy x0*mask into out[:, :96, :], zero logdet slots.
// ---------------------------------------------------------------------------
__global__ void k_init(const float* __restrict__ x, const float* __restrict__ mask,
                       float* __restrict__ out){
    long n = (long)BB * HALF * TLEN;
    for (long i = (long)blockIdx.x * blockDim.x + threadIdx.x; i < n;
         i += (long)gridDim.x * blockDim.x){
        int t = (int)(i % TLEN);
        long bc = i / TLEN;
        int c = (int)(bc % HALF);
        int b = (int)(bc / HALF);
        long src = (long)b*CC*TLEN + (long)c*TLEN + t;
        out[src] = x[src] * mask[(long)b*TLEN + t];
    }
    if (blockIdx.x == 0 && threadIdx.x < BB)
        out[(long)BB*CC*TLEN + threadIdx.x] = 0.f;
}

// ---------------------------------------------------------------------------
// Kernel 1: h[b][t][f] = sum_c pre_w[f][c] * x0[b][c][t] + pre_b[f]
// Block: (t-tile of 32, b); 256 threads (one per f).
// ---------------------------------------------------------------------------
__global__ __launch_bounds__(256) void k_pre(const float* __restrict__ x,
                                             const float* __restrict__ pre_w,
                                             const float* __restrict__ pre_b){
    __shared__ float sx[HALF][32];
    int b = blockIdx.y;
    int t0 = blockIdx.x * 32;
    int f = threadIdx.x;

    for (int i = threadIdx.x; i < HALF*32; i += 256){
        int c = i >> 5, tt = i & 31;
        sx[c][tt] = x[(long)b*CC*TLEN + (long)c*TLEN + t0 + tt];
    }
    __syncthreads();

    float acc[32];
    float bv = pre_b[f];
    #pragma unroll
    for (int tt = 0; tt < 32; tt++) acc[tt] = bv;

    const float4* wrow4 = (const float4*)(pre_w + (long)f*HALF);
    #pragma unroll 4
    for (int c4 = 0; c4 < HALF/4; c4++){
        float4 wq = wrow4[c4];
        #pragma unroll
        for (int s = 0; s < 4; s++){
            float w = (s==0)?wq.x:(s==1)?wq.y:(s==2)?wq.z:wq.w;
            int c = c4*4 + s;
            const float4* r4 = (const float4*)&sx[c][0];
            #pragma unroll
            for (int q = 0; q < 8; q++){
                float4 v = r4[q];
                acc[4*q+0] = fmaf(w, v.x, acc[4*q+0]);
                acc[4*q+1] = fmaf(w, v.y, acc[4*q+1]);
                acc[4*q+2] = fmaf(w, v.z, acc[4*q+2]);
                acc[4*q+3] = fmaf(w, v.w, acc[4*q+3]);
            }
        }
    }
    #pragma unroll
    for (int tt = 0; tt < 32; tt++)
        g_h[((long)b*TLEN + t0 + tt)*FF + f] = acc[tt];
}

// ---------------------------------------------------------------------------
// Kernel 2 (per layer): depthwise dilated conv on h*mask + channel_norm + GELU
// Block: one (b,t) column; 256 threads (one per f).
// ---------------------------------------------------------------------------
__global__ __launch_bounds__(256) void k_convnorm(const float* __restrict__ mask,
                                                  const float* __restrict__ dw_w,
                                                  const float* __restrict__ dw_b,
                                                  const float* __restrict__ gamma,
                                                  const float* __restrict__ beta,
                                                  int dil){
    int t = blockIdx.x, b = blockIdx.y, f = threadIdx.x;
    long base = (long)b*TLEN*FF;

    float vl = 0.f, vr = 0.f;
    float vc = g_h[base + (long)t*FF + f] * mask[(long)b*TLEN + t];
    if (t - dil >= 0)    vl = g_h[base + (long)(t-dil)*FF + f] * mask[(long)b*TLEN + t - dil];
    if (t + dil < TLEN)  vr = g_h[base + (long)(t+dil)*FF + f] * mask[(long)b*TLEN + t + dil];

    float w0 = dw_w[f*3+0], w1 = dw_w[f*3+1], w2 = dw_w[f*3+2];
    float v = fmaf(w0, vl, fmaf(w1, vc, fmaf(w2, vr, dw_b[f])));

    // block mean/var over 256 channels
    float s = v, sq = v*v;
    #pragma unroll
    for (int o = 16; o; o >>= 1){
        s  += __shfl_xor_sync(0xFFFFFFFFu, s,  o);
        sq += __shfl_xor_sync(0xFFFFFFFFu, sq, o);
    }
    __shared__ float ss[8], ssq[8];
    int w = threadIdx.x >> 5, l = threadIdx.x & 31;
    if (l == 0){ ss[w] = s; ssq[w] = sq; }
    __syncthreads();
    s = 0.f; sq = 0.f;
    #pragma unroll
    for (int k = 0; k < 8; k++){ s += ss[k]; sq += ssq[k]; }

    float mean = s * (1.f/FF);
    float var  = sq * (1.f/FF) - mean*mean;
    float rstd = rsqrtf(var + 1e-5f);
    float nv = (v - mean) * rstd * gamma[f] + beta[f];
    g_y[base + (long)t*FF + f] = gelu_exact(nv);
}

// ---------------------------------------------------------------------------
// Kernel 3 (per layer): y2 = pw_w @ y + pw_b; channel_norm; GELU; h += y2
// Block: (t-tile of 32, b); 256 threads (one per output channel o).
// ---------------------------------------------------------------------------
__global__ __launch_bounds__(256) void k_pw(const float* __restrict__ pw_w,
                                            const float* __restrict__ pw_b,
                                            const float* __restrict__ gamma,
                                            const float* __restrict__ beta){
    __shared__ float sy[FF][36];           // padded: LDS.128-aligned rows
    __shared__ float smean[32], srstd[32];
    int b = blockIdx.y;
    int t0 = blockIdx.x * 32;
    int o = threadIdx.x;
    long base = ((long)b*TLEN + t0) * FF;

    for (int i = threadIdx.x; i < FF*32; i += 256){
        int c = i & 255, tt = i >> 8;
        sy[c][tt] = g_y[base + (long)tt*FF + c];
    }
    __syncthreads();

    float acc[32];
    float bv = pw_b[o];
    #pragma unroll
    for (int tt = 0; tt < 32; tt++) acc[tt] = bv;

    const float4* wrow4 = (const float4*)(pw_w + (long)o*FF);
    for (int c4 = 0; c4 < FF/4; c4++){
        float4 wq = wrow4[c4];
        #pragma unroll
        for (int s = 0; s < 4; s++){
            float w = (s==0)?wq.x:(s==1)?wq.y:(s==2)?wq.z:wq.w;
            int c = c4*4 + s;
            const float4* r4 = (const float4*)&sy[c][0];
            #pragma unroll
            for (int q = 0; q < 8; q++){
                float4 v = r4[q];
                acc[4*q+0] = fmaf(w, v.x, acc[4*q+0]);
                acc[4*q+1] = fmaf(w, v.y, acc[4*q+1]);
                acc[4*q+2] = fmaf(w, v.z, acc[4*q+2]);
                acc[4*q+3] = fmaf(w, v.w, acc[4*q+3]);
            }
        }
    }
    __syncthreads();

    float* buf = &sy[0][0];                // alias: [t][o], 32*256 floats
    #pragma unroll
    for (int tt = 0; tt < 32; tt++) buf[tt*FF + o] = acc[tt];
    __syncthreads();

    int w = o >> 5, l = o & 31;
    for (int tt = w*4; tt < w*4 + 4; tt++){
        float s = 0.f, sq = 0.f;
        #pragma unroll
        for (int k = 0; k < 8; k++){
            float v = buf[tt*FF + l + k*32];
            s += v; sq += v*v;
        }
        #pragma unroll
        for (int off = 16; off; off >>= 1){
            s  += __shfl_xor_sync(0xFFFFFFFFu, s,  off);
            sq += __shfl_xor_sync(0xFFFFFFFFu, sq, off);
        }
        if (l == 0){
            float mean = s * (1.f/FF);
            smean[tt] = mean;
            srstd[tt] = rsqrtf(sq * (1.f/FF) - mean*mean + 1e-5f);
        }
    }
    __syncthreads();

    float gv = gamma[o], bev = beta[o];
    #pragma unroll
    for (int tt = 0; tt < 32; tt++){
        float nv = (buf[tt*FF + o] - smean[tt]) * srstd[tt] * gv + bev;
        g_h[base + (long)tt*FF + o] += gelu_exact(nv);
    }
}

// ---------------------------------------------------------------------------
// Kernel 4: fused proj (256 -> 29 per half-channel) + RQ spline + logdet
// Block: (t-tile 32, ch-group of 8, b); 256 threads.
// Phase A: 232 threads each own one (ch_l, j) pair, accumulate over all 256 c.
// Phase B: 256 threads each own one (ch_l, t), evaluate spline.
// Dynamic smem: shm[256][36] | spw[232*33] | smask[32] | sred[8]
// ---------------------------------------------------------------------------
__global__ __launch_bounds__(256) void k_proj(const float* __restrict__ x,
                                              const float* __restrict__ mask,
                                              const float* __restrict__ proj_w,
                                              const float* __restrict__ proj_b,
                                              float* __restrict__ out){
    extern __shared__ float sm[];
    float (*shm)[36] = (float(*)[36])sm;        // 256*36
    float* spw   = sm + FF*36;                  // 232*33 (later aliased as u-buf)
    float* smask = spw + NPAIR*33;              // 32
    float* sred  = smask + 32;                  // 8

    int b  = blockIdx.z;
    int g  = blockIdx.y;
    int t0 = blockIdx.x * 32;
    int ch0 = g * CHG;
    int tid = threadIdx.x;

    if (tid < 32) smask[tid] = mask[(long)b*TLEN + t0 + tid];
    for (int i = tid; i < FF*32; i += 256){
        int c = i & 255, tt = i >> 8;
        shm[c][tt] = g_h[((long)b*TLEN + t0 + tt)*FF + c] * mask[(long)b*TLEN + t0 + tt];
    }
    __syncthreads();

    float acc[32];
    #pragma unroll
    for (int tt = 0; tt < 32; tt++) acc[tt] = 0.f;
    int p = tid;  // pair = ch_l*29 + j

    for (int c0 = 0; c0 < FF; c0 += 32){
        for (int i = tid; i < NPAIR*32; i += 256){
            int pp = i >> 5, cc = i & 31;
            spw[pp*33 + cc] = proj_w[((long)(ch0*NJ + pp))*FF + c0 + cc];
        }
        __syncthreads();
        if (p < NPAIR){
            #pragma unroll 8
            for (int cc = 0; cc < 32; cc++){
                float w = spw[p*33 + cc];
                const float4* r4 = (const float4*)&shm[c0 + cc][0];
                #pragma unroll
                for (int q = 0; q < 8; q++){
                    float4 v = r4[q];
                    acc[4*q+0] = fmaf(w, v.x, acc[4*q+0]);
                    acc[4*q+1] = fmaf(w, v.y, acc[4*q+1]);
                    acc[4*q+2] = fmaf(w, v.z, acc[4*q+2]);
                    acc[4*q+3] = fmaf(w, v.w, acc[4*q+3]);
                }
            }
        }
        __syncthreads();
    }

    // spw now dead -> reuse as u-buffer: buf[(ch_l*29+j)*33 + t]
    float* buf = spw;
    if (p < NPAIR){
        float pb = proj_b[ch0*NJ + p];
        #pragma unroll
        for (int tt = 0; tt < 32; tt++)
            buf[p*33 + tt] = (acc[tt] + pb) * smask[tt];
    }
    __syncthreads();

    // --- Phase B: spline ---
    const float SCALE = 0.0625f;  // 1/sqrt(256)
    int ch_l = tid >> 5, tl = tid & 31;
    int ch = ch0 + ch_l;
    float x1v = x[(long)b*CC*TLEN + (long)(HALF + ch)*TLEN + t0 + tl];
    float mv  = smask[tl];
    const float* ub = buf + (ch_l*NJ)*33 + tl;  // ub[j*33] = u_j

    // widths -> cw[0..10]
    float uw[10];
    #pragma unroll
    for (int j = 0; j < 10; j++) uw[j] = ub[j*33] * SCALE;
    float mx = uw[0];
    #pragma unroll
    for (int j = 1; j < 10; j++) mx = fmaxf(mx, uw[j]);
    float ew[10]; float sw = 0.f;
    #pragma unroll
    for (int j = 0; j < 10; j++){ ew[j] = expf(uw[j] - mx); sw += ew[j]; }
    float cw[11]; cw[0] = -5.f;
    {
        float inv = 1.f / sw, cs = 0.f;
        #pragma unroll
        for (int j = 0; j < 9; j++){
            cs += fmaf(0.99f, ew[j]*inv, 0.001f);
            cw[j+1] = fmaf(10.f, cs, -5.f);
        }
        cw[10] = 5.f;
    }
    // heights -> chh[0..10]
    #pragma unroll
    for (int j = 0; j < 10; j++) uw[j] = ub[(10+j)*33] * SCALE;
    mx = uw[0];
    #pragma unroll
    for (int j = 1; j < 10; j++) mx = fmaxf(mx, uw[j]);
    sw = 0.f;
    #pragma unroll
    for (int j = 0; j < 10; j++){ ew[j] = expf(uw[j] - mx); sw += ew[j]; }
    float chh[11]; chh[0] = -5.f;
    {
        float inv = 1.f / sw, cs = 0.f;
        #pragma unroll
        for (int j = 0; j < 9; j++){
            cs += fmaf(0.99f, ew[j]*inv, 0.001f);
            chh[j+1] = fmaf(10.f, cs, -5.f);
        }
        chh[10] = 5.f;
    }

    float xc = fminf(fmaxf(x1v, -5.f), 5.f);
    int idx = 0;
    #pragma unroll
    for (int j = 1; j <= 9; j++) idx += (xc >= cw[j]) ? 1 : 0;

    float cwl = cw[0], cwr = cw[1], chl = chh[0], chr = chh[1];
    #pragma unroll
    for (int j = 1; j < 10; j++){
        if (idx == j){ cwl = cw[j]; cwr = cw[j+1]; chl = chh[j]; chr = chh[j+1]; }
    }
    float d0 = (idx == 0) ? 1.f : 0.001f + softplusf(ub[(19 + idx)*33]);
    float d1 = (idx == 9) ? 1.f : 0.001f + softplusf(ub[(20 + idx)*33]);

    float wb = cwr - cwl, hb = chr - chl;
    float delta = hb / wb;
    float th = (xc - cwl) / wb;
    float omt = 1.f - th;
    float t1m = th * omt;
    float denom = delta + (d0 + d1 - 2.f*delta) * t1m;
    float num = hb * (delta*th*th + d0*t1m);
    float yv = chl + num / denom;
    float dnum = delta*delta * (d1*th*th + 2.f*delta*t1m + d0*omt*omt);
    float lad = logf(dnum) - 2.f*logf(denom);

    bool inside = (x1v >= -5.f) && (x1v <= 5.f);
    float ov = inside ? yv : x1v;
    float lv = (inside ? lad : 0.f) * mv;

    out[(long)b*CC*TLEN + (long)(HALF + ch)*TLEN + t0 + tl] = ov * mv;

    // block-reduce lad, atomic into logdet[b]
    #pragma unroll
    for (int off = 16; off; off >>= 1)
        lv += __shfl_xor_sync(0xFFFFFFFFu, lv, off);
    if ((tid & 31) == 0) sred[tid >> 5] = lv;
    __syncthreads();
    if (tid == 0){
        float s = 0.f;
        #pragma unroll
        for (int k = 0; k < 8; k++) s += sred[k];
        atomicAdd(&out[(long)BB*CC*TLEN + b], s);
    }
}

// ---------------------------------------------------------------------------
extern "C" void kernel_launch(void* const* d_in, const int* in_sizes, int n_in,
                              void* d_out, int out_size){
    const float* x      = (const float*)d_in[0];
    const float* mask   = (const float*)d_in[1];
    const float* pre_w  = (const float*)d_in[2];
    const float* pre_b  = (const float*)d_in[3];
    const float* dw_w   = (const float*)d_in[4];
    const float* dw_b   = (const float*)d_in[5];
    const float* pw_w   = (const float*)d_in[6];
    const float* pw_b   = (const float*)d_in[7];
    const float* gamma1 = (const float*)d_in[8];
    const float* beta1  = (const float*)d_in[9];
    const float* gamma2 = (const float*)d_in[10];
    const float* beta2  = (const float*)d_in[11];
    const float* proj_w = (const float*)d_in[12];
    const float* proj_b = (const float*)d_in[13];
    float* out = (float*)d_out;

    const int PROJ_SMEM = (FF*36 + NPAIR*33 + 32 + 8) * (int)sizeof(float);
    cudaFuncSetAttribute(k_proj, cudaFuncAttributeMaxDynamicSharedMemorySize, PROJ_SMEM);

    k_init<<<4096, 256>>>(x, mask, out);
    k_pre<<<dim3(TLEN/32, BB), 256>>>(x, pre_w, pre_b);

    int dil = 1;
    for (int i = 0; i < 3; i++){
        k_convnorm<<<dim3(TLEN, BB), 256>>>(mask,
                                            dw_w + (long)i*FF*3, dw_b + (long)i*FF,
                                            gamma1 + (long)i*FF, beta1 + (long)i*FF, dil);
        k_pw<<<dim3(TLEN/32, BB), 256>>>(pw_w + (long)i*FF*FF, pw_b + (long)i*FF,
                                         gamma2 + (long)i*FF, beta2 + (long)i*FF);
        dil *= 3;
    }

    k_proj<<<dim3(TLEN/32, HALF/CHG, BB), 256, PROJ_SMEM>>>(x, mask, proj_w, proj_b, out);
}

// round 4
// speedup vs baseline: 1.9260x; 1.9260x over previous
#include <cuda_runtime.h>
#include <cuda_bf16.h>
#include <math.h>
#include <cstdint>

#define BB 16
#define CC 192
#define HALF 96
#define TLEN 2048
#define FF 256
#define NB 10
#define NJ 29        // 3*NB - 1

// ---- proj mma tiling ----
#define MROWS 3072   // 96 ch * 32 padded rows
#define MT 128       // m-tile (4 channels)
#define NT 64        // t-tile
#define ASTR 272     // A smem row stride bytes (128 bf16 + 16B pad)
#define BSTR 272
#define USTRIDE 65   // u smem row stride (floats)

#define OFF_AHI 0
#define OFF_ALO 34816
#define OFF_BHI 69632
#define OFF_BLO 87040
#define OFF_MASK 104448
#define OFF_RED 104704
#define PROJ_SMEM_BYTES 104768

// Scratch (allocation-free rule: __device__ globals). Layout: [b][t][f].
__device__ float g_h[(size_t)BB*TLEN*FF];
__device__ float g_y[(size_t)BB*TLEN*FF];
__device__ __nv_bfloat16 g_whi[(size_t)MROWS*FF];
__device__ __nv_bfloat16 g_wlo[(size_t)MROWS*FF];
__device__ __nv_bfloat16 g_hhi[(size_t)BB*TLEN*FF];
__device__ __nv_bfloat16 g_hlo[(size_t)BB*TLEN*FF];

__device__ __forceinline__ float gelu_exact(float v){
    return 0.5f * v * (1.f + erff(v * 0.70710678118654752f));
}
__device__ __forceinline__ float softplusf(float v){
    return v > 20.f ? v : log1pf(expf(v));
}
__device__ __forceinline__ uint32_t smem_u32(const void* p){
    uint32_t a;
    asm("{ .reg .u64 t; cvta.to.shared.u64 t, %1; cvt.u32.u64 %0, t; }" : "=r"(a) : "l"(p));
    return a;
}
__device__ __forceinline__ void ldm4(uint32_t* r, uint32_t addr){
    asm volatile("ldmatrix.sync.aligned.m8n8.x4.shared.b16 {%0,%1,%2,%3}, [%4];"
        : "=r"(r[0]),"=r"(r[1]),"=r"(r[2]),"=r"(r[3]) : "r"(addr));
}
__device__ __forceinline__ void mma_bf16(float* d, const uint32_t* a, uint32_t b0, uint32_t b1){
    asm volatile("mma.sync.aligned.m16n8k16.row.col.f32.bf16.bf16.f32 "
        "{%0,%1,%2,%3}, {%4,%5,%6,%7}, {%8,%9}, {%0,%1,%2,%3};"
        : "+f"(d[0]),"+f"(d[1]),"+f"(d[2]),"+f"(d[3])
        : "r"(a[0]),"r"(a[1]),"r"(a[2]),"r"(a[3]), "r"(b0),"r"(b1));
}

// ---------------------------------------------------------------------------
// Prep: bf16 hi/lo split of proj_w into padded [3072][256] rows (32/channel)
// ---------------------------------------------------------------------------
__global__ void k_prep_w(const float* __restrict__ proj_w){
    long n = (long)MROWS*FF;
    for (long i = (long)blockIdx.x*blockDim.x + threadIdx.x; i < n;
         i += (long)gridDim.x*blockDim.x){
        int k = (int)(i & (FF-1));
        int r = (int)(i >> 8);
        int ch = r >> 5, j = r & 31;
        float w = (j < NJ) ? proj_w[((long)(ch*NJ + j))*FF + k] : 0.f;
        __nv_bfloat16 hi = __float2bfloat16_rn(w);
        g_whi[i] = hi;
        g_wlo[i] = __float2bfloat16_rn(w - __bfloat162float(hi));
    }
}
// Prep: bf16 hi/lo of h*mask
__global__ void k_prep_h(const float* __restrict__ mask){
    long n = (long)BB*TLEN*FF;
    for (long i = (long)blockIdx.x*blockDim.x + threadIdx.x; i < n;
         i += (long)gridDim.x*blockDim.x){
        float v = g_h[i] * mask[i >> 8];
        __nv_bfloat16 hi = __float2bfloat16_rn(v);
        g_hhi[i] = hi;
        g_hlo[i] = __float2bfloat16_rn(v - __bfloat162float(hi));
    }
}

// ---------------------------------------------------------------------------
// Kernel 0: copy x0*mask into out[:, :96, :], zero logdet slots.
// ---------------------------------------------------------------------------
__global__ void k_init(const float* __restrict__ x, const float* __restrict__ mask,
                       float* __restrict__ out){
    long n = (long)BB * HALF * TLEN;
    for (long i = (long)blockIdx.x * blockDim.x + threadIdx.x; i < n;
         i += (long)gridDim.x * blockDim.x){
        int t = (int)(i % TLEN);
        long bc = i / TLEN;
        int c = (int)(bc % HALF);
        int b = (int)(bc / HALF);
        long src = (long)b*CC*TLEN + (long)c*TLEN + t;
        out[src] = x[src] * mask[(long)b*TLEN + t];
    }
    if (blockIdx.x == 0 && threadIdx.x < BB)
        out[(long)BB*CC*TLEN + threadIdx.x] = 0.f;
}

// ---------------------------------------------------------------------------
// Kernel 1: h[b][t][f] = sum_c pre_w[f][c] * x0[b][c][t] + pre_b[f]
// ---------------------------------------------------------------------------
__global__ __launch_bounds__(256) void k_pre(const float* __restrict__ x,
                                             const float* __restrict__ pre_w,
                                             const float* __restrict__ pre_b){
    __shared__ float sx[HALF][32];
    int b = blockIdx.y;
    int t0 = blockIdx.x * 32;
    int f = threadIdx.x;

    for (int i = threadIdx.x; i < HALF*32; i += 256){
        int c = i >> 5, tt = i & 31;
        sx[c][tt] = x[(long)b*CC*TLEN + (long)c*TLEN + t0 + tt];
    }
    __syncthreads();

    float acc[32];
    float bv = pre_b[f];
    #pragma unroll
    for (int tt = 0; tt < 32; tt++) acc[tt] = bv;

    const float4* wrow4 = (const float4*)(pre_w + (long)f*HALF);
    #pragma unroll 4
    for (int c4 = 0; c4 < HALF/4; c4++){
        float4 wq = wrow4[c4];
        #pragma unroll
        for (int s = 0; s < 4; s++){
            float w = (s==0)?wq.x:(s==1)?wq.y:(s==2)?wq.z:wq.w;
            int c = c4*4 + s;
            const float4* r4 = (const float4*)&sx[c][0];
            #pragma unroll
            for (int q = 0; q < 8; q++){
                float4 v = r4[q];
                acc[4*q+0] = fmaf(w, v.x, acc[4*q+0]);
                acc[4*q+1] = fmaf(w, v.y, acc[4*q+1]);
                acc[4*q+2] = fmaf(w, v.z, acc[4*q+2]);
                acc[4*q+3] = fmaf(w, v.w, acc[4*q+3]);
            }
        }
    }
    #pragma unroll
    for (int tt = 0; tt < 32; tt++)
        g_h[((long)b*TLEN + t0 + tt)*FF + f] = acc[tt];
}

// ---------------------------------------------------------------------------
// Kernel 2 (per layer): depthwise dilated conv + channel_norm + GELU
// ---------------------------------------------------------------------------
__global__ __launch_bounds__(256) void k_convnorm(const float* __restrict__ mask,
                                                  const float* __restrict__ dw_w,
                                                  const float* __restrict__ dw_b,
                                                  const float* __restrict__ gamma,
                                                  const float* __restrict__ beta,
                                                  int dil){
    int t = blockIdx.x, b = blockIdx.y, f = threadIdx.x;
    long base = (long)b*TLEN*FF;

    float vl = 0.f, vr = 0.f;
    float vc = g_h[base + (long)t*FF + f] * mask[(long)b*TLEN + t];
    if (t - dil >= 0)    vl = g_h[base + (long)(t-dil)*FF + f] * mask[(long)b*TLEN + t - dil];
    if (t + dil < TLEN)  vr = g_h[base + (long)(t+dil)*FF + f] * mask[(long)b*TLEN + t + dil];

    float w0 = dw_w[f*3+0], w1 = dw_w[f*3+1], w2 = dw_w[f*3+2];
    float v = fmaf(w0, vl, fmaf(w1, vc, fmaf(w2, vr, dw_b[f])));

    float s = v, sq = v*v;
    #pragma unroll
    for (int o = 16; o; o >>= 1){
        s  += __shfl_xor_sync(0xFFFFFFFFu, s,  o);
        sq += __shfl_xor_sync(0xFFFFFFFFu, sq, o);
    }
    __shared__ float ss[8], ssq[8];
    int w = threadIdx.x >> 5, l = threadIdx.x & 31;
    if (l == 0){ ss[w] = s; ssq[w] = sq; }
    __syncthreads();
    s = 0.f; sq = 0.f;
    #pragma unroll
    for (int k = 0; k < 8; k++){ s += ss[k]; sq += ssq[k]; }

    float mean = s * (1.f/FF);
    float var  = sq * (1.f/FF) - mean*mean;
    float rstd = rsqrtf(var + 1e-5f);
    float nv = (v - mean) * rstd * gamma[f] + beta[f];
    g_y[base + (long)t*FF + f] = gelu_exact(nv);
}

// ---------------------------------------------------------------------------
// Kernel 3 (per layer): y2 = pw_w @ y + pw_b; channel_norm; GELU; h += y2
// ---------------------------------------------------------------------------
__global__ __launch_bounds__(256) void k_pw(const float* __restrict__ pw_w,
                                            const float* __restrict__ pw_b,
                                            const float* __restrict__ gamma,
                                            const float* __restrict__ beta){
    __shared__ float sy[FF][36];
    __shared__ float smean[32], srstd[32];
    int b = blockIdx.y;
    int t0 = blockIdx.x * 32;
    int o = threadIdx.x;
    long base = ((long)b*TLEN + t0) * FF;

    for (int i = threadIdx.x; i < FF*32; i += 256){
        int c = i & 255, tt = i >> 8;
        sy[c][tt] = g_y[base + (long)tt*FF + c];
    }
    __syncthreads();

    float acc[32];
    float bv = pw_b[o];
    #pragma unroll
    for (int tt = 0; tt < 32; tt++) acc[tt] = bv;

    const float4* wrow4 = (const float4*)(pw_w + (long)o*FF);
    for (int c4 = 0; c4 < FF/4; c4++){
        float4 wq = wrow4[c4];
        #pragma unroll
        for (int s = 0; s < 4; s++){
            float w = (s==0)?wq.x:(s==1)?wq.y:(s==2)?wq.z:wq.w;
            int c = c4*4 + s;
            const float4* r4 = (const float4*)&sy[c][0];
            #pragma unroll
            for (int q = 0; q < 8; q++){
                float4 v = r4[q];
                acc[4*q+0] = fmaf(w, v.x, acc[4*q+0]);
                acc[4*q+1] = fmaf(w, v.y, acc[4*q+1]);
                acc[4*q+2] = fmaf(w, v.z, acc[4*q+2]);
                acc[4*q+3] = fmaf(w, v.w, acc[4*q+3]);
            }
        }
    }
    __syncthreads();

    float* buf = &sy[0][0];
    #pragma unroll
    for (int tt = 0; tt < 32; tt++) buf[tt*FF + o] = acc[tt];
    __syncthreads();

    int w = o >> 5, l = o & 31;
    for (int tt = w*4; tt < w*4 + 4; tt++){
        float s = 0.f, sq = 0.f;
        #pragma unroll
        for (int k = 0; k < 8; k++){
            float v = buf[tt*FF + l + k*32];
            s += v; sq += v*v;
        }
        #pragma unroll
        for (int off = 16; off; off >>= 1){
            s  += __shfl_xor_sync(0xFFFFFFFFu, s,  off);
            sq += __shfl_xor_sync(0xFFFFFFFFu, sq, off);
        }
        if (l == 0){
            float mean = s * (1.f/FF);
            smean[tt] = mean;
            srstd[tt] = rsqrtf(sq * (1.f/FF) - mean*mean + 1e-5f);
        }
    }
    __syncthreads();

    float gv = gamma[o], bev = beta[o];
    #pragma unroll
    for (int tt = 0; tt < 32; tt++){
        float nv = (buf[tt*FF + o] - smean[tt]) * srstd[tt] * gv + bev;
        g_h[base + (long)tt*FF + o] += gelu_exact(nv);
    }
}

// ---------------------------------------------------------------------------
// Kernel 4: bf16-split GEMM (u = W @ h^T) via ldmatrix + mma.sync, fused with
// the RQ spline. CTA 256 thr / 8 warps (4m x 2n), tile M=128 x N=64, K=256.
// ---------------------------------------------------------------------------
__global__ __launch_bounds__(256) void k_proj_mma(const float* __restrict__ x,
                                                  const float* __restrict__ mask,
                                                  const float* __restrict__ proj_b,
                                                  float* __restrict__ out){
    extern __shared__ char smem[];
    uint32_t sb = smem_u32(smem);
    int tid = threadIdx.x, lane = tid & 31, wid = tid >> 5;
    int t0 = blockIdx.x * NT;
    int mtile = blockIdx.y;
    int b = blockIdx.z;
    int m0 = mtile * MT;
    int ch0 = mtile * 4;

    float* smask = (float*)(smem + OFF_MASK);
    if (tid < NT) smask[tid] = mask[(long)b*TLEN + t0 + tid];

    float acc[2][4][4];
    #pragma unroll
    for (int mt = 0; mt < 2; mt++)
        #pragma unroll
        for (int nt = 0; nt < 4; nt++)
            #pragma unroll
            for (int q = 0; q < 4; q++) acc[mt][nt][q] = 0.f;

    int wm = wid & 3, wn = wid >> 2;
    uint32_t aoff = (uint32_t)((wm*32 + (lane & 15)) * ASTR + ((lane >> 4) * 8) * 2);
    uint32_t aH0 = sb + OFF_AHI + aoff, aH1 = aH0 + 16*ASTR;
    uint32_t aL0 = sb + OFF_ALO + aoff, aL1 = aL0 + 16*ASTR;
    uint32_t boff = (uint32_t)((wn*32 + ((lane >> 4) * 8) + (lane & 7)) * BSTR
                               + ((lane >> 3) & 1) * 16);
    uint32_t bH0 = sb + OFF_BHI + boff, bH1 = bH0 + 16*BSTR;
    uint32_t bL0 = sb + OFF_BLO + boff, bL1 = bL0 + 16*BSTR;

    for (int c = 0; c < 2; c++){
        if (c) __syncthreads();
        // stage A hi/lo: 128 rows x 16 uint4
        for (int i = tid; i < MT*16; i += 256){
            int r = i >> 4, g = i & 15;
            uint32_t off = (uint32_t)(r*ASTR + g*16);
            size_t s4 = ((size_t)(m0 + r))*32 + (size_t)c*16 + g;
            *(uint4*)(smem + OFF_AHI + off) = ((const uint4*)g_whi)[s4];
            *(uint4*)(smem + OFF_ALO + off) = ((const uint4*)g_wlo)[s4];
        }
        // stage B hi/lo: 64 t-rows x 16 uint4
        for (int i = tid; i < NT*16; i += 256){
            int r = i >> 4, g = i & 15;
            uint32_t off = (uint32_t)(r*BSTR + g*16);
            size_t s4 = ((size_t)b*TLEN + t0 + r)*32 + (size_t)c*16 + g;
            *(uint4*)(smem + OFF_BHI + off) = ((const uint4*)g_hhi)[s4];
            *(uint4*)(smem + OFF_BLO + off) = ((const uint4*)g_hlo)[s4];
        }
        __syncthreads();

        #pragma unroll
        for (int k16 = 0; k16 < 8; k16++){
            uint32_t ko = (uint32_t)(k16 * 32);
            uint32_t Ah[2][4], Al[2][4], Bh[2][4], Bl[2][4];
            ldm4(Ah[0], aH0 + ko); ldm4(Ah[1], aH1 + ko);
            ldm4(Al[0], aL0 + ko); ldm4(Al[1], aL1 + ko);
            ldm4(Bh[0], bH0 + ko); ldm4(Bh[1], bH1 + ko);
            ldm4(Bl[0], bL0 + ko); ldm4(Bl[1], bL1 + ko);
            #pragma unroll
            for (int mt = 0; mt < 2; mt++){
                #pragma unroll
                for (int nt = 0; nt < 4; nt++){
                    uint32_t h0 = Bh[nt>>1][(nt&1)*2], h1 = Bh[nt>>1][(nt&1)*2+1];
                    uint32_t l0 = Bl[nt>>1][(nt&1)*2], l1 = Bl[nt>>1][(nt&1)*2+1];
                    mma_bf16(acc[mt][nt], Ah[mt], h0, h1);
                    mma_bf16(acc[mt][nt], Ah[mt], l0, l1);
                    mma_bf16(acc[mt][nt], Al[mt], h0, h1);
                }
            }
        }
    }
    __syncthreads();

    // u -> smem (alias over A region): us[row][t], stride 65 floats
    float* us = (float*)smem;
    #pragma unroll
    for (int mt = 0; mt < 2; mt++){
        #pragma unroll
        for (int nt = 0; nt < 4; nt++){
            int r = wm*32 + mt*16 + (lane >> 2);
            int t = wn*32 + nt*8 + (lane & 3)*2;
            #pragma unroll
            for (int hh = 0; hh < 2; hh++){
                int rr = r + hh*8;
                int j = rr & 31;
                int ch = ch0 + (rr >> 5);
                float pb = (j < NJ) ? proj_b[ch*NJ + j] : 0.f;
                us[rr*USTRIDE + t]     = (acc[mt][nt][2*hh+0] + pb) * smask[t];
                us[rr*USTRIDE + t + 1] = (acc[mt][nt][2*hh+1] + pb) * smask[t+1];
            }
        }
    }
    __syncthreads();

    // --- spline: 4 ch x 64 t = 256 evals, one per thread ---
    const float SCALE = 0.0625f;
    int chl = tid >> 6, tl = tid & 63;
    int ch = ch0 + chl;
    const float* ub = us + (chl*32)*USTRIDE + tl;   // ub[j*USTRIDE]

    float x1v = x[(long)b*CC*TLEN + (long)(HALF + ch)*TLEN + t0 + tl];
    float mv  = smask[tl];

    float uw[10];
    #pragma unroll
    for (int j = 0; j < 10; j++) uw[j] = ub[j*USTRIDE] * SCALE;
    float mx = uw[0];
    #pragma unroll
    for (int j = 1; j < 10; j++) mx = fmaxf(mx, uw[j]);
    float ew[10]; float sw = 0.f;
    #pragma unroll
    for (int j = 0; j < 10; j++){ ew[j] = expf(uw[j] - mx); sw += ew[j]; }
    float cw[11]; cw[0] = -5.f;
    {
        float inv = 1.f / sw, cs = 0.f;
        #pragma unroll
        for (int j = 0; j < 9; j++){
            cs += fmaf(0.99f, ew[j]*inv, 0.001f);
            cw[j+1] = fmaf(10.f, cs, -5.f);
        }
        cw[10] = 5.f;
    }
    #pragma unroll
    for (int j = 0; j < 10; j++) uw[j] = ub[(10+j)*USTRIDE] * SCALE;
    mx = uw[0];
    #pragma unroll
    for (int j = 1; j < 10; j++) mx = fmaxf(mx, uw[j]);
    sw = 0.f;
    #pragma unroll
    for (int j = 0; j < 10; j++){ ew[j] = expf(uw[j] - mx); sw += ew[j]; }
    float chh[11]; chh[0] = -5.f;
    {
        float inv = 1.f / sw, cs = 0.f;
        #pragma unroll
        for (int j = 0; j < 9; j++){
            cs += fmaf(0.99f, ew[j]*inv, 0.001f);
            chh[j+1] = fmaf(10.f, cs, -5.f);
        }
        chh[10] = 5.f;
    }

    float xc = fminf(fmaxf(x1v, -5.f), 5.f);
    int idx = 0;
    #pragma unroll
    for (int j = 1; j <= 9; j++) idx += (xc >= cw[j]) ? 1 : 0;

    float cwl = cw[0], cwr = cw[1], chl2 = chh[0], chr = chh[1];
    #pragma unroll
    for (int j = 1; j < 10; j++){
        if (idx == j){ cwl = cw[j]; cwr = cw[j+1]; chl2 = chh[j]; chr = chh[j+1]; }
    }
    float d0 = (idx == 0) ? 1.f : 0.001f + softplusf(ub[(19 + idx)*USTRIDE]);
    float d1 = (idx == 9) ? 1.f : 0.001f + softplusf(ub[(20 + idx)*USTRIDE]);

    float wb = cwr - cwl, hb = chr - chl2;
    float delta = hb / wb;
    float th = (xc - cwl) / wb;
    float omt = 1.f - th;
    float t1m = th * omt;
    float denom = delta + (d0 + d1 - 2.f*delta) * t1m;
    float num = hb * (delta*th*th + d0*t1m);
    float yv = chl2 + num / denom;
    float dnum = delta*delta * (d1*th*th + 2.f*delta*t1m + d0*omt*omt);
    float lad = logf(dnum) - 2.f*logf(denom);

    bool inside = (x1v >= -5.f) && (x1v <= 5.f);
    float ov = inside ? yv : x1v;
    float ldsum = (inside ? lad : 0.f) * mv;

    out[(long)b*CC*TLEN + (long)(HALF + ch)*TLEN + t0 + tl] = ov * mv;

    // logdet reduction
    #pragma unroll
    for (int off = 16; off; off >>= 1)
        ldsum += __shfl_xor_sync(0xFFFFFFFFu, ldsum, off);
    float* sred = (float*)(smem + OFF_RED);
    if (lane == 0) sred[wid] = ldsum;
    __syncthreads();
    if (tid == 0){
        float s = 0.f;
        #pragma unroll
        for (int k = 0; k < 8; k++) s += sred[k];
        atomicAdd(&out[(long)BB*CC*TLEN + b], s);
    }
}

// ---------------------------------------------------------------------------
extern "C" void kernel_launch(void* const* d_in, const int* in_sizes, int n_in,
                              void* d_out, int out_size){
    const float* x      = (const float*)d_in[0];
    const float* mask   = (const float*)d_in[1];
    const float* pre_w  = (const float*)d_in[2];
    const float* pre_b  = (const float*)d_in[3];
    const float* dw_w   = (const float*)d_in[4];
    const float* dw_b   = (const float*)d_in[5];
    const float* pw_w   = (const float*)d_in[6];
    const float* pw_b   = (const float*)d_in[7];
    const float* gamma1 = (const float*)d_in[8];
    const float* beta1  = (const float*)d_in[9];
    const float* gamma2 = (const float*)d_in[10];
    const float* beta2  = (const float*)d_in[11];
    const float* proj_w = (const float*)d_in[12];
    const float* proj_b = (const float*)d_in[13];
    float* out = (float*)d_out;

    cudaFuncSetAttribute(k_proj_mma, cudaFuncAttributeMaxDynamicSharedMemorySize,
                         PROJ_SMEM_BYTES);

    k_prep_w<<<768, 256>>>(proj_w);
    k_init<<<4096, 256>>>(x, mask, out);
    k_pre<<<dim3(TLEN/32, BB), 256>>>(x, pre_w, pre_b);

    int dil = 1;
    for (int i = 0; i < 3; i++){
        k_convnorm<<<dim3(TLEN, BB), 256>>>(mask,
                                            dw_w + (long)i*FF*3, dw_b + (long)i*FF,
                                            gamma1 + (long)i*FF, beta1 + (long)i*FF, dil);
        k_pw<<<dim3(TLEN/32, BB), 256>>>(pw_w + (long)i*FF*FF, pw_b + (long)i*FF,
                                         gamma2 + (long)i*FF, beta2 + (long)i*FF);
        dil *= 3;
    }

    k_prep_h<<<4096, 256>>>(mask);
    k_proj_mma<<<dim3(TLEN/NT, MROWS/MT, BB), 256, PROJ_SMEM_BYTES>>>(x, mask, proj_b, out);
}

// round 5
// speedup vs baseline: 2.5575x; 1.3279x over previous
#include <cuda_runtime.h>
#include <cuda_bf16.h>
#include <math.h>
#include <cstdint>

#define BB 16
#define CC 192
#define HALF 96
#define TLEN 2048
#define FF 256
#define NB 10
#define NJ 29        // 3*NB - 1

// ---- proj mma tiling ----
#define MROWS 3072   // 96 ch * 32 padded rows
#define MT 128       // m-tile (4 channels)
#define NT 64        // t-tile
#define ASTR 272     // A smem row stride bytes (128 bf16 + 16B pad)
#define BSTR 272
#define USTRIDE 65   // u smem row stride (floats)

#define OFF_AHI 0
#define OFF_ALO 34816
#define OFF_BHI 69632
#define OFF_BLO 87040
#define OFF_MASK 104448
#define OFF_RED 104704
#define PROJ_SMEM_BYTES 104768

// ---- pw mma tiling (M=256 full channels, N=64 t, K staged in 4x64) ----
#define PASTR 144              // 64 bf16 + 16B pad
#define PW_OFF_AHI 0
#define PW_OFF_ALO 36864
#define PW_OFF_BHI 73728
#define PW_OFF_BLO 82944
#define PW_SMEM_BYTES 92160
#define PW_USTR 260            // epilogue f32 row stride (words)
#define PW_OFF_STAT 66560      // bytes; smean[64] | srstd[64]

// Scratch (allocation-free rule: __device__ globals). Layout: [b][t][f].
__device__ float g_h[(size_t)BB*TLEN*FF];
__device__ __nv_bfloat16 g_whi[(size_t)MROWS*FF];
__device__ __nv_bfloat16 g_wlo[(size_t)MROWS*FF];
__device__ __nv_bfloat16 g_hhi[(size_t)BB*TLEN*FF];
__device__ __nv_bfloat16 g_hlo[(size_t)BB*TLEN*FF];
__device__ __nv_bfloat16 g_yhi[(size_t)BB*TLEN*FF];
__device__ __nv_bfloat16 g_ylo[(size_t)BB*TLEN*FF];
__device__ __nv_bfloat16 g_pwhi[(size_t)3*FF*FF];
__device__ __nv_bfloat16 g_pwlo[(size_t)3*FF*FF];

__device__ __forceinline__ float gelu_exact(float v){
    return 0.5f * v * (1.f + erff(v * 0.70710678118654752f));
}
__device__ __forceinline__ float softplusf(float v){
    return v > 20.f ? v : log1pf(expf(v));
}
__device__ __forceinline__ uint32_t smem_u32(const void* p){
    uint32_t a;
    asm("{ .reg .u64 t; cvta.to.shared.u64 t, %1; cvt.u32.u64 %0, t; }" : "=r"(a) : "l"(p));
    return a;
}
__device__ __forceinline__ void ldm4(uint32_t* r, uint32_t addr){
    asm volatile("ldmatrix.sync.aligned.m8n8.x4.shared.b16 {%0,%1,%2,%3}, [%4];"
        : "=r"(r[0]),"=r"(r[1]),"=r"(r[2]),"=r"(r[3]) : "r"(addr));
}
__device__ __forceinline__ void mma_bf16(float* d, const uint32_t* a, uint32_t b0, uint32_t b1){
    asm volatile("mma.sync.aligned.m16n8k16.row.col.f32.bf16.bf16.f32 "
        "{%0,%1,%2,%3}, {%4,%5,%6,%7}, {%8,%9}, {%0,%1,%2,%3};"
        : "+f"(d[0]),"+f"(d[1]),"+f"(d[2]),"+f"(d[3])
        : "r"(a[0]),"r"(a[1]),"r"(a[2]),"r"(a[3]), "r"(b0),"r"(b1));
}

// ---------------------------------------------------------------------------
// Prep: bf16 hi/lo split of proj_w into padded [3072][256] rows (32/channel)
// ---------------------------------------------------------------------------
__global__ void k_prep_w(const float* __restrict__ proj_w){
    long n = (long)MROWS*FF;
    for (long i = (long)blockIdx.x*blockDim.x + threadIdx.x; i < n;
         i += (long)gridDim.x*blockDim.x){
        int k = (int)(i & (FF-1));
        int r = (int)(i >> 8);
        int ch = r >> 5, j = r & 31;
        float w = (j < NJ) ? proj_w[((long)(ch*NJ + j))*FF + k] : 0.f;
        __nv_bfloat16 hi = __float2bfloat16_rn(w);
        g_whi[i] = hi;
        g_wlo[i] = __float2bfloat16_rn(w - __bfloat162float(hi));
    }
}
// Prep: bf16 hi/lo split of all 3 pw weight matrices
__global__ void k_prep_pw(const float* __restrict__ pw_w){
    long n = 3L*FF*FF;
    for (long i = (long)blockIdx.x*blockDim.x + threadIdx.x; i < n;
         i += (long)gridDim.x*blockDim.x){
        float w = pw_w[i];
        __nv_bfloat16 hi = __float2bfloat16_rn(w);
        g_pwhi[i] = hi;
        g_pwlo[i] = __float2bfloat16_rn(w - __bfloat162float(hi));
    }
}

// ---------------------------------------------------------------------------
// Kernel 0: copy x0*mask into out[:, :96, :], zero logdet slots.
// ---------------------------------------------------------------------------
__global__ void k_init(const float* __restrict__ x, const float* __restrict__ mask,
                       float* __restrict__ out){
    long n = (long)BB * HALF * TLEN;
    for (long i = (long)blockIdx.x * blockDim.x + threadIdx.x; i < n;
         i += (long)gridDim.x * blockDim.x){
        int t = (int)(i % TLEN);
        long bc = i / TLEN;
        int c = (int)(bc % HALF);
        int b = (int)(bc / HALF);
        long src = (long)b*CC*TLEN + (long)c*TLEN + t;
        out[src] = x[src] * mask[(long)b*TLEN + t];
    }
    if (blockIdx.x == 0 && threadIdx.x < BB)
        out[(long)BB*CC*TLEN + threadIdx.x] = 0.f;
}

// ---------------------------------------------------------------------------
// Kernel 1: h[b][t][f] = sum_c pre_w[f][c] * x0[b][c][t] + pre_b[f]
// ---------------------------------------------------------------------------
__global__ __launch_bounds__(256) void k_pre(const float* __restrict__ x,
                                             const float* __restrict__ pre_w,
                                             const float* __restrict__ pre_b){
    __shared__ float sx[HALF][32];
    int b = blockIdx.y;
    int t0 = blockIdx.x * 32;
    int f = threadIdx.x;

    for (int i = threadIdx.x; i < HALF*32; i += 256){
        int c = i >> 5, tt = i & 31;
        sx[c][tt] = x[(long)b*CC*TLEN + (long)c*TLEN + t0 + tt];
    }
    __syncthreads();

    float acc[32];
    float bv = pre_b[f];
    #pragma unroll
    for (int tt = 0; tt < 32; tt++) acc[tt] = bv;

    const float4* wrow4 = (const float4*)(pre_w + (long)f*HALF);
    #pragma unroll 4
    for (int c4 = 0; c4 < HALF/4; c4++){
        float4 wq = wrow4[c4];
        #pragma unroll
        for (int s = 0; s < 4; s++){
            float w = (s==0)?wq.x:(s==1)?wq.y:(s==2)?wq.z:wq.w;
            int c = c4*4 + s;
            const float4* r4 = (const float4*)&sx[c][0];
            #pragma unroll
            for (int q = 0; q < 8; q++){
                float4 v = r4[q];
                acc[4*q+0] = fmaf(w, v.x, acc[4*q+0]);
                acc[4*q+1] = fmaf(w, v.y, acc[4*q+1]);
                acc[4*q+2] = fmaf(w, v.z, acc[4*q+2]);
                acc[4*q+3] = fmaf(w, v.w, acc[4*q+3]);
            }
        }
    }
    #pragma unroll
    for (int tt = 0; tt < 32; tt++)
        g_h[((long)b*TLEN + t0 + tt)*FF + f] = acc[tt];
}

// ---------------------------------------------------------------------------
// Kernel 2 (per layer): depthwise dilated conv + channel_norm + GELU
// Writes bf16 hi/lo of y (feeds the pw MMA).
// ---------------------------------------------------------------------------
__global__ __launch_bounds__(256) void k_convnorm(const float* __restrict__ mask,
                                                  const float* __restrict__ dw_w,
                                                  const float* __restrict__ dw_b,
                                                  const float* __restrict__ gamma,
                                                  const float* __restrict__ beta,
                                                  int dil){
    int t = blockIdx.x, b = blockIdx.y, f = threadIdx.x;
    long base = (long)b*TLEN*FF;

    float vl = 0.f, vr = 0.f;
    float vc = g_h[base + (long)t*FF + f] * mask[(long)b*TLEN + t];
    if (t - dil >= 0)    vl = g_h[base + (long)(t-dil)*FF + f] * mask[(long)b*TLEN + t - dil];
    if (t + dil < TLEN)  vr = g_h[base + (long)(t+dil)*FF + f] * mask[(long)b*TLEN + t + dil];

    float w0 = dw_w[f*3+0], w1 = dw_w[f*3+1], w2 = dw_w[f*3+2];
    float v = fmaf(w0, vl, fmaf(w1, vc, fmaf(w2, vr, dw_b[f])));

    float s = v, sq = v*v;
    #pragma unroll
    for (int o = 16; o; o >>= 1){
        s  += __shfl_xor_sync(0xFFFFFFFFu, s,  o);
        sq += __shfl_xor_sync(0xFFFFFFFFu, sq, o);
    }
    __shared__ float ss[8], ssq[8];
    int w = threadIdx.x >> 5, l = threadIdx.x & 31;
    if (l == 0){ ss[w] = s; ssq[w] = sq; }
    __syncthreads();
    s = 0.f; sq = 0.f;
    #pragma unroll
    for (int k = 0; k < 8; k++){ s += ss[k]; sq += ssq[k]; }

    float mean = s * (1.f/FF);
    float var  = sq * (1.f/FF) - mean*mean;
    float rstd = rsqrtf(var + 1e-5f);
    float nv = (v - mean) * rstd * gamma[f] + beta[f];
    float yv = gelu_exact(nv);
    __nv_bfloat16 hi = __float2bfloat16_rn(yv);
    g_yhi[base + (long)t*FF + f] = hi;
    g_ylo[base + (long)t*FF + f] = __float2bfloat16_rn(yv - __bfloat162float(hi));
}

// ---------------------------------------------------------------------------
// Kernel 3 (per layer): y2 = pw_w @ y + pw_b via ldmatrix+mma (bf16 split),
// fused channel_norm + GELU + residual into g_h. Last layer also emits
// bf16 hi/lo of h*mask for the proj GEMM.
// CTA 512 thr / 16 warps (8m x 2n); tile M=256 x N=64 t; K=256 in 4x64.
// ---------------------------------------------------------------------------
__global__ __launch_bounds__(512) void k_pw_mma(int lay,
                                                const float* __restrict__ pw_b,
                                                const float* __restrict__ gamma,
                                                const float* __restrict__ beta,
                                                const float* __restrict__ mask,
                                                int last){
    extern __shared__ char smem[];
    uint32_t sb = smem_u32(smem);
    int tid = threadIdx.x, lane = tid & 31, wid = tid >> 5;
    int t0 = blockIdx.x * 64;
    int b = blockIdx.y;
    int wm = wid & 7, wn = wid >> 3;

    float acc[2][4][4];
    #pragma unroll
    for (int mt = 0; mt < 2; mt++)
        #pragma unroll
        for (int nt = 0; nt < 4; nt++)
            #pragma unroll
            for (int q = 0; q < 4; q++) acc[mt][nt][q] = 0.f;

    uint32_t aoff = (uint32_t)((wm*32 + (lane & 15)) * PASTR + ((lane >> 4) * 8) * 2);
    uint32_t aH0 = sb + PW_OFF_AHI + aoff, aH1 = aH0 + 16*PASTR;
    uint32_t aL0 = sb + PW_OFF_ALO + aoff, aL1 = aL0 + 16*PASTR;
    uint32_t boff = (uint32_t)((wn*32 + ((lane >> 4) * 8) + (lane & 7)) * PASTR
                               + ((lane >> 3) & 1) * 16);
    uint32_t bH0 = sb + PW_OFF_BHI + boff, bH1 = bH0 + 16*PASTR;
    uint32_t bL0 = sb + PW_OFF_BLO + boff, bL1 = bL0 + 16*PASTR;

    for (int c0 = 0; c0 < 4; c0++){
        if (c0) __syncthreads();
        // stage A hi/lo: 256 rows x 8 uint4 (64 k)
        for (int i = tid; i < FF*8; i += 512){
            int r = i >> 3, g = i & 7;
            uint32_t off = (uint32_t)(r*PASTR + g*16);
            size_t s4 = ((size_t)(lay*FF + r))*32 + (size_t)c0*8 + g;
            *(uint4*)(smem + PW_OFF_AHI + off) = ((const uint4*)g_pwhi)[s4];
            *(uint4*)(smem + PW_OFF_ALO + off) = ((const uint4*)g_pwlo)[s4];
        }
        // stage B hi/lo: 64 t-rows x 8 uint4
        for (int i = tid; i < 64*8; i += 512){
            int r = i >> 3, g = i & 7;
            uint32_t off = (uint32_t)(r*PASTR + g*16);
            size_t s4 = ((size_t)b*TLEN + t0 + r)*32 + (size_t)c0*8 + g;
            *(uint4*)(smem + PW_OFF_BHI + off) = ((const uint4*)g_yhi)[s4];
            *(uint4*)(smem + PW_OFF_BLO + off) = ((const uint4*)g_ylo)[s4];
        }
        __syncthreads();

        #pragma unroll
        for (int k16 = 0; k16 < 4; k16++){
            uint32_t ko = (uint32_t)(k16 * 32);
            uint32_t Ah[2][4], Al[2][4], Bh[2][4], Bl[2][4];
            ldm4(Ah[0], aH0 + ko); ldm4(Ah[1], aH1 + ko);
            ldm4(Al[0], aL0 + ko); ldm4(Al[1], aL1 + ko);
            ldm4(Bh[0], bH0 + ko); ldm4(Bh[1], bH1 + ko);
            ldm4(Bl[0], bL0 + ko); ldm4(Bl[1], bL1 + ko);
            #pragma unroll
            for (int mt = 0; mt < 2; mt++){
                #pragma unroll
                for (int nt = 0; nt < 4; nt++){
                    uint32_t h0 = Bh[nt>>1][(nt&1)*2], h1 = Bh[nt>>1][(nt&1)*2+1];
                    uint32_t l0 = Bl[nt>>1][(nt&1)*2], l1 = Bl[nt>>1][(nt&1)*2+1];
                    mma_bf16(acc[mt][nt], Ah[mt], h0, h1);
                    mma_bf16(acc[mt][nt], Ah[mt], l0, l1);
                    mma_bf16(acc[mt][nt], Al[mt], h0, h1);
                }
            }
        }
    }
    __syncthreads();

    // epilogue: us[t][o] (stride PW_USTR), bias folded in
    float* us = (float*)smem;
    #pragma unroll
    for (int mt = 0; mt < 2; mt++){
        #pragma unroll
        for (int nt = 0; nt < 4; nt++){
            int t = wn*32 + nt*8 + (lane & 3)*2;
            int m = wm*32 + mt*16 + (lane >> 2);
            #pragma unroll
            for (int hh = 0; hh < 2; hh++){
                int o = m + hh*8;
                float pb = pw_b[o];
                us[t*PW_USTR + o]     = acc[mt][nt][2*hh+0] + pb;
                us[(t+1)*PW_USTR + o] = acc[mt][nt][2*hh+1] + pb;
            }
        }
    }
    __syncthreads();

    // channel-norm stats: warp w handles t = 4w..4w+3
    float* smean = (float*)(smem + PW_OFF_STAT);
    float* srstd = smean + 64;
    #pragma unroll
    for (int it = 0; it < 4; it++){
        int t = wid*4 + it;
        float s = 0.f, sq = 0.f;
        #pragma unroll
        for (int k = 0; k < 8; k++){
            float v = us[t*PW_USTR + lane + k*32];
            s += v; sq += v*v;
        }
        #pragma unroll
        for (int off = 16; off; off >>= 1){
            s  += __shfl_xor_sync(0xFFFFFFFFu, s,  off);
            sq += __shfl_xor_sync(0xFFFFFFFFu, sq, off);
        }
        if (lane == 0){
            float mean = s * (1.f/FF);
            smean[t] = mean;
            srstd[t] = rsqrtf(sq * (1.f/FF) - mean*mean + 1e-5f);
        }
    }
    __syncthreads();

    // gelu + residual (+ optional bf16 emit for proj)
    long gbase = ((long)b*TLEN + t0) * FF;
    for (int i = tid; i < 64*64; i += 512){
        int t = i >> 6, o4 = i & 63;
        float4 u = *(float4*)&us[t*PW_USTR + o4*4];
        float mean = smean[t], rstd = srstd[t];
        const float4 ga = *(const float4*)&gamma[o4*4];
        const float4 be = *(const float4*)&beta[o4*4];
        long idx = gbase + (long)t*FF + o4*4;
        float4 hv = *(float4*)&g_h[idx];
        hv.x += gelu_exact((u.x - mean)*rstd*ga.x + be.x);
        hv.y += gelu_exact((u.y - mean)*rstd*ga.y + be.y);
        hv.z += gelu_exact((u.z - mean)*rstd*ga.z + be.z);
        hv.w += gelu_exact((u.w - mean)*rstd*ga.w + be.w);
        *(float4*)&g_h[idx] = hv;
        if (last){
            float mv = mask[(long)b*TLEN + t0 + t];
            float v0 = hv.x*mv, v1 = hv.y*mv, v2 = hv.z*mv, v3 = hv.w*mv;
            __nv_bfloat16 h0 = __float2bfloat16_rn(v0);
            __nv_bfloat16 h1 = __float2bfloat16_rn(v1);
            __nv_bfloat16 h2 = __float2bfloat16_rn(v2);
            __nv_bfloat16 h3 = __float2bfloat16_rn(v3);
            __nv_bfloat162 p0; p0.x = h0; p0.y = h1;
            __nv_bfloat162 p1; p1.x = h2; p1.y = h3;
            *(__nv_bfloat162*)&g_hhi[idx]   = p0;
            *(__nv_bfloat162*)&g_hhi[idx+2] = p1;
            __nv_bfloat162 q0, q1;
            q0.x = __float2bfloat16_rn(v0 - __bfloat162float(h0));
            q0.y = __float2bfloat16_rn(v1 - __bfloat162float(h1));
            q1.x = __float2bfloat16_rn(v2 - __bfloat162float(h2));
            q1.y = __float2bfloat16_rn(v3 - __bfloat162float(h3));
            *(__nv_bfloat162*)&g_hlo[idx]   = q0;
            *(__nv_bfloat162*)&g_hlo[idx+2] = q1;
        }
    }
}

// ---------------------------------------------------------------------------
// Kernel 4: bf16-split GEMM (u = W @ h^T) via ldmatrix + mma.sync, fused with
// the RQ spline. CTA 256 thr / 8 warps (4m x 2n), tile M=128 x N=64, K=256.
// ---------------------------------------------------------------------------
__global__ __launch_bounds__(256) void k_proj_mma(const float* __restrict__ x,
                                                  const float* __restrict__ mask,
                                                  const float* __restrict__ proj_b,
                                                  float* __restrict__ out){
    extern __shared__ char smem[];
    uint32_t sb = smem_u32(smem);
    int tid = threadIdx.x, lane = tid & 31, wid = tid >> 5;
    int t0 = blockIdx.x * NT;
    int mtile = blockIdx.y;
    int b = blockIdx.z;
    int m0 = mtile * MT;
    int ch0 = mtile * 4;

    float* smask = (float*)(smem + OFF_MASK);
    if (tid < NT) smask[tid] = mask[(long)b*TLEN + t0 + tid];

    float acc[2][4][4];
    #pragma unroll
    for (int mt = 0; mt < 2; mt++)
        #pragma unroll
        for (int nt = 0; nt < 4; nt++)
            #pragma unroll
            for (int q = 0; q < 4; q++) acc[mt][nt][q] = 0.f;

    int wm = wid & 3, wn = wid >> 2;
    uint32_t aoff = (uint32_t)((wm*32 + (lane & 15)) * ASTR + ((lane >> 4) * 8) * 2);
    uint32_t aH0 = sb + OFF_AHI + aoff, aH1 = aH0 + 16*ASTR;
    uint32_t aL0 = sb + OFF_ALO + aoff, aL1 = aL0 + 16*ASTR;
    uint32_t boff = (uint32_t)((wn*32 + ((lane >> 4) * 8) + (lane & 7)) * BSTR
                               + ((lane >> 3) & 1) * 16);
    uint32_t bH0 = sb + OFF_BHI + boff, bH1 = bH0 + 16*BSTR;
    uint32_t bL0 = sb + OFF_BLO + boff, bL1 = bL0 + 16*BSTR;

    for (int c = 0; c < 2; c++){
        if (c) __syncthreads();
        // stage A hi/lo: 128 rows x 16 uint4
        for (int i = tid; i < MT*16; i += 256){
            int r = i >> 4, g = i & 15;
            uint32_t off = (uint32_t)(r*ASTR + g*16);
            size_t s4 = ((size_t)(m0 + r))*32 + (size_t)c*16 + g;
            *(uint4*)(smem + OFF_AHI + off) = ((const uint4*)g_whi)[s4];
            *(uint4*)(smem + OFF_ALO + off) = ((const uint4*)g_wlo)[s4];
        }
        // stage B hi/lo: 64 t-rows x 16 uint4
        for (int i = tid; i < NT*16; i += 256){
            int r = i >> 4, g = i & 15;
            uint32_t off = (uint32_t)(r*BSTR + g*16);
            size_t s4 = ((size_t)b*TLEN + t0 + r)*32 + (size_t)c*16 + g;
            *(uint4*)(smem + OFF_BHI + off) = ((const uint4*)g_hhi)[s4];
            *(uint4*)(smem + OFF_BLO + off) = ((const uint4*)g_hlo)[s4];
        }
        __syncthreads();

        #pragma unroll
        for (int k16 = 0; k16 < 8; k16++){
            uint32_t ko = (uint32_t)(k16 * 32);
            uint32_t Ah[2][4], Al[2][4], Bh[2][4], Bl[2][4];
            ldm4(Ah[0], aH0 + ko); ldm4(Ah[1], aH1 + ko);
            ldm4(Al[0], aL0 + ko); ldm4(Al[1], aL1 + ko);
            ldm4(Bh[0], bH0 + ko); ldm4(Bh[1], bH1 + ko);
            ldm4(Bl[0], bL0 + ko); ldm4(Bl[1], bL1 + ko);
            #pragma unroll
            for (int mt = 0; mt < 2; mt++){
                #pragma unroll
                for (int nt = 0; nt < 4; nt++){
                    uint32_t h0 = Bh[nt>>1][(nt&1)*2], h1 = Bh[nt>>1][(nt&1)*2+1];
                    uint32_t l0 = Bl[nt>>1][(nt&1)*2], l1 = Bl[nt>>1][(nt&1)*2+1];
                    mma_bf16(acc[mt][nt], Ah[mt], h0, h1);
                    mma_bf16(acc[mt][nt], Ah[mt], l0, l1);
                    mma_bf16(acc[mt][nt], Al[mt], h0, h1);
                }
            }
        }
    }
    __syncthreads();

    // u -> smem (alias over A region): us[row][t], stride 65 floats
    float* us = (float*)smem;
    #pragma unroll
    for (int mt = 0; mt < 2; mt++){
        #pragma unroll
        for (int nt = 0; nt < 4; nt++){
            int r = wm*32 + mt*16 + (lane >> 2);
            int t = wn*32 + nt*8 + (lane & 3)*2;
            #pragma unroll
            for (int hh = 0; hh < 2; hh++){
                int rr = r + hh*8;
                int j = rr & 31;
                int ch = ch0 + (rr >> 5);
                float pb = (j < NJ) ? proj_b[ch*NJ + j] : 0.f;
                us[rr*USTRIDE + t]     = (acc[mt][nt][2*hh+0] + pb) * smask[t];
                us[rr*USTRIDE + t + 1] = (acc[mt][nt][2*hh+1] + pb) * smask[t+1];
            }
        }
    }
    __syncthreads();

    // --- spline: 4 ch x 64 t = 256 evals, one per thread ---
    const float SCALE = 0.0625f;
    int chl = tid >> 6, tl = tid & 63;
    int ch = ch0 + chl;
    const float* ub = us + (chl*32)*USTRIDE + tl;   // ub[j*USTRIDE]

    float x1v = x[(long)b*CC*TLEN + (long)(HALF + ch)*TLEN + t0 + tl];
    float mv  = smask[tl];

    float uw[10];
    #pragma unroll
    for (int j = 0; j < 10; j++) uw[j] = ub[j*USTRIDE] * SCALE;
    float mx = uw[0];
    #pragma unroll
    for (int j = 1; j < 10; j++) mx = fmaxf(mx, uw[j]);
    float ew[10]; float sw = 0.f;
    #pragma unroll
    for (int j = 0; j < 10; j++){ ew[j] = expf(uw[j] - mx); sw += ew[j]; }
    float cw[11]; cw[0] = -5.f;
    {
        float inv = 1.f / sw, cs = 0.f;
        #pragma unroll
        for (int j = 0; j < 9; j++){
            cs += fmaf(0.99f, ew[j]*inv, 0.001f);
            cw[j+1] = fmaf(10.f, cs, -5.f);
        }
        cw[10] = 5.f;
    }
    #pragma unroll
    for (int j = 0; j < 10; j++) uw[j] = ub[(10+j)*USTRIDE] * SCALE;
    mx = uw[0];
    #pragma unroll
    for (int j = 1; j < 10; j++) mx = fmaxf(mx, uw[j]);
    sw = 0.f;
    #pragma unroll
    for (int j = 0; j < 10; j++){ ew[j] = expf(uw[j] - mx); sw += ew[j]; }
    float chh[11]; chh[0] = -5.f;
    {
        float inv = 1.f / sw, cs = 0.f;
        #pragma unroll
        for (int j = 0; j < 9; j++){
            cs += fmaf(0.99f, ew[j]*inv, 0.001f);
            chh[j+1] = fmaf(10.f, cs, -5.f);
        }
        chh[10] = 5.f;
    }

    float xc = fminf(fmaxf(x1v, -5.f), 5.f);
    int idx = 0;
    #pragma unroll
    for (int j = 1; j <= 9; j++) idx += (xc >= cw[j]) ? 1 : 0;

    float cwl = cw[0], cwr = cw[1], chl2 = chh[0], chr = chh[1];
    #pragma unroll
    for (int j = 1; j < 10; j++){
        if (idx == j){ cwl = cw[j]; cwr = cw[j+1]; chl2 = chh[j]; chr = chh[j+1]; }
    }
    float d0 = (idx == 0) ? 1.f : 0.001f + softplusf(ub[(19 + idx)*USTRIDE]);
    float d1 = (idx == 9) ? 1.f : 0.001f + softplusf(ub[(20 + idx)*USTRIDE]);

    float wb = cwr - cwl, hb = chr - chl2;
    float delta = hb / wb;
    float th = (xc - cwl) / wb;
    float omt = 1.f - th;
    float t1m = th * omt;
    float denom = delta + (d0 + d1 - 2.f*delta) * t1m;
    float num = hb * (delta*th*th + d0*t1m);
    float yv = chl2 + num / denom;
    float dnum = delta*delta * (d1*th*th + 2.f*delta*t1m + d0*omt*omt);
    float lad = logf(dnum) - 2.f*logf(denom);

    bool inside = (x1v >= -5.f) && (x1v <= 5.f);
    float ov = inside ? yv : x1v;
    float ldsum = (inside ? lad : 0.f) * mv;

    out[(long)b*CC*TLEN + (long)(HALF + ch)*TLEN + t0 + tl] = ov * mv;

    // logdet reduction
    #pragma unroll
    for (int off = 16; off; off >>= 1)
        ldsum += __shfl_xor_sync(0xFFFFFFFFu, ldsum, off);
    float* sred = (float*)(smem + OFF_RED);
    if (lane == 0) sred[wid] = ldsum;
    __syncthreads();
    if (tid == 0){
        float s = 0.f;
        #pragma unroll
        for (int k = 0; k < 8; k++) s += sred[k];
        atomicAdd(&out[(long)BB*CC*TLEN + b], s);
    }
}

// ---------------------------------------------------------------------------
extern "C" void kernel_launch(void* const* d_in, const int* in_sizes, int n_in,
                              void* d_out, int out_size){
    const float* x      = (const float*)d_in[0];
    const float* mask   = (const float*)d_in[1];
    const float* pre_w  = (const float*)d_in[2];
    const float* pre_b  = (const float*)d_in[3];
    const float* dw_w   = (const float*)d_in[4];
    const float* dw_b   = (const float*)d_in[5];
    const float* pw_w   = (const float*)d_in[6];
    const float* pw_b   = (const float*)d_in[7];
    const float* gamma1 = (const float*)d_in[8];
    const float* beta1  = (const float*)d_in[9];
    const float* gamma2 = (const float*)d_in[10];
    const float* beta2  = (const float*)d_in[11];
    const float* proj_w = (const float*)d_in[12];
    const float* proj_b = (const float*)d_in[13];
    float* out = (float*)d_out;

    cudaFuncSetAttribute(k_proj_mma, cudaFuncAttributeMaxDynamicSharedMemorySize,
                         PROJ_SMEM_BYTES);
    cudaFuncSetAttribute(k_pw_mma, cudaFuncAttributeMaxDynamicSharedMemorySize,
                         PW_SMEM_BYTES);

    k_prep_w<<<768, 256>>>(proj_w);
    k_prep_pw<<<192, 256>>>(pw_w);
    k_init<<<4096, 256>>>(x, mask, out);
    k_pre<<<dim3(TLEN/32, BB), 256>>>(x, pre_w, pre_b);

    int dil = 1;
    for (int i = 0; i < 3; i++){
        k_convnorm<<<dim3(TLEN, BB), 256>>>(mask,
                                            dw_w + (long)i*FF*3, dw_b + (long)i*FF,
                                            gamma1 + (long)i*FF, beta1 + (long)i*FF, dil);
        k_pw_mma<<<dim3(TLEN/64, BB), 512, PW_SMEM_BYTES>>>(i,
                                            pw_b + (long)i*FF,
                                            gamma2 + (long)i*FF, beta2 + (long)i*FF,
                                            mask, (i == 2) ? 1 : 0);
        dil *= 3;
    }

    k_proj_mma<<<dim3(TLEN/NT, MROWS/MT, BB), 256, PROJ_SMEM_BYTES>>>(x, mask, proj_b, out);
}

// round 6
// speedup vs baseline: 3.3212x; 1.2986x over previous
#include <cuda_runtime.h>
#include <cuda_bf16.h>
#include <math.h>
#include <cstdint>

#define BB 16
#define CC 192
#define HALF 96
#define TLEN 2048
#define FF 256
#define NB 10
#define NJ 29        // 3*NB - 1

// ---- proj mma tiling (2-term: W bf16-rounded, h hi/lo split) ----
#define MROWS 3072   // 96 ch * 32 padded rows
#define MT 128       // m-tile (4 channels)
#define NT 128       // t-tile
#define ASTR 272     // smem row stride bytes (128 bf16 + 16B pad)
#define BSTR 272
#define USTRIDE 129  // u smem row stride (floats), odd -> conflict-free

#define OFF_A    0            // 128*272 = 34816 (hi only)
#define OFF_BHI  34816        // 128*272
#define OFF_BLO  69632        // 128*272
#define OFF_MASK 104448       // 128 floats
#define OFF_RED  104960       // 8 floats
#define PROJ_SMEM_BYTES 105088

// ---- pw mma tiling (M=256 full channels, N=64 t, K staged in 4x64) ----
#define PASTR 144              // 64 bf16 + 16B pad
#define PW_OFF_AHI 0
#define PW_OFF_ALO 36864
#define PW_OFF_BHI 73728
#define PW_OFF_BLO 82944
#define PW_SMEM_BYTES 92160
#define PW_USTR 260            // epilogue f32 row stride (words)
#define PW_OFF_STAT 66560      // bytes; smean[64] | srstd[64]

// Scratch (allocation-free rule: __device__ globals). Layout: [b][t][f].
__device__ float g_h[(size_t)BB*TLEN*FF];
__device__ __nv_bfloat16 g_whi[(size_t)MROWS*FF];
__device__ __nv_bfloat16 g_hhi[(size_t)BB*TLEN*FF];
__device__ __nv_bfloat16 g_hlo[(size_t)BB*TLEN*FF];
__device__ __nv_bfloat16 g_yhi[(size_t)BB*TLEN*FF];
__device__ __nv_bfloat16 g_ylo[(size_t)BB*TLEN*FF];
__device__ __nv_bfloat16 g_pwhi[(size_t)3*FF*FF];
__device__ __nv_bfloat16 g_pwlo[(size_t)3*FF*FF];

__device__ __forceinline__ float gelu_exact(float v){
    return 0.5f * v * (1.f + erff(v * 0.70710678118654752f));
}
__device__ __forceinline__ float softplusf(float v){
    return v > 20.f ? v : log1pf(expf(v));
}
__device__ __forceinline__ uint32_t smem_u32(const void* p){
    uint32_t a;
    asm("{ .reg .u64 t; cvta.to.shared.u64 t, %1; cvt.u32.u64 %0, t; }" : "=r"(a) : "l"(p));
    return a;
}
__device__ __forceinline__ void ldm4(uint32_t* r, uint32_t addr){
    asm volatile("ldmatrix.sync.aligned.m8n8.x4.shared.b16 {%0,%1,%2,%3}, [%4];"
        : "=r"(r[0]),"=r"(r[1]),"=r"(r[2]),"=r"(r[3]) : "r"(addr));
}
__device__ __forceinline__ void mma_bf16(float* d, const uint32_t* a, uint32_t b0, uint32_t b1){
    asm volatile("mma.sync.aligned.m16n8k16.row.col.f32.bf16.bf16.f32 "
        "{%0,%1,%2,%3}, {%4,%5,%6,%7}, {%8,%9}, {%0,%1,%2,%3};"
        : "+f"(d[0]),"+f"(d[1]),"+f"(d[2]),"+f"(d[3])
        : "r"(a[0]),"r"(a[1]),"r"(a[2]),"r"(a[3]), "r"(b0),"r"(b1));
}

// ---------------------------------------------------------------------------
// Prep: bf16 (round-to-nearest) proj_w into padded [3072][256] rows
// ---------------------------------------------------------------------------
__global__ void k_prep_w(const float* __restrict__ proj_w){
    long n = (long)MROWS*FF;
    for (long i = (long)blockIdx.x*blockDim.x + threadIdx.x; i < n;
         i += (long)gridDim.x*blockDim.x){
        int k = (int)(i & (FF-1));
        int r = (int)(i >> 8);
        int ch = r >> 5, j = r & 31;
        float w = (j < NJ) ? proj_w[((long)(ch*NJ + j))*FF + k] : 0.f;
        g_whi[i] = __float2bfloat16_rn(w);
    }
}
// Prep: bf16 hi/lo split of all 3 pw weight matrices
__global__ void k_prep_pw(const float* __restrict__ pw_w){
    long n = 3L*FF*FF;
    for (long i = (long)blockIdx.x*blockDim.x + threadIdx.x; i < n;
         i += (long)gridDim.x*blockDim.x){
        float w = pw_w[i];
        __nv_bfloat16 hi = __float2bfloat16_rn(w);
        g_pwhi[i] = hi;
        g_pwlo[i] = __float2bfloat16_rn(w - __bfloat162float(hi));
    }
}

// ---------------------------------------------------------------------------
// Kernel 0: copy x0*mask into out[:, :96, :], zero logdet slots.
// ---------------------------------------------------------------------------
__global__ void k_init(const float* __restrict__ x, const float* __restrict__ mask,
                       float* __restrict__ out){
    long n = (long)BB * HALF * TLEN;
    for (long i = (long)blockIdx.x * blockDim.x + threadIdx.x; i < n;
         i += (long)gridDim.x * blockDim.x){
        int t = (int)(i % TLEN);
        long bc = i / TLEN;
        int c = (int)(bc % HALF);
        int b = (int)(bc / HALF);
        long src = (long)b*CC*TLEN + (long)c*TLEN + t;
        out[src] = x[src] * mask[(long)b*TLEN + t];
    }
    if (blockIdx.x == 0 && threadIdx.x < BB)
        out[(long)BB*CC*TLEN + threadIdx.x] = 0.f;
}

// ---------------------------------------------------------------------------
// Kernel 1: h[b][t][f] = sum_c pre_w[f][c] * x0[b][c][t] + pre_b[f]
// ---------------------------------------------------------------------------
__global__ __launch_bounds__(256) void k_pre(const float* __restrict__ x,
                                             const float* __restrict__ pre_w,
                                             const float* __restrict__ pre_b){
    __shared__ float sx[HALF][32];
    int b = blockIdx.y;
    int t0 = blockIdx.x * 32;
    int f = threadIdx.x;

    for (int i = threadIdx.x; i < HALF*32; i += 256){
        int c = i >> 5, tt = i & 31;
        sx[c][tt] = x[(long)b*CC*TLEN + (long)c*TLEN + t0 + tt];
    }
    __syncthreads();

    float acc[32];
    float bv = pre_b[f];
    #pragma unroll
    for (int tt = 0; tt < 32; tt++) acc[tt] = bv;

    const float4* wrow4 = (const float4*)(pre_w + (long)f*HALF);
    #pragma unroll 4
    for (int c4 = 0; c4 < HALF/4; c4++){
        float4 wq = wrow4[c4];
        #pragma unroll
        for (int s = 0; s < 4; s++){
            float w = (s==0)?wq.x:(s==1)?wq.y:(s==2)?wq.z:wq.w;
            int c = c4*4 + s;
            const float4* r4 = (const float4*)&sx[c][0];
            #pragma unroll
            for (int q = 0; q < 8; q++){
                float4 v = r4[q];
                acc[4*q+0] = fmaf(w, v.x, acc[4*q+0]);
                acc[4*q+1] = fmaf(w, v.y, acc[4*q+1]);
                acc[4*q+2] = fmaf(w, v.z, acc[4*q+2]);
                acc[4*q+3] = fmaf(w, v.w, acc[4*q+3]);
            }
        }
    }
    #pragma unroll
    for (int tt = 0; tt < 32; tt++)
        g_h[((long)b*TLEN + t0 + tt)*FF + f] = acc[tt];
}

// ---------------------------------------------------------------------------
// Kernel 2 (per layer): depthwise dilated conv + channel_norm + GELU,
// 4 t-columns per CTA (amortize addressing). Writes bf16 hi/lo of y.
// ---------------------------------------------------------------------------
__global__ __launch_bounds__(256) void k_convnorm(const float* __restrict__ mask,
                                                  const float* __restrict__ dw_w,
                                                  const float* __restrict__ dw_b,
                                                  const float* __restrict__ gamma,
                                                  const float* __restrict__ beta,
                                                  int dil){
    int t0 = blockIdx.x * 4, b = blockIdx.y, f = threadIdx.x;
    long base = (long)b*TLEN*FF;
    const float* mrow = mask + (long)b*TLEN;
    __shared__ float ss[8], ssq[8];

    float w0 = dw_w[f*3+0], w1 = dw_w[f*3+1], w2 = dw_w[f*3+2];
    float bias = dw_b[f], ga = gamma[f], be = beta[f];
    int w = threadIdx.x >> 5, l = threadIdx.x & 31;

    #pragma unroll
    for (int tt = 0; tt < 4; tt++){
        int t = t0 + tt;
        float vl = 0.f, vr = 0.f;
        float vc = g_h[base + (long)t*FF + f] * mrow[t];
        if (t - dil >= 0)    vl = g_h[base + (long)(t-dil)*FF + f] * mrow[t - dil];
        if (t + dil < TLEN)  vr = g_h[base + (long)(t+dil)*FF + f] * mrow[t + dil];
        float v = fmaf(w0, vl, fmaf(w1, vc, fmaf(w2, vr, bias)));

        float s = v, sq = v*v;
        #pragma unroll
        for (int o = 16; o; o >>= 1){
            s  += __shfl_xor_sync(0xFFFFFFFFu, s,  o);
            sq += __shfl_xor_sync(0xFFFFFFFFu, sq, o);
        }
        if (l == 0){ ss[w] = s; ssq[w] = sq; }
        __syncthreads();
        s = 0.f; sq = 0.f;
        #pragma unroll
        for (int k = 0; k < 8; k++){ s += ss[k]; sq += ssq[k]; }
        __syncthreads();

        float mean = s * (1.f/FF);
        float var  = sq * (1.f/FF) - mean*mean;
        float rstd = rsqrtf(var + 1e-5f);
        float nv = (v - mean) * rstd * ga + be;
        float yv = gelu_exact(nv);
        __nv_bfloat16 hi = __float2bfloat16_rn(yv);
        g_yhi[base + (long)t*FF + f] = hi;
        g_ylo[base + (long)t*FF + f] = __float2bfloat16_rn(yv - __bfloat162float(hi));
    }
}

// ---------------------------------------------------------------------------
// Kernel 3 (per layer): y2 = pw_w @ y + pw_b via ldmatrix+mma (bf16 3-term),
// fused channel_norm + GELU + residual into g_h. Last layer also emits
// bf16 hi/lo of h*mask for the proj GEMM.
// ---------------------------------------------------------------------------
__global__ __launch_bounds__(512) void k_pw_mma(int lay,
                                                const float* __restrict__ pw_b,
                                                const float* __restrict__ gamma,
                                                const float* __restrict__ beta,
                                                const float* __restrict__ mask,
                                                int last){
    extern __shared__ char smem[];
    uint32_t sb = smem_u32(smem);
    int tid = threadIdx.x, lane = tid & 31, wid = tid >> 5;
    int t0 = blockIdx.x * 64;
    int b = blockIdx.y;
    int wm = wid & 7, wn = wid >> 3;

    float acc[2][4][4];
    #pragma unroll
    for (int mt = 0; mt < 2; mt++)
        #pragma unroll
        for (int nt = 0; nt < 4; nt++)
            #pragma unroll
            for (int q = 0; q < 4; q++) acc[mt][nt][q] = 0.f;

    uint32_t aoff = (uint32_t)((wm*32 + (lane & 15)) * PASTR + ((lane >> 4) * 8) * 2);
    uint32_t aH0 = sb + PW_OFF_AHI + aoff, aH1 = aH0 + 16*PASTR;
    uint32_t aL0 = sb + PW_OFF_ALO + aoff, aL1 = aL0 + 16*PASTR;
    uint32_t boff = (uint32_t)((wn*32 + ((lane >> 4) * 8) + (lane & 7)) * PASTR
                               + ((lane >> 3) & 1) * 16);
    uint32_t bH0 = sb + PW_OFF_BHI + boff, bH1 = bH0 + 16*PASTR;
    uint32_t bL0 = sb + PW_OFF_BLO + boff, bL1 = bL0 + 16*PASTR;

    for (int c0 = 0; c0 < 4; c0++){
        if (c0) __syncthreads();
        for (int i = tid; i < FF*8; i += 512){
            int r = i >> 3, g = i & 7;
            uint32_t off = (uint32_t)(r*PASTR + g*16);
            size_t s4 = ((size_t)(lay*FF + r))*32 + (size_t)c0*8 + g;
            *(uint4*)(smem + PW_OFF_AHI + off) = ((const uint4*)g_pwhi)[s4];
            *(uint4*)(smem + PW_OFF_ALO + off) = ((const uint4*)g_pwlo)[s4];
        }
        for (int i = tid; i < 64*8; i += 512){
            int r = i >> 3, g = i & 7;
            uint32_t off = (uint32_t)(r*PASTR + g*16);
            size_t s4 = ((size_t)b*TLEN + t0 + r)*32 + (size_t)c0*8 + g;
            *(uint4*)(smem + PW_OFF_BHI + off) = ((const uint4*)g_yhi)[s4];
            *(uint4*)(smem + PW_OFF_BLO + off) = ((const uint4*)g_ylo)[s4];
        }
        __syncthreads();

        #pragma unroll
        for (int k16 = 0; k16 < 4; k16++){
            uint32_t ko = (uint32_t)(k16 * 32);
            uint32_t Ah[2][4], Al[2][4], Bh[2][4], Bl[2][4];
            ldm4(Ah[0], aH0 + ko); ldm4(Ah[1], aH1 + ko);
            ldm4(Al[0], aL0 + ko); ldm4(Al[1], aL1 + ko);
            ldm4(Bh[0], bH0 + ko); ldm4(Bh[1], bH1 + ko);
            ldm4(Bl[0], bL0 + ko); ldm4(Bl[1], bL1 + ko);
            #pragma unroll
            for (int mt = 0; mt < 2; mt++){
                #pragma unroll
                for (int nt = 0; nt < 4; nt++){
                    uint32_t h0 = Bh[nt>>1][(nt&1)*2], h1 = Bh[nt>>1][(nt&1)*2+1];
                    uint32_t l0 = Bl[nt>>1][(nt&1)*2], l1 = Bl[nt>>1][(nt&1)*2+1];
                    mma_bf16(acc[mt][nt], Ah[mt], h0, h1);
                    mma_bf16(acc[mt][nt], Ah[mt], l0, l1);
                    mma_bf16(acc[mt][nt], Al[mt], h0, h1);
                }
            }
        }
    }
    __syncthreads();

    float* us = (float*)smem;
    #pragma unroll
    for (int mt = 0; mt < 2; mt++){
        #pragma unroll
        for (int nt = 0; nt < 4; nt++){
            int t = wn*32 + nt*8 + (lane & 3)*2;
            int m = wm*32 + mt*16 + (lane >> 2);
            #pragma unroll
            for (int hh = 0; hh < 2; hh++){
                int o = m + hh*8;
                float pb = pw_b[o];
                us[t*PW_USTR + o]     = acc[mt][nt][2*hh+0] + pb;
                us[(t+1)*PW_USTR + o] = acc[mt][nt][2*hh+1] + pb;
            }
        }
    }
    __syncthreads();

    float* smean = (float*)(smem + PW_OFF_STAT);
    float* srstd = smean + 64;
    #pragma unroll
    for (int it = 0; it < 4; it++){
        int t = wid*4 + it;
        float s = 0.f, sq = 0.f;
        #pragma unroll
        for (int k = 0; k < 8; k++){
            float v = us[t*PW_USTR + lane + k*32];
            s += v; sq += v*v;
        }
        #pragma unroll
        for (int off = 16; off; off >>= 1){
            s  += __shfl_xor_sync(0xFFFFFFFFu, s,  off);
            sq += __shfl_xor_sync(0xFFFFFFFFu, sq, off);
        }
        if (lane == 0){
            float mean = s * (1.f/FF);
            smean[t] = mean;
            srstd[t] = rsqrtf(sq * (1.f/FF) - mean*mean + 1e-5f);
        }
    }
    __syncthreads();

    long gbase = ((long)b*TLEN + t0) * FF;
    for (int i = tid; i < 64*64; i += 512){
        int t = i >> 6, o4 = i & 63;
        float4 u = *(float4*)&us[t*PW_USTR + o4*4];
        float mean = smean[t], rstd = srstd[t];
        const float4 ga = *(const float4*)&gamma[o4*4];
        const float4 be = *(const float4*)&beta[o4*4];
        long idx = gbase + (long)t*FF + o4*4;
        float4 hv = *(float4*)&g_h[idx];
        hv.x += gelu_exact((u.x - mean)*rstd*ga.x + be.x);
        hv.y += gelu_exact((u.y - mean)*rstd*ga.y + be.y);
        hv.z += gelu_exact((u.z - mean)*rstd*ga.z + be.z);
        hv.w += gelu_exact((u.w - mean)*rstd*ga.w + be.w);
        *(float4*)&g_h[idx] = hv;
        if (last){
            float mv = mask[(long)b*TLEN + t0 + t];
            float v0 = hv.x*mv, v1 = hv.y*mv, v2 = hv.z*mv, v3 = hv.w*mv;
            __nv_bfloat16 h0 = __float2bfloat16_rn(v0);
            __nv_bfloat16 h1 = __float2bfloat16_rn(v1);
            __nv_bfloat16 h2 = __float2bfloat16_rn(v2);
            __nv_bfloat16 h3 = __float2bfloat16_rn(v3);
            __nv_bfloat162 p0; p0.x = h0; p0.y = h1;
            __nv_bfloat162 p1; p1.x = h2; p1.y = h3;
            *(__nv_bfloat162*)&g_hhi[idx]   = p0;
            *(__nv_bfloat162*)&g_hhi[idx+2] = p1;
            __nv_bfloat162 q0, q1;
            q0.x = __float2bfloat16_rn(v0 - __bfloat162float(h0));
            q0.y = __float2bfloat16_rn(v1 - __bfloat162float(h1));
            q1.x = __float2bfloat16_rn(v2 - __bfloat162float(h2));
            q1.y = __float2bfloat16_rn(v3 - __bfloat162float(h3));
            *(__nv_bfloat162*)&g_hlo[idx]   = q0;
            *(__nv_bfloat162*)&g_hlo[idx+2] = q1;
        }
    }
}

// ---------------------------------------------------------------------------
// Kernel 4: 2-term bf16 GEMM (u = W @ h^T) via ldmatrix + mma.sync, fused
// with the RQ spline. CTA 256 thr / 8 warps (4m x 2n, n=64/warp).
// Tile M=128 x N=128 t, K=256 in 2 chunks.
// ---------------------------------------------------------------------------
__global__ __launch_bounds__(256, 2) void k_proj_mma(const float* __restrict__ x,
                                                     const float* __restrict__ mask,
                                                     const float* __restrict__ proj_b,
                                                     float* __restrict__ out){
    extern __shared__ char smem[];
    uint32_t sb = smem_u32(smem);
    int tid = threadIdx.x, lane = tid & 31, wid = tid >> 5;
    int t0 = blockIdx.x * NT;
    int mtile = blockIdx.y;
    int b = blockIdx.z;
    int m0 = mtile * MT;
    int ch0 = mtile * 4;

    float* smask = (float*)(smem + OFF_MASK);
    if (tid < NT) smask[tid] = mask[(long)b*TLEN + t0 + tid];

    float acc[2][8][4];
    #pragma unroll
    for (int mt = 0; mt < 2; mt++)
        #pragma unroll
        for (int nt = 0; nt < 8; nt++)
            #pragma unroll
            for (int q = 0; q < 4; q++) acc[mt][nt][q] = 0.f;

    int wm = wid & 3, wn = wid >> 2;
    uint32_t aoff = (uint32_t)((wm*32 + (lane & 15)) * ASTR + ((lane >> 4) * 8) * 2);
    uint32_t aH0 = sb + OFF_A + aoff, aH1 = aH0 + 16*ASTR;
    uint32_t boffc = (uint32_t)((((lane >> 4) * 8) + (lane & 7)) * BSTR
                                + ((lane >> 3) & 1) * 16);
    uint32_t bHp[2], bLp[2];
    #pragma unroll
    for (int hf = 0; hf < 2; hf++){
        uint32_t rowo = (uint32_t)((wn*64 + hf*32) * BSTR);
        bHp[hf] = sb + OFF_BHI + rowo + boffc;
        bLp[hf] = sb + OFF_BLO + rowo + boffc;
    }

    for (int c = 0; c < 2; c++){
        if (c) __syncthreads();
        // stage A (hi only): 128 rows x 16 uint4
        for (int i = tid; i < MT*16; i += 256){
            int r = i >> 4, g = i & 15;
            uint32_t off = (uint32_t)(r*ASTR + g*16);
            size_t s4 = ((size_t)(m0 + r))*32 + (size_t)c*16 + g;
            *(uint4*)(smem + OFF_A + off) = ((const uint4*)g_whi)[s4];
        }
        // stage B hi/lo: 128 t-rows x 16 uint4
        for (int i = tid; i < NT*16; i += 256){
            int r = i >> 4, g = i & 15;
            uint32_t off = (uint32_t)(r*BSTR + g*16);
            size_t s4 = ((size_t)b*TLEN + t0 + r)*32 + (size_t)c*16 + g;
            *(uint4*)(smem + OFF_BHI + off) = ((const uint4*)g_hhi)[s4];
            *(uint4*)(smem + OFF_BLO + off) = ((const uint4*)g_hlo)[s4];
        }
        __syncthreads();

        #pragma unroll
        for (int k16 = 0; k16 < 8; k16++){
            uint32_t ko = (uint32_t)(k16 * 32);
            uint32_t Ah[2][4];
            ldm4(Ah[0], aH0 + ko); ldm4(Ah[1], aH1 + ko);
            #pragma unroll
            for (int hf = 0; hf < 2; hf++){
                uint32_t Bh[2][4], Bl[2][4];
                ldm4(Bh[0], bHp[hf] + ko); ldm4(Bh[1], bHp[hf] + 16*BSTR + ko);
                ldm4(Bl[0], bLp[hf] + ko); ldm4(Bl[1], bLp[hf] + 16*BSTR + ko);
                #pragma unroll
                for (int mt = 0; mt < 2; mt++){
                    #pragma unroll
                    for (int nt = 0; nt < 4; nt++){
                        uint32_t h0 = Bh[nt>>1][(nt&1)*2], h1 = Bh[nt>>1][(nt&1)*2+1];
                        uint32_t l0 = Bl[nt>>1][(nt&1)*2], l1 = Bl[nt>>1][(nt&1)*2+1];
                        mma_bf16(acc[mt][hf*4+nt], Ah[mt], h0, h1);
                        mma_bf16(acc[mt][hf*4+nt], Ah[mt], l0, l1);
                    }
                }
            }
        }
    }
    __syncthreads();

    // u -> smem (alias over A/B regions): us[row][t], stride 129 floats
    float* us = (float*)smem;
    #pragma unroll
    for (int mt = 0; mt < 2; mt++){
        #pragma unroll
        for (int g = 0; g < 8; g++){
            int r = wm*32 + mt*16 + (lane >> 2);
            int t = wn*64 + g*8 + (lane & 3)*2;
            #pragma unroll
            for (int hh = 0; hh < 2; hh++){
                int rr = r + hh*8;
                int j = rr & 31;
                int ch = ch0 + (rr >> 5);
                float pb = (j < NJ) ? proj_b[ch*NJ + j] : 0.f;
                us[rr*USTRIDE + t]     = (acc[mt][g][2*hh+0] + pb) * smask[t];
                us[rr*USTRIDE + t + 1] = (acc[mt][g][2*hh+1] + pb) * smask[t+1];
            }
        }
    }
    __syncthreads();

    // --- spline: 4 ch x 128 t = 512 evals, 2 per thread ---
    const float SCALE = 0.0625f;
    int chl = tid >> 6;
    int ch = ch0 + chl;
    float ldsum = 0.f;

    #pragma unroll
    for (int it = 0; it < 2; it++){
        int tl = (tid & 63) + it*64;
        const float* ub = us + (chl*32)*USTRIDE + tl;   // ub[j*USTRIDE]
        float x1v = x[(long)b*CC*TLEN + (long)(HALF + ch)*TLEN + t0 + tl];
        float mv  = smask[tl];

        float uw[10];
        #pragma unroll
        for (int j = 0; j < 10; j++) uw[j] = ub[j*USTRIDE] * SCALE;
        float mx = uw[0];
        #pragma unroll
        for (int j = 1; j < 10; j++) mx = fmaxf(mx, uw[j]);
        float ew[10]; float sw = 0.f;
        #pragma unroll
        for (int j = 0; j < 10; j++){ ew[j] = expf(uw[j] - mx); sw += ew[j]; }
        float cw[11]; cw[0] = -5.f;
        {
            float inv = 1.f / sw, cs = 0.f;
            #pragma unroll
            for (int j = 0; j < 9; j++){
                cs += fmaf(0.99f, ew[j]*inv, 0.001f);
                cw[j+1] = fmaf(10.f, cs, -5.f);
            }
            cw[10] = 5.f;
        }
        #pragma unroll
        for (int j = 0; j < 10; j++) uw[j] = ub[(10+j)*USTRIDE] * SCALE;
        mx = uw[0];
        #pragma unroll
        for (int j = 1; j < 10; j++) mx = fmaxf(mx, uw[j]);
        sw = 0.f;
        #pragma unroll
        for (int j = 0; j < 10; j++){ ew[j] = expf(uw[j] - mx); sw += ew[j]; }
        float chh[11]; chh[0] = -5.f;
        {
            float inv = 1.f / sw, cs = 0.f;
            #pragma unroll
            for (int j = 0; j < 9; j++){
                cs += fmaf(0.99f, ew[j]*inv, 0.001f);
                chh[j+1] = fmaf(10.f, cs, -5.f);
            }
            chh[10] = 5.f;
        }

        float xc = fminf(fmaxf(x1v, -5.f), 5.f);
        int idx = 0;
        #pragma unroll
        for (int j = 1; j <= 9; j++) idx += (xc >= cw[j]) ? 1 : 0;

        float cwl = cw[0], cwr = cw[1], chl2 = chh[0], chr = chh[1];
        #pragma unroll
        for (int j = 1; j < 10; j++){
            if (idx == j){ cwl = cw[j]; cwr = cw[j+1]; chl2 = chh[j]; chr = chh[j+1]; }
        }
        float d0 = (idx == 0) ? 1.f : 0.001f + softplusf(ub[(19 + idx)*USTRIDE]);
        float d1 = (idx == 9) ? 1.f : 0.001f + softplusf(ub[(20 + idx)*USTRIDE]);

        float wb = cwr - cwl, hb = chr - chl2;
        float delta = hb / wb;
        float th = (xc - cwl) / wb;
        float omt = 1.f - th;
        float t1m = th * omt;
        float denom = delta + (d0 + d1 - 2.f*delta) * t1m;
        float num = hb * (delta*th*th + d0*t1m);
        float yv = chl2 + num / denom;
        float dnum = delta*delta * (d1*th*th + 2.f*delta*t1m + d0*omt*omt);
        float lad = logf(dnum) - 2.f*logf(denom);

        bool inside = (x1v >= -5.f) && (x1v <= 5.f);
        float ov = inside ? yv : x1v;
        ldsum += (inside ? lad : 0.f) * mv;

        out[(long)b*CC*TLEN + (long)(HALF + ch)*TLEN + t0 + tl] = ov * mv;
    }

    // logdet reduction
    #pragma unroll
    for (int off = 16; off; off >>= 1)
        ldsum += __shfl_xor_sync(0xFFFFFFFFu, ldsum, off);
    float* sred = (float*)(smem + OFF_RED);
    if (lane == 0) sred[wid] = ldsum;
    __syncthreads();
    if (tid == 0){
        float s = 0.f;
        #pragma unroll
        for (int k = 0; k < 8; k++) s += sred[k];
        atomicAdd(&out[(long)BB*CC*TLEN + b], s);
    }
}

// ---------------------------------------------------------------------------
extern "C" void kernel_launch(void* const* d_in, const int* in_sizes, int n_in,
                              void* d_out, int out_size){
    const float* x      = (const float*)d_in[0];
    const float* mask   = (const float*)d_in[1];
    const float* pre_w  = (const float*)d_in[2];
    const float* pre_b  = (const float*)d_in[3];
    const float* dw_w   = (const float*)d_in[4];
    const float* dw_b   = (const float*)d_in[5];
    const float* pw_w   = (const float*)d_in[6];
    const float* pw_b   = (const float*)d_in[7];
    const float* gamma1 = (const float*)d_in[8];
    const float* beta1  = (const float*)d_in[9];
    const float* gamma2 = (const float*)d_in[10];
    const float* beta2  = (const float*)d_in[11];
    const float* proj_w = (const float*)d_in[12];
    const float* proj_b = (const float*)d_in[13];
    float* out = (float*)d_out;

    cudaFuncSetAttribute(k_proj_mma, cudaFuncAttributeMaxDynamicSharedMemorySize,
                         PROJ_SMEM_BYTES);
    cudaFuncSetAttribute(k_pw_mma, cudaFuncAttributeMaxDynamicSharedMemorySize,
                         PW_SMEM_BYTES);

    k_prep_w<<<768, 256>>>(proj_w);
    k_prep_pw<<<192, 256>>>(pw_w);
    k_init<<<4096, 256>>>(x, mask, out);
    k_pre<<<dim3(TLEN/32, BB), 256>>>(x, pre_w, pre_b);

    int dil = 1;
    for (int i = 0; i < 3; i++){
        k_convnorm<<<dim3(TLEN/4, BB), 256>>>(mask,
                                            dw_w + (long)i*FF*3, dw_b + (long)i*FF,
                                            gamma1 + (long)i*FF, beta1 + (long)i*FF, dil);
        k_pw_mma<<<dim3(TLEN/64, BB), 512, PW_SMEM_BYTES>>>(i,
                                            pw_b + (long)i*FF,
                                            gamma2 + (long)i*FF, beta2 + (long)i*FF,
                                            mask, (i == 2) ? 1 : 0);
        dil *= 3;
    }

    k_proj_mma<<<dim3(TLEN/NT, MROWS/MT, BB), 256, PROJ_SMEM_BYTES>>>(x, mask, proj_b, out);
}

// round 8
// speedup vs baseline: 3.5473x; 1.0681x over previous
#include <cuda_runtime.h>
#include <cuda_bf16.h>
#include <math.h>
#include <cstdint>

#define BB 16
#define CC 192
#define HALF 96
#define TLEN 2048
#define FF 256
#define NB 10
#define NJ 29        // 3*NB - 1

// ---- proj mma tiling (2-term: W bf16-rounded, h hi/lo split) ----
#define MROWS 3072   // 96 ch * 32 padded rows
#define MT 128       // m-tile (4 channels)
#define NT 128       // t-tile
#define ASTR 272     // smem row stride bytes (128 bf16 + 16B pad)
#define BSTR 272
#define USTRIDE 129  // u smem row stride (floats), odd -> conflict-free

#define OFF_A    0            // 128*272 = 34816 (hi only)
#define OFF_BHI  34816        // 128*272
#define OFF_BLO  69632        // 128*272
#define OFF_MASK 104448       // 128 floats
#define OFF_RED  104960       // 8 floats
#define PROJ_SMEM_BYTES 105088

// ---- pw mma tiling (M=256 full channels, N=128 t, K staged in 4x64) ----
#define PASTR 144              // 64 bf16 + 16B pad
#define PW_OFF_AHI 0
#define PW_OFF_ALO 36864
#define PW_OFF_BHI 73728      // 128*144 = 18432
#define PW_OFF_BLO 92160
#define PW_SMEM_BYTES 110592
#define PW_USTR 260            // epilogue f32 row stride (words), 64 t per pass
#define PW_OFF_STAT 66560      // bytes; smean[64] | srstd[64]

// ---- pre mma tiling (M=256 f, N=64 t, K=96 whole) ----
#define PRE_STR 208            // 96 bf16 = 192B + 16B pad
#define PRE_OFF_AHI 0          // 256*208 = 53248
#define PRE_OFF_ALO 53248
#define PRE_OFF_BHI 106496     // 64*208 = 13312
#define PRE_OFF_BLO 119808
#define PRE_SMEM_BYTES 133120

// Scratch (allocation-free rule: __device__ globals). Layout: [b][t][f].
__device__ float g_h[(size_t)BB*TLEN*FF];
__device__ __nv_bfloat16 g_whi[(size_t)MROWS*FF];
__device__ __nv_bfloat16 g_hhi[(size_t)BB*TLEN*FF];
__device__ __nv_bfloat16 g_hlo[(size_t)BB*TLEN*FF];
__device__ __nv_bfloat16 g_yhi[(size_t)BB*TLEN*FF];
__device__ __nv_bfloat16 g_ylo[(size_t)BB*TLEN*FF];
__device__ __nv_bfloat16 g_pwhi[(size_t)3*FF*FF];
__device__ __nv_bfloat16 g_pwlo[(size_t)3*FF*FF];

__device__ __forceinline__ float gelu_exact(float v){
    return 0.5f * v * (1.f + erff(v * 0.70710678118654752f));
}
__device__ __forceinline__ float softplusf(float v){
    return v > 20.f ? v : log1pf(expf(v));
}
__device__ __forceinline__ uint32_t smem_u32(const void* p){
    uint32_t a;
    asm("{ .reg .u64 t; cvta.to.shared.u64 t, %1; cvt.u32.u64 %0, t; }" : "=r"(a) : "l"(p));
    return a;
}
__device__ __forceinline__ void ldm4(uint32_t* r, uint32_t addr){
    asm volatile("ldmatrix.sync.aligned.m8n8.x4.shared.b16 {%0,%1,%2,%3}, [%4];"
        : "=r"(r[0]),"=r"(r[1]),"=r"(r[2]),"=r"(r[3]) : "r"(addr));
}
__device__ __forceinline__ void mma_bf16(float* d, const uint32_t* a, uint32_t b0, uint32_t b1){
    asm volatile("mma.sync.aligned.m16n8k16.row.col.f32.bf16.bf16.f32 "
        "{%0,%1,%2,%3}, {%4,%5,%6,%7}, {%8,%9}, {%0,%1,%2,%3};"
        : "+f"(d[0]),"+f"(d[1]),"+f"(d[2]),"+f"(d[3])
        : "r"(a[0]),"r"(a[1]),"r"(a[2]),"r"(a[3]), "r"(b0),"r"(b1));
}

// ---------------------------------------------------------------------------
// Prep: bf16 (round-to-nearest) proj_w into padded [3072][256] rows
// ---------------------------------------------------------------------------
__global__ void k_prep_w(const float* __restrict__ proj_w){
    long n = (long)MROWS*FF;
    for (long i = (long)blockIdx.x*blockDim.x + threadIdx.x; i < n;
         i += (long)gridDim.x*blockDim.x){
        int k = (int)(i & (FF-1));
        int r = (int)(i >> 8);
        int ch = r >> 5, j = r & 31;
        float w = (j < NJ) ? proj_w[((long)(ch*NJ + j))*FF + k] : 0.f;
        g_whi[i] = __float2bfloat16_rn(w);
    }
}
// Prep: bf16 hi/lo split of all 3 pw weight matrices
__global__ void k_prep_pw(const float* __restrict__ pw_w){
    long n = 3L*FF*FF;
    for (long i = (long)blockIdx.x*blockDim.x + threadIdx.x; i < n;
         i += (long)gridDim.x*blockDim.x){
        float w = pw_w[i];
        __nv_bfloat16 hi = __float2bfloat16_rn(w);
        g_pwhi[i] = hi;
        g_pwlo[i] = __float2bfloat16_rn(w - __bfloat162float(hi));
    }
}

// ---------------------------------------------------------------------------
// Kernel 0: copy x0*mask into out[:, :96, :], zero logdet slots.
// ---------------------------------------------------------------------------
__global__ void k_init(const float* __restrict__ x, const float* __restrict__ mask,
                       float* __restrict__ out){
    long n = (long)BB * HALF * TLEN;
    for (long i = (long)blockIdx.x * blockDim.x + threadIdx.x; i < n;
         i += (long)gridDim.x * blockDim.x){
        int t = (int)(i % TLEN);
        long bc = i / TLEN;
        int c = (int)(bc % HALF);
        int b = (int)(bc / HALF);
        long src = (long)b*CC*TLEN + (long)c*TLEN + t;
        out[src] = x[src] * mask[(long)b*TLEN + t];
    }
    if (blockIdx.x == 0 && threadIdx.x < BB)
        out[(long)BB*CC*TLEN + threadIdx.x] = 0.f;
}

// ---------------------------------------------------------------------------
// Kernel 1: h = pre_w @ x0 + pre_b via ldmatrix+mma (bf16 3-term).
// CTA 512 thr / 16 warps (8m x 2n). Tile M=256 f x N=64 t x K=96 (one shot).
// ---------------------------------------------------------------------------
__global__ __launch_bounds__(512) void k_pre_mma(const float* __restrict__ x,
                                                 const float* __restrict__ pre_w,
                                                 const float* __restrict__ pre_b){
    extern __shared__ char smem[];
    uint32_t sb = smem_u32(smem);
    int tid = threadIdx.x, lane = tid & 31, wid = tid >> 5;
    int t0 = blockIdx.x * 64;
    int b = blockIdx.y;

    // stage A: pre_w [256][96] f32 -> bf16 hi/lo
    for (int i = tid; i < FF*HALF; i += 512){
        int f = i / HALF, c = i - f*HALF;
        float w = pre_w[i];
        __nv_bfloat16 hi = __float2bfloat16_rn(w);
        uint32_t off = (uint32_t)(f*PRE_STR + c*2);
        *(__nv_bfloat16*)(smem + PRE_OFF_AHI + off) = hi;
        *(__nv_bfloat16*)(smem + PRE_OFF_ALO + off) =
            __float2bfloat16_rn(w - __bfloat162float(hi));
    }
    // stage B: x0 [c][t] f32 -> smem [t][c] bf16 hi/lo (transpose)
    for (int i = tid; i < HALF*64; i += 512){
        int c = i >> 6, tt = i & 63;
        float v = x[(long)b*CC*TLEN + (long)c*TLEN + t0 + tt];
        __nv_bfloat16 hi = __float2bfloat16_rn(v);
        uint32_t off = (uint32_t)(tt*PRE_STR + c*2);
        *(__nv_bfloat16*)(smem + PRE_OFF_BHI + off) = hi;
        *(__nv_bfloat16*)(smem + PRE_OFF_BLO + off) =
            __float2bfloat16_rn(v - __bfloat162float(hi));
    }
    __syncthreads();

    int wm = wid & 7, wn = wid >> 3;
    float acc[2][4][4];
    #pragma unroll
    for (int mt = 0; mt < 2; mt++)
        #pragma unroll
        for (int nt = 0; nt < 4; nt++)
            #pragma unroll
            for (int q = 0; q < 4; q++) acc[mt][nt][q] = 0.f;

    uint32_t aoff = (uint32_t)((wm*32 + (lane & 15)) * PRE_STR + ((lane >> 4) * 8) * 2);
    uint32_t aH0 = sb + PRE_OFF_AHI + aoff, aH1 = aH0 + 16*PRE_STR;
    uint32_t aL0 = sb + PRE_OFF_ALO + aoff, aL1 = aL0 + 16*PRE_STR;
    uint32_t boff = (uint32_t)((wn*32 + ((lane >> 4) * 8) + (lane & 7)) * PRE_STR
                               + ((lane >> 3) & 1) * 16);
    uint32_t bH0 = sb + PRE_OFF_BHI + boff, bH1 = bH0 + 16*PRE_STR;
    uint32_t bL0 = sb + PRE_OFF_BLO + boff, bL1 = bL0 + 16*PRE_STR;

    #pragma unroll
    for (int k16 = 0; k16 < 6; k16++){
        uint32_t ko = (uint32_t)(k16 * 32);
        uint32_t Ah[2][4], Al[2][4], Bh[2][4], Bl[2][4];
        ldm4(Ah[0], aH0 + ko); ldm4(Ah[1], aH1 + ko);
        ldm4(Al[0], aL0 + ko); ldm4(Al[1], aL1 + ko);
        ldm4(Bh[0], bH0 + ko); ldm4(Bh[1], bH1 + ko);
        ldm4(Bl[0], bL0 + ko); ldm4(Bl[1], bL1 + ko);
        #pragma unroll
        for (int mt = 0; mt < 2; mt++){
            #pragma unroll
            for (int nt = 0; nt < 4; nt++){
                uint32_t h0 = Bh[nt>>1][(nt&1)*2], h1 = Bh[nt>>1][(nt&1)*2+1];
                uint32_t l0 = Bl[nt>>1][(nt&1)*2], l1 = Bl[nt>>1][(nt&1)*2+1];
                mma_bf16(acc[mt][nt], Ah[mt], h0, h1);
                mma_bf16(acc[mt][nt], Ah[mt], l0, l1);
                mma_bf16(acc[mt][nt], Al[mt], h0, h1);
            }
        }
    }
    __syncthreads();

    // epilogue: us[t][o] + bias, then coalesced f32 write
    float* us = (float*)smem;
    #pragma unroll
    for (int mt = 0; mt < 2; mt++){
        #pragma unroll
        for (int nt = 0; nt < 4; nt++){
            int t = wn*32 + nt*8 + (lane & 3)*2;
            int m = wm*32 + mt*16 + (lane >> 2);
            #pragma unroll
            for (int hh = 0; hh < 2; hh++){
                int o = m + hh*8;
                float pb = pre_b[o];
                us[t*PW_USTR + o]     = acc[mt][nt][2*hh+0] + pb;
                us[(t+1)*PW_USTR + o] = acc[mt][nt][2*hh+1] + pb;
            }
        }
    }
    __syncthreads();

    long gbase = ((long)b*TLEN + t0) * FF;
    for (int i = tid; i < 64*64; i += 512){
        int t = i >> 6, o4 = i & 63;
        *(float4*)&g_h[gbase + (long)t*FF + o4*4] = *(float4*)&us[t*PW_USTR + o4*4];
    }
}

// ---------------------------------------------------------------------------
// Kernel 2 (per layer): depthwise dilated conv + channel_norm + GELU,
// 4 t-columns per CTA. Writes bf16 hi/lo of y.
// ---------------------------------------------------------------------------
__global__ __launch_bounds__(256) void k_convnorm(const float* __restrict__ mask,
                                                  const float* __restrict__ dw_w,
                                                  const float* __restrict__ dw_b,
                                                  const float* __restrict__ gamma,
                                                  const float* __restrict__ beta,
                                                  int dil){
    int t0 = blockIdx.x * 4, b = blockIdx.y, f = threadIdx.x;
    long base = (long)b*TLEN*FF;
    const float* mrow = mask + (long)b*TLEN;
    __shared__ float ss[8], ssq[8];

    float w0 = dw_w[f*3+0], w1 = dw_w[f*3+1], w2 = dw_w[f*3+2];
    float bias = dw_b[f], ga = gamma[f], be = beta[f];
    int w = threadIdx.x >> 5, l = threadIdx.x & 31;

    #pragma unroll
    for (int tt = 0; tt < 4; tt++){
        int t = t0 + tt;
        float vl = 0.f, vr = 0.f;
        float vc = g_h[base + (long)t*FF + f] * mrow[t];
        if (t - dil >= 0)    vl = g_h[base + (long)(t-dil)*FF + f] * mrow[t - dil];
        if (t + dil < TLEN)  vr = g_h[base + (long)(t+dil)*FF + f] * mrow[t + dil];
        float v = fmaf(w0, vl, fmaf(w1, vc, fmaf(w2, vr, bias)));

        float s = v, sq = v*v;
        #pragma unroll
        for (int o = 16; o; o >>= 1){
            s  += __shfl_xor_sync(0xFFFFFFFFu, s,  o);
            sq += __shfl_xor_sync(0xFFFFFFFFu, sq, o);
        }
        if (l == 0){ ss[w] = s; ssq[w] = sq; }
        __syncthreads();
        s = 0.f; sq = 0.f;
        #pragma unroll
        for (int k = 0; k < 8; k++){ s += ss[k]; sq += ssq[k]; }
        __syncthreads();

        float mean = s * (1.f/FF);
        float var  = sq * (1.f/FF) - mean*mean;
        float rstd = rsqrtf(var + 1e-5f);
        float nv = (v - mean) * rstd * ga + be;
        float yv = gelu_exact(nv);
        __nv_bfloat16 hi = __float2bfloat16_rn(yv);
        g_yhi[base + (long)t*FF + f] = hi;
        g_ylo[base + (long)t*FF + f] = __float2bfloat16_rn(yv - __bfloat162float(hi));
    }
}

// ---------------------------------------------------------------------------
// Kernel 3 (per layer): y2 = pw_w @ y + pw_b via ldmatrix+mma (bf16 3-term),
// fused channel_norm + GELU + residual into g_h. Last layer also emits
// bf16 hi/lo of h*mask for the proj GEMM.
// CTA 512 thr / 16 warps (8m x 2n); tile M=256 x N=128 t; K=256 in 4x64.
// ---------------------------------------------------------------------------
__global__ __launch_bounds__(512) void k_pw_mma(int lay,
                                                const float* __restrict__ pw_b,
                                                const float* __restrict__ gamma,
                                                const float* __restrict__ beta,
                                                const float* __restrict__ mask,
                                                int last){
    extern __shared__ char smem[];
    uint32_t sb = smem_u32(smem);
    int tid = threadIdx.x, lane = tid & 31, wid = tid >> 5;
    int t0 = blockIdx.x * 128;
    int b = blockIdx.y;
    int wm = wid & 7, wn = wid >> 3;

    float acc[2][8][4];
    #pragma unroll
    for (int mt = 0; mt < 2; mt++)
        #pragma unroll
        for (int nt = 0; nt < 8; nt++)
            #pragma unroll
            for (int q = 0; q < 4; q++) acc[mt][nt][q] = 0.f;

    uint32_t aoff = (uint32_t)((wm*32 + (lane & 15)) * PASTR + ((lane >> 4) * 8) * 2);
    uint32_t aH0 = sb + PW_OFF_AHI + aoff, aH1 = aH0 + 16*PASTR;
    uint32_t aL0 = sb + PW_OFF_ALO + aoff, aL1 = aL0 + 16*PASTR;
    uint32_t boffc = (uint32_t)((((lane >> 4) * 8) + (lane & 7)) * PASTR
                                + ((lane >> 3) & 1) * 16);
    uint32_t bHp[2], bLp[2];
    #pragma unroll
    for (int hf = 0; hf < 2; hf++){
        uint32_t rowo = (uint32_t)((wn*64 + hf*32) * PASTR);
        bHp[hf] = sb + PW_OFF_BHI + rowo + boffc;
        bLp[hf] = sb + PW_OFF_BLO + rowo + boffc;
    }

    for (int c0 = 0; c0 < 4; c0++){
        if (c0) __syncthreads();
        for (int i = tid; i < FF*8; i += 512){
            int r = i >> 3, g = i & 7;
            uint32_t off = (uint32_t)(r*PASTR + g*16);
            size_t s4 = ((size_t)(lay*FF + r))*32 + (size_t)c0*8 + g;
            *(uint4*)(smem + PW_OFF_AHI + off) = ((const uint4*)g_pwhi)[s4];
            *(uint4*)(smem + PW_OFF_ALO + off) = ((const uint4*)g_pwlo)[s4];
        }
        for (int i = tid; i < 128*8; i += 512){
            int r = i >> 3, g = i & 7;
            uint32_t off = (uint32_t)(r*PASTR + g*16);
            size_t s4 = ((size_t)b*TLEN + t0 + r)*32 + (size_t)c0*8 + g;
            *(uint4*)(smem + PW_OFF_BHI + off) = ((const uint4*)g_yhi)[s4];
            *(uint4*)(smem + PW_OFF_BLO + off) = ((const uint4*)g_ylo)[s4];
        }
        __syncthreads();

        #pragma unroll
        for (int k16 = 0; k16 < 4; k16++){
            uint32_t ko = (uint32_t)(k16 * 32);
            uint32_t Ah[2][4], Al[2][4];
            ldm4(Ah[0], aH0 + ko); ldm4(Ah[1], aH1 + ko);
            ldm4(Al[0], aL0 + ko); ldm4(Al[1], aL1 + ko);
            #pragma unroll
            for (int hf = 0; hf < 2; hf++){
                uint32_t Bh[2][4], Bl[2][4];
                ldm4(Bh[0], bHp[hf] + ko); ldm4(Bh[1], bHp[hf] + 16*PASTR + ko);
                ldm4(Bl[0], bLp[hf] + ko); ldm4(Bl[1], bLp[hf] + 16*PASTR + ko);
                #pragma unroll
                for (int mt = 0; mt < 2; mt++){
                    #pragma unroll
                    for (int nt = 0; nt < 4; nt++){
                        uint32_t h0 = Bh[nt>>1][(nt&1)*2], h1 = Bh[nt>>1][(nt&1)*2+1];
                        uint32_t l0 = Bl[nt>>1][(nt&1)*2], l1 = Bl[nt>>1][(nt&1)*2+1];
                        mma_bf16(acc[mt][hf*4+nt], Ah[mt], h0, h1);
                        mma_bf16(acc[mt][hf*4+nt], Ah[mt], l0, l1);
                        mma_bf16(acc[mt][hf*4+nt], Al[mt], h0, h1);
                    }
                }
            }
        }
    }

    // epilogue in two 64-t passes over the aliased smem buffer
    float* us = (float*)smem;
    float* smean = (float*)(smem + PW_OFF_STAT);
    float* srstd = smean + 64;

    for (int p = 0; p < 2; p++){
        __syncthreads();
        if (wn == p){
            #pragma unroll
            for (int mt = 0; mt < 2; mt++){
                #pragma unroll
                for (int nt = 0; nt < 8; nt++){
                    int tl = nt*8 + (lane & 3)*2;
                    int m = wm*32 + mt*16 + (lane >> 2);
                    #pragma unroll
                    for (int hh = 0; hh < 2; hh++){
                        int o = m + hh*8;
                        float pb = pw_b[o];
                        us[tl*PW_USTR + o]     = acc[mt][nt][2*hh+0] + pb;
                        us[(tl+1)*PW_USTR + o] = acc[mt][nt][2*hh+1] + pb;
                    }
                }
            }
        }
        __syncthreads();

        #pragma unroll
        for (int it = 0; it < 4; it++){
            int t = wid*4 + it;
            float s = 0.f, sq = 0.f;
            #pragma unroll
            for (int k = 0; k < 8; k++){
                float v = us[t*PW_USTR + lane + k*32];
                s += v; sq += v*v;
            }
            #pragma unroll
            for (int off = 16; off; off >>= 1){
                s  += __shfl_xor_sync(0xFFFFFFFFu, s,  off);
                sq += __shfl_xor_sync(0xFFFFFFFFu, sq, off);
            }
            if (lane == 0){
                float mean = s * (1.f/FF);
                smean[t] = mean;
                srstd[t] = rsqrtf(sq * (1.f/FF) - mean*mean + 1e-5f);
            }
        }
        __syncthreads();

        long gbase = ((long)b*TLEN + t0 + p*64) * FF;
        for (int i = tid; i < 64*64; i += 512){
            int t = i >> 6, o4 = i & 63;
            float4 u = *(float4*)&us[t*PW_USTR + o4*4];
            float mean = smean[t], rstd = srstd[t];
            const float4 ga = *(const float4*)&gamma[o4*4];
            const float4 be = *(const float4*)&beta[o4*4];
            long idx = gbase + (long)t*FF + o4*4;
            float4 hv = *(float4*)&g_h[idx];
            hv.x += gelu_exact((u.x - mean)*rstd*ga.x + be.x);
            hv.y += gelu_exact((u.y - mean)*rstd*ga.y + be.y);
            hv.z += gelu_exact((u.z - mean)*rstd*ga.z + be.z);
            hv.w += gelu_exact((u.w - mean)*rstd*ga.w + be.w);
            *(float4*)&g_h[idx] = hv;
            if (last){
                float mv = mask[(long)b*TLEN + t0 + p*64 + t];
                float v0 = hv.x*mv, v1 = hv.y*mv, v2 = hv.z*mv, v3 = hv.w*mv;
                __nv_bfloat16 h0 = __float2bfloat16_rn(v0);
                __nv_bfloat16 h1 = __float2bfloat16_rn(v1);
                __nv_bfloat16 h2 = __float2bfloat16_rn(v2);
                __nv_bfloat16 h3 = __float2bfloat16_rn(v3);
                __nv_bfloat162 p0; p0.x = h0; p0.y = h1;
                __nv_bfloat162 p1; p1.x = h2; p1.y = h3;
                *(__nv_bfloat162*)&g_hhi[idx]   = p0;
                *(__nv_bfloat162*)&g_hhi[idx+2] = p1;
                __nv_bfloat162 q0, q1;
                q0.x = __float2bfloat16_rn(v0 - __bfloat162float(h0));
                q0.y = __float2bfloat16_rn(v1 - __bfloat162float(h1));
                q1.x = __float2bfloat16_rn(v2 - __bfloat162float(h2));
                q1.y = __float2bfloat16_rn(v3 - __bfloat162float(h3));
                *(__nv_bfloat162*)&g_hlo[idx]   = q0;
                *(__nv_bfloat162*)&g_hlo[idx+2] = q1;
            }
        }
    }
}

// ---------------------------------------------------------------------------
// Kernel 4: 2-term bf16 GEMM (u = W @ h^T) via ldmatrix + mma.sync, fused
// with the RQ spline. CTA 256 thr / 8 warps (4m x 2n, n=64/warp).
// Tile M=128 x N=128 t, K=256 in 2 chunks.
// ---------------------------------------------------------------------------
__global__ __launch_bounds__(256, 2) void k_proj_mma(const float* __restrict__ x,
                                                     const float* __restrict__ mask,
                                                     const float* __restrict__ proj_b,
                                                     float* __restrict__ out){
    extern __shared__ char smem[];
    uint32_t sb = smem_u32(smem);
    int tid = threadIdx.x, lane = tid & 31, wid = tid >> 5;
    int t0 = blockIdx.x * NT;
    int mtile = blockIdx.y;
    int b = blockIdx.z;
    int m0 = mtile * MT;
    int ch0 = mtile * 4;

    float* smask = (float*)(smem + OFF_MASK);
    if (tid < NT) smask[tid] = mask[(long)b*TLEN + t0 + tid];

    float acc[2][8][4];
    #pragma unroll
    for (int mt = 0; mt < 2; mt++)
        #pragma unroll
        for (int nt = 0; nt < 8; nt++)
            #pragma unroll
            for (int q = 0; q < 4; q++) acc[mt][nt][q] = 0.f;

    int wm = wid & 3, wn = wid >> 2;
    uint32_t aoff = (uint32_t)((wm*32 + (lane & 15)) * ASTR + ((lane >> 4) * 8) * 2);
    uint32_t aH0 = sb + OFF_A + aoff, aH1 = aH0 + 16*ASTR;
    uint32_t boffc = (uint32_t)((((lane >> 4) * 8) + (lane & 7)) * BSTR
                                + ((lane >> 3) & 1) * 16);
    uint32_t bHp[2], bLp[2];
    #pragma unroll
    for (int hf = 0; hf < 2; hf++){
        uint32_t rowo = (uint32_t)((wn*64 + hf*32) * BSTR);
        bHp[hf] = sb + OFF_BHI + rowo + boffc;
        bLp[hf] = sb + OFF_BLO + rowo + boffc;
    }

    for (int c = 0; c < 2; c++){
        if (c) __syncthreads();
        for (int i = tid; i < MT*16; i += 256){
            int r = i >> 4, g = i & 15;
            uint32_t off = (uint32_t)(r*ASTR + g*16);
            size_t s4 = ((size_t)(m0 + r))*32 + (size_t)c*16 + g;
            *(uint4*)(smem + OFF_A + off) = ((const uint4*)g_whi)[s4];
        }
        for (int i = tid; i < NT*16; i += 256){
            int r = i >> 4, g = i & 15;
            uint32_t off = (uint32_t)(r*BSTR + g*16);
            size_t s4 = ((size_t)b*TLEN + t0 + r)*32 + (size_t)c*16 + g;
            *(uint4*)(smem + OFF_BHI + off) = ((const uint4*)g_hhi)[s4];
            *(uint4*)(smem + OFF_BLO + off) = ((const uint4*)g_hlo)[s4];
        }
        __syncthreads();

        #pragma unroll
        for (int k16 = 0; k16 < 8; k16++){
            uint32_t ko = (uint32_t)(k16 * 32);
            uint32_t Ah[2][4];
            ldm4(Ah[0], aH0 + ko); ldm4(Ah[1], aH1 + ko);
            #pragma unroll
            for (int hf = 0; hf < 2; hf++){
                uint32_t Bh[2][4], Bl[2][4];
                ldm4(Bh[0], bHp[hf] + ko); ldm4(Bh[1], bHp[hf] + 16*BSTR + ko);
                ldm4(Bl[0], bLp[hf] + ko); ldm4(Bl[1], bLp[hf] + 16*BSTR + ko);
                #pragma unroll
                for (int mt = 0; mt < 2; mt++){
                    #pragma unroll
                    for (int nt = 0; nt < 4; nt++){
                        uint32_t h0 = Bh[nt>>1][(nt&1)*2], h1 = Bh[nt>>1][(nt&1)*2+1];
                        uint32_t l0 = Bl[nt>>1][(nt&1)*2], l1 = Bl[nt>>1][(nt&1)*2+1];
                        mma_bf16(acc[mt][hf*4+nt], Ah[mt], h0, h1);
                        mma_bf16(acc[mt][hf*4+nt], Ah[mt], l0, l1);
                    }
                }
            }
        }
    }
    __syncthreads();

    // u -> smem (alias over A/B regions): us[row][t], stride 129 floats
    float* us = (float*)smem;
    #pragma unroll
    for (int mt = 0; mt < 2; mt++){
        #pragma unroll
        for (int g = 0; g < 8; g++){
            int r = wm*32 + mt*16 + (lane >> 2);
            int t = wn*64 + g*8 + (lane & 3)*2;
            #pragma unroll
            for (int hh = 0; hh < 2; hh++){
                int rr = r + hh*8;
                int j = rr & 31;
                int ch = ch0 + (rr >> 5);
                float pb = (j < NJ) ? proj_b[ch*NJ + j] : 0.f;
                us[rr*USTRIDE + t]     = (acc[mt][g][2*hh+0] + pb) * smask[t];
                us[rr*USTRIDE + t + 1] = (acc[mt][g][2*hh+1] + pb) * smask[t+1];
            }
        }
    }
    __syncthreads();

    // --- spline: 4 ch x 128 t = 512 evals, 2 per thread ---
    const float SCALE = 0.0625f;
    int chl = tid >> 6;
    int ch = ch0 + chl;
    float ldsum = 0.f;

    #pragma unroll
    for (int it = 0; it < 2; it++){
        int tl = (tid & 63) + it*64;
        const float* ub = us + (chl*32)*USTRIDE + tl;   // ub[j*USTRIDE]
        float x1v = x[(long)b*CC*TLEN + (long)(HALF + ch)*TLEN + t0 + tl];
        float mv  = smask[tl];

        float uw[10];
        #pragma unroll
        for (int j = 0; j < 10; j++) uw[j] = ub[j*USTRIDE] * SCALE;
        float mx = uw[0];
        #pragma unroll
        for (int j = 1; j < 10; j++) mx = fmaxf(mx, uw[j]);
        float ew[10]; float sw = 0.f;
        #pragma unroll
        for (int j = 0; j < 10; j++){ ew[j] = expf(uw[j] - mx); sw += ew[j]; }
        float cw[11]; cw[0] = -5.f;
        {
            float inv = 1.f / sw, cs = 0.f;
            #pragma unroll
            for (int j = 0; j < 9; j++){
                cs += fmaf(0.99f, ew[j]*inv, 0.001f);
                cw[j+1] = fmaf(10.f, cs, -5.f);
            }
            cw[10] = 5.f;
        }
        #pragma unroll
        for (int j = 0; j < 10; j++) uw[j] = ub[(10+j)*USTRIDE] * SCALE;
        mx = uw[0];
        #pragma unroll
        for (int j = 1; j < 10; j++) mx = fmaxf(mx, uw[j]);
        sw = 0.f;
        #pragma unroll
        for (int j = 0; j < 10; j++){ ew[j] = expf(uw[j] - mx); sw += ew[j]; }
        float chh[11]; chh[0] = -5.f;
        {
            float inv = 1.f / sw, cs = 0.f;
            #pragma unroll
            for (int j = 0; j < 9; j++){
                cs += fmaf(0.99f, ew[j]*inv, 0.001f);
                chh[j+1] = fmaf(10.f, cs, -5.f);
            }
            chh[10] = 5.f;
        }

        float xc = fminf(fmaxf(x1v, -5.f), 5.f);
        int idx = 0;
        #pragma unroll
        for (int j = 1; j <= 9; j++) idx += (xc >= cw[j]) ? 1 : 0;

        float cwl = cw[0], cwr = cw[1], chl2 = chh[0], chr = chh[1];
        #pragma unroll
        for (int j = 1; j < 10; j++){
            if (idx == j){ cwl = cw[j]; cwr = cw[j+1]; chl2 = chh[j]; chr = chh[j+1]; }
        }
        float d0 = (idx == 0) ? 1.f : 0.001f + softplusf(ub[(19 + idx)*USTRIDE]);
        float d1 = (idx == 9) ? 1.f : 0.001f + softplusf(ub[(20 + idx)*USTRIDE]);

        float wb = cwr - cwl, hb = chr - chl2;
        float delta = hb / wb;
        float th = (xc - cwl) / wb;
        float omt = 1.f - th;
        float t1m = th * omt;
        float denom = delta + (d0 + d1 - 2.f*delta) * t1m;
        float num = hb * (delta*th*th + d0*t1m);
        float yv = chl2 + num / denom;
        float dnum = delta*delta * (d1*th*th + 2.f*delta*t1m + d0*omt*omt);
        float lad = logf(dnum) - 2.f*logf(denom);

        bool inside = (x1v >= -5.f) && (x1v <= 5.f);
        float ov = inside ? yv : x1v;
        ldsum += (inside ? lad : 0.f) * mv;

        out[(long)b*CC*TLEN + (long)(HALF + ch)*TLEN + t0 + tl] = ov * mv;
    }

    // logdet reduction
    #pragma unroll
    for (int off = 16; off; off >>= 1)
        ldsum += __shfl_xor_sync(0xFFFFFFFFu, ldsum, off);
    float* sred = (float*)(smem + OFF_RED);
    if (lane == 0) sred[wid] = ldsum;
    __syncthreads();
    if (tid == 0){
        float s = 0.f;
        #pragma unroll
        for (int k = 0; k < 8; k++) s += sred[k];
        atomicAdd(&out[(long)BB*CC*TLEN + b], s);
    }
}

// ---------------------------------------------------------------------------
extern "C" void kernel_launch(void* const* d_in, const int* in_sizes, int n_in,
                              void* d_out, int out_size){
    const float* x      = (const float*)d_in[0];
    const float* mask   = (const float*)d_in[1];
    const float* pre_w  = (const float*)d_in[2];
    const float* pre_b  = (const float*)d_in[3];
    const float* dw_w   = (const float*)d_in[4];
    const float* dw_b   = (const float*)d_in[5];
    const float* pw_w   = (const float*)d_in[6];
    const float* pw_b   = (const float*)d_in[7];
    const float* gamma1 = (const float*)d_in[8];
    const float* beta1  = (const float*)d_in[9];
    const float* gamma2 = (const float*)d_in[10];
    const float* beta2  = (const float*)d_in[11];
    const float* proj_w = (const float*)d_in[12];
    const float* proj_b = (const float*)d_in[13];
    float* out = (float*)d_out;

    cudaFuncSetAttribute(k_proj_mma, cudaFuncAttributeMaxDynamicSharedMemorySize,
                         PROJ_SMEM_BYTES);
    cudaFuncSetAttribute(k_pw_mma, cudaFuncAttributeMaxDynamicSharedMemorySize,
                         PW_SMEM_BYTES);
    cudaFuncSetAttribute(k_pre_mma, cudaFuncAttributeMaxDynamicSharedMemorySize,
                         PRE_SMEM_BYTES);

    k_prep_w<<<768, 256>>>(proj_w);
    k_prep_pw<<<192, 256>>>(pw_w);
    k_init<<<4096, 256>>>(x, mask, out);
    k_pre_mma<<<dim3(TLEN/64, BB), 512, PRE_SMEM_BYTES>>>(x, pre_w, pre_b);

    int dil = 1;
    for (int i = 0; i < 3; i++){
        k_convnorm<<<dim3(TLEN/4, BB), 256>>>(mask,
                                            dw_w + (long)i*FF*3, dw_b + (long)i*FF,
                                            gamma1 + (long)i*FF, beta1 + (long)i*FF, dil);
        k_pw_mma<<<dim3(TLEN/128, BB), 512, PW_SMEM_BYTES>>>(i,
                                            pw_b + (long)i*FF,
                                            gamma2 + (long)i*FF, beta2 + (long)i*FF,
                                            mask, (i == 2) ? 1 : 0);
        dil *= 3;
    }

    k_proj_mma<<<dim3(TLEN/NT, MROWS/MT, BB), 256, PROJ_SMEM_BYTES>>>(x, mask, proj_b, out);
}

// round 10
// speedup vs baseline: 3.7167x; 1.0478x over previous
#include <cuda_runtime.h>
#include <cuda_bf16.h>
#include <math.h>
#include <cstdint>

#define BB 16
#define CC 192
#define HALF 96
#define TLEN 2048
#define FF 256
#define NB 10
#define NJ 29        // 3*NB - 1

// ---- proj mma tiling (2-term: W bf16-rounded, h hi/lo split) ----
#define MROWS 3072   // 96 ch * 32 padded rows
#define MT 128       // m-tile (4 channels)
#define NT 128       // t-tile
#define ASTR 272     // smem row stride bytes (128 bf16 + 16B pad)
#define BSTR 272
#define USTRIDE 129  // u smem row stride (floats), odd -> conflict-free

#define OFF_A    0            // 128*272 = 34816 (hi only)
#define OFF_BHI  34816        // 128*272
#define OFF_BLO  69632        // 128*272
#define OFF_MASK 104448       // 128 floats
#define OFF_RED  104960       // 8 floats
#define PROJ_SMEM_BYTES 105088

// ---- pw mma tiling (M=256 full channels, N=128 t, K staged in 4x64) ----
#define PASTR 144              // 64 bf16 + 16B pad
#define PW_OFF_AHI 0
#define PW_OFF_ALO 36864
#define PW_OFF_BHI 73728
#define PW_OFF_BLO 92160
#define PW_SMEM_BYTES 110592
#define PW_USTR 260            // epilogue f32 row stride (words), 64 t per pass
#define PW_OFF_STAT 66560      // bytes; smean[64] | srstd[64]

// ---- pre mma tiling (M=256 f, N=128 t, K=96 whole) ----
#define PRE_STR 208            // 96 bf16 = 192B + 16B pad
#define PRE_OFF_AHI 0          // 256*208 = 53248
#define PRE_OFF_ALO 53248
#define PRE_OFF_BHI 106496     // 128*208 = 26624
#define PRE_OFF_BLO 133120
#define PRE_SMEM_BYTES 159744

// Scratch (allocation-free rule: __device__ globals). Layout: [b][t][f].
__device__ float g_h[(size_t)BB*TLEN*FF];
__device__ __nv_bfloat16 g_whi[(size_t)MROWS*FF];
__device__ __nv_bfloat16 g_hhi[(size_t)BB*TLEN*FF];
__device__ __nv_bfloat16 g_hlo[(size_t)BB*TLEN*FF];
__device__ __nv_bfloat16 g_yhi[(size_t)BB*TLEN*FF];
__device__ __nv_bfloat16 g_ylo[(size_t)BB*TLEN*FF];
__device__ __nv_bfloat16 g_pwhi[(size_t)3*FF*FF];
__device__ __nv_bfloat16 g_pwlo[(size_t)3*FF*FF];
__device__ __nv_bfloat16 g_prehi[(size_t)FF*HALF];
__device__ __nv_bfloat16 g_prelo[(size_t)FF*HALF];

__device__ __forceinline__ float gelu_exact(float v){
    return 0.5f * v * (1.f + erff(v * 0.70710678118654752f));
}
__device__ __forceinline__ float softplusf(float v){
    return v > 20.f ? v : log1pf(expf(v));
}
__device__ __forceinline__ uint32_t smem_u32(const void* p){
    uint32_t a;
    asm("{ .reg .u64 t; cvta.to.shared.u64 t, %1; cvt.u32.u64 %0, t; }" : "=r"(a) : "l"(p));
    return a;
}
__device__ __forceinline__ void ldm4(uint32_t* r, uint32_t addr){
    asm volatile("ldmatrix.sync.aligned.m8n8.x4.shared.b16 {%0,%1,%2,%3}, [%4];"
        : "=r"(r[0]),"=r"(r[1]),"=r"(r[2]),"=r"(r[3]) : "r"(addr));
}
__device__ __forceinline__ void mma_bf16(float* d, const uint32_t* a, uint32_t b0, uint32_t b1){
    asm volatile("mma.sync.aligned.m16n8k16.row.col.f32.bf16.bf16.f32 "
        "{%0,%1,%2,%3}, {%4,%5,%6,%7}, {%8,%9}, {%0,%1,%2,%3};"
        : "+f"(d[0]),"+f"(d[1]),"+f"(d[2]),"+f"(d[3])
        : "r"(a[0]),"r"(a[1]),"r"(a[2]),"r"(a[3]), "r"(b0),"r"(b1));
}
__device__ __forceinline__ void cp16(uint32_t saddr, const void* gptr){
    asm volatile("cp.async.cg.shared.global [%0], [%1], 16;"
        :: "r"(saddr), "l"(gptr));
}
__device__ __forceinline__ void cp_wait_all(){
    asm volatile("cp.async.commit_group;");
    asm volatile("cp.async.wait_all;" ::: "memory");
}

// ---------------------------------------------------------------------------
// Prep kernels (one-time weight conversion)
// ---------------------------------------------------------------------------
__global__ void k_prep_w(const float* __restrict__ proj_w){
    long n = (long)MROWS*FF;
    for (long i = (long)blockIdx.x*blockDim.x + threadIdx.x; i < n;
         i += (long)gridDim.x*blockDim.x){
        int k = (int)(i & (FF-1));
        int r = (int)(i >> 8);
        int ch = r >> 5, j = r & 31;
        float w = (j < NJ) ? proj_w[((long)(ch*NJ + j))*FF + k] : 0.f;
        g_whi[i] = __float2bfloat16_rn(w);
    }
}
__global__ void k_prep_pw(const float* __restrict__ pw_w){
    long n = 3L*FF*FF;
    for (long i = (long)blockIdx.x*blockDim.x + threadIdx.x; i < n;
         i += (long)gridDim.x*blockDim.x){
        float w = pw_w[i];
        __nv_bfloat16 hi = __float2bfloat16_rn(w);
        g_pwhi[i] = hi;
        g_pwlo[i] = __float2bfloat16_rn(w - __bfloat162float(hi));
    }
}
__global__ void k_prep_pre(const float* __restrict__ pre_w){
    long n = (long)FF*HALF;
    for (long i = (long)blockIdx.x*blockDim.x + threadIdx.x; i < n;
         i += (long)gridDim.x*blockDim.x){
        float w = pre_w[i];
        __nv_bfloat16 hi = __float2bfloat16_rn(w);
        g_prehi[i] = hi;
        g_prelo[i] = __float2bfloat16_rn(w - __bfloat162float(hi));
    }
}

// ---------------------------------------------------------------------------
// Kernel 0: copy x0*mask into out[:, :96, :], zero logdet slots.
// ---------------------------------------------------------------------------
__global__ void k_init(const float* __restrict__ x, const float* __restrict__ mask,
                       float* __restrict__ out){
    long n = (long)BB * HALF * TLEN;
    for (long i = (long)blockIdx.x * blockDim.x + threadIdx.x; i < n;
         i += (long)gridDim.x * blockDim.x){
        int t = (int)(i % TLEN);
        long bc = i / TLEN;
        int c = (int)(bc % HALF);
        int b = (int)(bc / HALF);
        long src = (long)b*CC*TLEN + (long)c*TLEN + t;
        out[src] = x[src] * mask[(long)b*TLEN + t];
    }
    if (blockIdx.x == 0 && threadIdx.x < BB)
        out[(long)BB*CC*TLEN + threadIdx.x] = 0.f;
}

// ---------------------------------------------------------------------------
// Kernel 1: h = pre_w @ x0 + pre_b via ldmatrix+mma (bf16 3-term).
// CTA 512 thr / 16 warps (8m x 2n). Tile M=256 f x N=128 t x K=96 (one shot).
// A from prepped hi/lo globals via cp.async; B transposed on the fly.
// ---------------------------------------------------------------------------
__global__ __launch_bounds__(512) void k_pre_mma(const float* __restrict__ x,
                                                 const float* __restrict__ pre_b){
    extern __shared__ char smem[];
    uint32_t sb = smem_u32(smem);
    int tid = threadIdx.x, lane = tid & 31, wid = tid >> 5;
    int t0 = blockIdx.x * 128;
    int b = blockIdx.y;

    // stage A hi/lo via cp.async: 256 rows x 12 uint4 (192B of K=96 bf16)
    for (int i = tid; i < FF*12; i += 512){
        int r = i / 12, g = i - r*12;
        uint32_t off = (uint32_t)(r*PRE_STR + g*16);
        cp16(sb + PRE_OFF_AHI + off, ((const uint4*)g_prehi) + (size_t)r*12 + g);
        cp16(sb + PRE_OFF_ALO + off, ((const uint4*)g_prelo) + (size_t)r*12 + g);
    }
    // stage B: x0 [c][t] f32 -> smem [t][c] bf16 hi/lo (transpose)
    for (int i = tid; i < HALF*128; i += 512){
        int c = i >> 7, tt = i & 127;
        float v = x[(long)b*CC*TLEN + (long)c*TLEN + t0 + tt];
        __nv_bfloat16 hi = __float2bfloat16_rn(v);
        uint32_t off = (uint32_t)(tt*PRE_STR + c*2);
        *(__nv_bfloat16*)(smem + PRE_OFF_BHI + off) = hi;
        *(__nv_bfloat16*)(smem + PRE_OFF_BLO + off) =
            __float2bfloat16_rn(v - __bfloat162float(hi));
    }
    cp_wait_all();
    __syncthreads();

    int wm = wid & 7, wn = wid >> 3;
    float acc[2][8][4];
    #pragma unroll
    for (int mt = 0; mt < 2; mt++)
        #pragma unroll
        for (int nt = 0; nt < 8; nt++)
            #pragma unroll
            for (int q = 0; q < 4; q++) acc[mt][nt][q] = 0.f;

    uint32_t aoff = (uint32_t)((wm*32 + (lane & 15)) * PRE_STR + ((lane >> 4) * 8) * 2);
    uint32_t aH0 = sb + PRE_OFF_AHI + aoff, aH1 = aH0 + 16*PRE_STR;
    uint32_t aL0 = sb + PRE_OFF_ALO + aoff, aL1 = aL0 + 16*PRE_STR;
    uint32_t boffc = (uint32_t)((((lane >> 4) * 8) + (lane & 7)) * PRE_STR
                                + ((lane >> 3) & 1) * 16);
    uint32_t bHp[2], bLp[2];
    #pragma unroll
    for (int hf = 0; hf < 2; hf++){
        uint32_t rowo = (uint32_t)((wn*64 + hf*32) * PRE_STR);
        bHp[hf] = sb + PRE_OFF_BHI + rowo + boffc;
        bLp[hf] = sb + PRE_OFF_BLO + rowo + boffc;
    }

    #pragma unroll
    for (int k16 = 0; k16 < 6; k16++){
        uint32_t ko = (uint32_t)(k16 * 32);
        uint32_t Ah[2][4], Al[2][4];
        ldm4(Ah[0], aH0 + ko); ldm4(Ah[1], aH1 + ko);
        ldm4(Al[0], aL0 + ko); ldm4(Al[1], aL1 + ko);
        #pragma unroll
        for (int hf = 0; hf < 2; hf++){
            uint32_t Bh[2][4], Bl[2][4];
            ldm4(Bh[0], bHp[hf] + ko); ldm4(Bh[1], bHp[hf] + 16*PRE_STR + ko);
            ldm4(Bl[0], bLp[hf] + ko); ldm4(Bl[1], bLp[hf] + 16*PRE_STR + ko);
            #pragma unroll
            for (int mt = 0; mt < 2; mt++){
                #pragma unroll
                for (int nt = 0; nt < 4; nt++){
                    uint32_t h0 = Bh[nt>>1][(nt&1)*2], h1 = Bh[nt>>1][(nt&1)*2+1];
                    uint32_t l0 = Bl[nt>>1][(nt&1)*2], l1 = Bl[nt>>1][(nt&1)*2+1];
                    mma_bf16(acc[mt][hf*4+nt], Ah[mt], h0, h1);
                    mma_bf16(acc[mt][hf*4+nt], Ah[mt], l0, l1);
                    mma_bf16(acc[mt][hf*4+nt], Al[mt], h0, h1);
                }
            }
        }
    }

    // epilogue in two 64-t passes over the aliased smem buffer
    float* us = (float*)smem;
    for (int p = 0; p < 2; p++){
        __syncthreads();
        if (wn == p){
            #pragma unroll
            for (int mt = 0; mt < 2; mt++){
                #pragma unroll
                for (int nt = 0; nt < 8; nt++){
                    int tl = nt*8 + (lane & 3)*2;
                    int m = wm*32 + mt*16 + (lane >> 2);
                    #pragma unroll
                    for (int hh = 0; hh < 2; hh++){
                        int o = m + hh*8;
                        float pb = pre_b[o];
                        us[tl*PW_USTR + o]     = acc[mt][nt][2*hh+0] + pb;
                        us[(tl+1)*PW_USTR + o] = acc[mt][nt][2*hh+1] + pb;
                    }
                }
            }
        }
        __syncthreads();
        long gbase = ((long)b*TLEN + t0 + p*64) * FF;
        for (int i = tid; i < 64*64; i += 512){
            int t = i >> 6, o4 = i & 63;
            *(float4*)&g_h[gbase + (long)t*FF + o4*4] = *(float4*)&us[t*PW_USTR + o4*4];
        }
    }
}

// ---------------------------------------------------------------------------
// Kernel 2 (per layer): depthwise dilated conv + channel_norm + GELU,
// 4 t-columns per CTA. Writes bf16 hi/lo of y.
// ---------------------------------------------------------------------------
__global__ __launch_bounds__(256) void k_convnorm(const float* __restrict__ mask,
                                                  const float* __restrict__ dw_w,
                                                  const float* __restrict__ dw_b,
                                                  const float* __restrict__ gamma,
                                                  const float* __restrict__ beta,
                                                  int dil){
    int t0 = blockIdx.x * 4, b = blockIdx.y, f = threadIdx.x;
    long base = (long)b*TLEN*FF;
    const float* mrow = mask + (long)b*TLEN;
    __shared__ float ss[8], ssq[8];

    float w0 = dw_w[f*3+0], w1 = dw_w[f*3+1], w2 = dw_w[f*3+2];
    float bias = dw_b[f], ga = gamma[f], be = beta[f];
    int w = threadIdx.x >> 5, l = threadIdx.x & 31;

    #pragma unroll
    for (int tt = 0; tt < 4; tt++){
        int t = t0 + tt;
        float vl = 0.f, vr = 0.f;
        float vc = g_h[base + (long)t*FF + f] * mrow[t];
        if (t - dil >= 0)    vl = g_h[base + (long)(t-dil)*FF + f] * mrow[t - dil];
        if (t + dil < TLEN)  vr = g_h[base + (long)(t+dil)*FF + f] * mrow[t + dil];
        float v = fmaf(w0, vl, fmaf(w1, vc, fmaf(w2, vr, bias)));

        float s = v, sq = v*v;
        #pragma unroll
        for (int o = 16; o; o >>= 1){
            s  += __shfl_xor_sync(0xFFFFFFFFu, s,  o);
            sq += __shfl_xor_sync(0xFFFFFFFFu, sq, o);
        }
        if (l == 0){ ss[w] = s; ssq[w] = sq; }
        __syncthreads();
        s = 0.f; sq = 0.f;
        #pragma unroll
        for (int k = 0; k < 8; k++){ s += ss[k]; sq += ssq[k]; }
        __syncthreads();

        float mean = s * (1.f/FF);
        float var  = sq * (1.f/FF) - mean*mean;
        float rstd = rsqrtf(var + 1e-5f);
        float nv = (v - mean) * rstd * ga + be;
        float yv = gelu_exact(nv);
        __nv_bfloat16 hi = __float2bfloat16_rn(yv);
        g_yhi[base + (long)t*FF + f] = hi;
        g_ylo[base + (long)t*FF + f] = __float2bfloat16_rn(yv - __bfloat162float(hi));
    }
}

// ---------------------------------------------------------------------------
// Kernel 3 (per layer): y2 = pw_w @ y + pw_b via ldmatrix+mma (bf16 3-term),
// fused channel_norm + GELU + residual into g_h. Last layer also emits
// bf16 hi/lo of h*mask for the proj GEMM.
// CTA 512 thr / 16 warps (8m x 2n); tile M=256 x N=128 t; K=256 in 4x64.
// ---------------------------------------------------------------------------
__global__ __launch_bounds__(512) void k_pw_mma(int lay,
                                                const float* __restrict__ pw_b,
                                                const float* __restrict__ gamma,
                                                const float* __restrict__ beta,
                                                const float* __restrict__ mask,
                                                int last){
    extern __shared__ char smem[];
    uint32_t sb = smem_u32(smem);
    int tid = threadIdx.x, lane = tid & 31, wid = tid >> 5;
    int t0 = blockIdx.x * 128;
    int b = blockIdx.y;
    int wm = wid & 7, wn = wid >> 3;

    float acc[2][8][4];
    #pragma unroll
    for (int mt = 0; mt < 2; mt++)
        #pragma unroll
        for (int nt = 0; nt < 8; nt++)
            #pragma unroll
            for (int q = 0; q < 4; q++) acc[mt][nt][q] = 0.f;

    uint32_t aoff = (uint32_t)((wm*32 + (lane & 15)) * PASTR + ((lane >> 4) * 8) * 2);
    uint32_t aH0 = sb + PW_OFF_AHI + aoff, aH1 = aH0 + 16*PASTR;
    uint32_t aL0 = sb + PW_OFF_ALO + aoff, aL1 = aL0 + 16*PASTR;
    uint32_t boffc = (uint32_t)((((lane >> 4) * 8) + (lane & 7)) * PASTR
                                + ((lane >> 3) & 1) * 16);
    uint32_t bHp[2], bLp[2];
    #pragma unroll
    for (int hf = 0; hf < 2; hf++){
        uint32_t rowo = (uint32_t)((wn*64 + hf*32) * PASTR);
        bHp[hf] = sb + PW_OFF_BHI + rowo + boffc;
        bLp[hf] = sb + PW_OFF_BLO + rowo + boffc;
    }

    for (int c0 = 0; c0 < 4; c0++){
        if (c0) __syncthreads();
        for (int i = tid; i < FF*8; i += 512){
            int r = i >> 3, g = i & 7;
            uint32_t off = (uint32_t)(r*PASTR + g*16);
            size_t s4 = ((size_t)(lay*FF + r))*32 + (size_t)c0*8 + g;
            cp16(sb + PW_OFF_AHI + off, ((const uint4*)g_pwhi) + s4);
            cp16(sb + PW_OFF_ALO + off, ((const uint4*)g_pwlo) + s4);
        }
        for (int i = tid; i < 128*8; i += 512){
            int r = i >> 3, g = i & 7;
            uint32_t off = (uint32_t)(r*PASTR + g*16);
            size_t s4 = ((size_t)b*TLEN + t0 + r)*32 + (size_t)c0*8 + g;
            cp16(sb + PW_OFF_BHI + off, ((const uint4*)g_yhi) + s4);
            cp16(sb + PW_OFF_BLO + off, ((const uint4*)g_ylo) + s4);
        }
        cp_wait_all();
        __syncthreads();

        #pragma unroll
        for (int k16 = 0; k16 < 4; k16++){
            uint32_t ko = (uint32_t)(k16 * 32);
            uint32_t Ah[2][4], Al[2][4];
            ldm4(Ah[0], aH0 + ko); ldm4(Ah[1], aH1 + ko);
            ldm4(Al[0], aL0 + ko); ldm4(Al[1], aL1 + ko);
            #pragma unroll
            for (int hf = 0; hf < 2; hf++){
                uint32_t Bh[2][4], Bl[2][4];
                ldm4(Bh[0], bHp[hf] + ko); ldm4(Bh[1], bHp[hf] + 16*PASTR + ko);
                ldm4(Bl[0], bLp[hf] + ko); ldm4(Bl[1], bLp[hf] + 16*PASTR + ko);
                #pragma unroll
                for (int mt = 0; mt < 2; mt++){
                    #pragma unroll
                    for (int nt = 0; nt < 4; nt++){
                        uint32_t h0 = Bh[nt>>1][(nt&1)*2], h1 = Bh[nt>>1][(nt&1)*2+1];
                        uint32_t l0 = Bl[nt>>1][(nt&1)*2], l1 = Bl[nt>>1][(nt&1)*2+1];
                        mma_bf16(acc[mt][hf*4+nt], Ah[mt], h0, h1);
                        mma_bf16(acc[mt][hf*4+nt], Ah[mt], l0, l1);
                        mma_bf16(acc[mt][hf*4+nt], Al[mt], h0, h1);
                    }
                }
            }
        }
    }

    // epilogue in two 64-t passes over the aliased smem buffer
    float* us = (float*)smem;
    float* smean = (float*)(smem + PW_OFF_STAT);
    float* srstd = smean + 64;

    for (int p = 0; p < 2; p++){
        __syncthreads();
        if (wn == p){
            #pragma unroll
            for (int mt = 0; mt < 2; mt++){
                #pragma unroll
                for (int nt = 0; nt < 8; nt++){
                    int tl = nt*8 + (lane & 3)*2;
                    int m = wm*32 + mt*16 + (lane >> 2);
                    #pragma unroll
                    for (int hh = 0; hh < 2; hh++){
                        int o = m + hh*8;
                        float pb = pw_b[o];
                        us[tl*PW_USTR + o]     = acc[mt][nt][2*hh+0] + pb;
                        us[(tl+1)*PW_USTR + o] = acc[mt][nt][2*hh+1] + pb;
                    }
                }
            }
        }
        __syncthreads();

        #pragma unroll
        for (int it = 0; it < 4; it++){
            int t = wid*4 + it;
            float s = 0.f, sq = 0.f;
            #pragma unroll
            for (int k = 0; k < 8; k++){
                float v = us[t*PW_USTR + lane + k*32];
                s += v; sq += v*v;
            }
            #pragma unroll
            for (int off = 16; off; off >>= 1){
                s  += __shfl_xor_sync(0xFFFFFFFFu, s,  off);
                sq += __shfl_xor_sync(0xFFFFFFFFu, sq, off);
            }
            if (lane == 0){
                float mean = s * (1.f/FF);
                smean[t] = mean;
                srstd[t] = rsqrtf(sq * (1.f/FF) - mean*mean + 1e-5f);
            }
        }
        __syncthreads();

        long gbase = ((long)b*TLEN + t0 + p*64) * FF;
        for (int i = tid; i < 64*64; i += 512){
            int t = i >> 6, o4 = i & 63;
            float4 u = *(float4*)&us[t*PW_USTR + o4*4];
            float mean = smean[t], rstd = srstd[t];
            const float4 ga = *(const float4*)&gamma[o4*4];
            const float4 be = *(const float4*)&beta[o4*4];
            long idx = gbase + (long)t*FF + o4*4;
            float4 hv = *(float4*)&g_h[idx];
            hv.x += gelu_exact((u.x - mean)*rstd*ga.x + be.x);
            hv.y += gelu_exact((u.y - mean)*rstd*ga.y + be.y);
            hv.z += gelu_exact((u.z - mean)*rstd*ga.z + be.z);
            hv.w += gelu_exact((u.w - mean)*rstd*ga.w + be.w);
            *(float4*)&g_h[idx] = hv;
            if (last){
                float mv = mask[(long)b*TLEN + t0 + p*64 + t];
                float v0 = hv.x*mv, v1 = hv.y*mv, v2 = hv.z*mv, v3 = hv.w*mv;
                __nv_bfloat16 h0 = __float2bfloat16_rn(v0);
                __nv_bfloat16 h1 = __float2bfloat16_rn(v1);
                __nv_bfloat16 h2 = __float2bfloat16_rn(v2);
                __nv_bfloat16 h3 = __float2bfloat16_rn(v3);
                __nv_bfloat162 p0; p0.x = h0; p0.y = h1;
                __nv_bfloat162 p1; p1.x = h2; p1.y = h3;
                *(__nv_bfloat162*)&g_hhi[idx]   = p0;
                *(__nv_bfloat162*)&g_hhi[idx+2] = p1;
                __nv_bfloat162 q0, q1;
                q0.x = __float2bfloat16_rn(v0 - __bfloat162float(h0));
                q0.y = __float2bfloat16_rn(v1 - __bfloat162float(h1));
                q1.x = __float2bfloat16_rn(v2 - __bfloat162float(h2));
                q1.y = __float2bfloat16_rn(v3 - __bfloat162float(h3));
                *(__nv_bfloat162*)&g_hlo[idx]   = q0;
                *(__nv_bfloat162*)&g_hlo[idx+2] = q1;
            }
        }
    }
}

// ---------------------------------------------------------------------------
// Kernel 4: 2-term bf16 GEMM (u = W @ h^T) via ldmatrix + mma.sync, fused
// with the RQ spline. CTA 256 thr / 8 warps (4m x 2n, n=64/warp).
// Tile M=128 x N=128 t, K=256 in 2 chunks.
// ---------------------------------------------------------------------------
__global__ __launch_bounds__(256, 2) void k_proj_mma(const float* __restrict__ x,
                                                     const float* __restrict__ mask,
                                                     const float* __restrict__ proj_b,
                                                     float* __restrict__ out){
    extern __shared__ char smem[];
    uint32_t sb = smem_u32(smem);
    int tid = threadIdx.x, lane = tid & 31, wid = tid >> 5;
    int t0 = blockIdx.x * NT;
    int mtile = blockIdx.y;
    int b = blockIdx.z;
    int m0 = mtile * MT;
    int ch0 = mtile * 4;

    float* smask = (float*)(smem + OFF_MASK);
    if (tid < NT) smask[tid] = mask[(long)b*TLEN + t0 + tid];

    float acc[2][8][4];
    #pragma unroll
    for (int mt = 0; mt < 2; mt++)
        #pragma unroll
        for (int nt = 0; nt < 8; nt++)
            #pragma unroll
            for (int q = 0; q < 4; q++) acc[mt][nt][q] = 0.f;

    int wm = wid & 3, wn = wid >> 2;
    uint32_t aoff = (uint32_t)((wm*32 + (lane & 15)) * ASTR + ((lane >> 4) * 8) * 2);
    uint32_t aH0 = sb + OFF_A + aoff, aH1 = aH0 + 16*ASTR;
    uint32_t boffc = (uint32_t)((((lane >> 4) * 8) + (lane & 7)) * BSTR
                                + ((lane >> 3) & 1) * 16);
    uint32_t bHp[2], bLp[2];
    #pragma unroll
    for (int hf = 0; hf < 2; hf++){
        uint32_t rowo = (uint32_t)((wn*64 + hf*32) * BSTR);
        bHp[hf] = sb + OFF_BHI + rowo + boffc;
        bLp[hf] = sb + OFF_BLO + rowo + boffc;
    }

    for (int c = 0; c < 2; c++){
        if (c) __syncthreads();
        for (int i = tid; i < MT*16; i += 256){
            int r = i >> 4, g = i & 15;
            uint32_t off = (uint32_t)(r*ASTR + g*16);
            size_t s4 = ((size_t)(m0 + r))*32 + (size_t)c*16 + g;
            cp16(sb + OFF_A + off, ((const uint4*)g_whi) + s4);
        }
        for (int i = tid; i < NT*16; i += 256){
            int r = i >> 4, g = i & 15;
            uint32_t off = (uint32_t)(r*BSTR + g*16);
            size_t s4 = ((size_t)b*TLEN + t0 + r)*32 + (size_t)c*16 + g;
            cp16(sb + OFF_BHI + off, ((const uint4*)g_hhi) + s4);
            cp16(sb + OFF_BLO + off, ((const uint4*)g_hlo) + s4);
        }
        cp_wait_all();
        __syncthreads();

        #pragma unroll
        for (int k16 = 0; k16 < 8; k16++){
            uint32_t ko = (uint32_t)(k16 * 32);
            uint32_t Ah[2][4];
            ldm4(Ah[0], aH0 + ko); ldm4(Ah[1], aH1 + ko);
            #pragma unroll
            for (int hf = 0; hf < 2; hf++){
                uint32_t Bh[2][4], Bl[2][4];
                ldm4(Bh[0], bHp[hf] + ko); ldm4(Bh[1], bHp[hf] + 16*BSTR + ko);
                ldm4(Bl[0], bLp[hf] + ko); ldm4(Bl[1], bLp[hf] + 16*BSTR + ko);
                #pragma unroll
                for (int mt = 0; mt < 2; mt++){
                    #pragma unroll
                    for (int nt = 0; nt < 4; nt++){
                        uint32_t h0 = Bh[nt>>1][(nt&1)*2], h1 = Bh[nt>>1][(nt&1)*2+1];
                        uint32_t l0 = Bl[nt>>1][(nt&1)*2], l1 = Bl[nt>>1][(nt&1)*2+1];
                        mma_bf16(acc[mt][hf*4+nt], Ah[mt], h0, h1);
                        mma_bf16(acc[mt][hf*4+nt], Ah[mt], l0, l1);
                    }
                }
            }
        }
    }
    __syncthreads();

    // u -> smem (alias over A/B regions): us[row][t], stride 129 floats
    float* us = (float*)smem;
    #pragma unroll
    for (int mt = 0; mt < 2; mt++){
        #pragma unroll
        for (int g = 0; g < 8; g++){
            int r = wm*32 + mt*16 + (lane >> 2);
            int t = wn*64 + g*8 + (lane & 3)*2;
            #pragma unroll
            for (int hh = 0; hh < 2; hh++){
                int rr = r + hh*8;
                int j = rr & 31;
                int ch = ch0 + (rr >> 5);
                float pb = (j < NJ) ? proj_b[ch*NJ + j] : 0.f;
                us[rr*USTRIDE + t]     = (acc[mt][g][2*hh+0] + pb) * smask[t];
                us[rr*USTRIDE + t + 1] = (acc[mt][g][2*hh+1] + pb) * smask[t+1];
            }
        }
    }
    __syncthreads();

    // --- spline: 4 ch x 128 t = 512 evals, 2 per thread ---
    const float SCALE = 0.0625f;
    int chl = tid >> 6;
    int ch = ch0 + chl;
    float ldsum = 0.f;

    #pragma unroll
    for (int it = 0; it < 2; it++){
        int tl = (tid & 63) + it*64;
        const float* ub = us + (chl*32)*USTRIDE + tl;   // ub[j*USTRIDE]
        float x1v = x[(long)b*CC*TLEN + (long)(HALF + ch)*TLEN + t0 + tl];
        float mv  = smask[tl];

        float uw[10];
        #pragma unroll
        for (int j = 0; j < 10; j++) uw[j] = ub[j*USTRIDE] * SCALE;
        float mx = uw[0];
        #pragma unroll
        for (int j = 1; j < 10; j++) mx = fmaxf(mx, uw[j]);
        float ew[10]; float sw = 0.f;
        #pragma unroll
        for (int j = 0; j < 10; j++){ ew[j] = expf(uw[j] - mx); sw += ew[j]; }
        float cw[11]; cw[0] = -5.f;
        {
            float inv = 1.f / sw, cs = 0.f;
            #pragma unroll
            for (int j = 0; j < 9; j++){
                cs += fmaf(0.99f, ew[j]*inv, 0.001f);
                cw[j+1] = fmaf(10.f, cs, -5.f);
            }
            cw[10] = 5.f;
        }
        #pragma unroll
        for (int j = 0; j < 10; j++) uw[j] = ub[(10+j)*USTRIDE] * SCALE;
        mx = uw[0];
        #pragma unroll
        for (int j = 1; j < 10; j++) mx = fmaxf(mx, uw[j]);
        sw = 0.f;
        #pragma unroll
        for (int j = 0; j < 10; j++){ ew[j] = expf(uw[j] - mx); sw += ew[j]; }
        float chh[11]; chh[0] = -5.f;
        {
            float inv = 1.f / sw, cs = 0.f;
            #pragma unroll
            for (int j = 0; j < 9; j++){
                cs += fmaf(0.99f, ew[j]*inv, 0.001f);
                chh[j+1] = fmaf(10.f, cs, -5.f);
            }
            chh[10] = 5.f;
        }

        float xc = fminf(fmaxf(x1v, -5.f), 5.f);
        int idx = 0;
        #pragma unroll
        for (int j = 1; j <= 9; j++) idx += (xc >= cw[j]) ? 1 : 0;

        float cwl = cw[0], cwr = cw[1], chl2 = chh[0], chr = chh[1];
        #pragma unroll
        for (int j = 1; j < 10; j++){
            if (idx == j){ cwl = cw[j]; cwr = cw[j+1]; chl2 = chh[j]; chr = chh[j+1]; }
        }
        float d0 = (idx == 0) ? 1.f : 0.001f + softplusf(ub[(19 + idx)*USTRIDE]);
        float d1 = (idx == 9) ? 1.f : 0.001f + softplusf(ub[(20 + idx)*USTRIDE]);

        float wb = cwr - cwl, hb = chr - chl2;
        float delta = hb / wb;
        float th = (xc - cwl) / wb;
        float omt = 1.f - th;
        float t1m = th * omt;
        float denom = delta + (d0 + d1 - 2.f*delta) * t1m;
        float num = hb * (delta*th*th + d0*t1m);
        float yv = chl2 + num / denom;
        float dnum = delta*delta * (d1*th*th + 2.f*delta*t1m + d0*omt*omt);
        float lad = logf(dnum) - 2.f*logf(denom);

        bool inside = (x1v >= -5.f) && (x1v <= 5.f);
        float ov = inside ? yv : x1v;
        ldsum += (inside ? lad : 0.f) * mv;

        out[(long)b*CC*TLEN + (long)(HALF + ch)*TLEN + t0 + tl] = ov * mv;
    }

    // logdet reduction
    #pragma unroll
    for (int off = 16; off; off >>= 1)
        ldsum += __shfl_xor_sync(0xFFFFFFFFu, ldsum, off);
    float* sred = (float*)(smem + OFF_RED);
    if (lane == 0) sred[wid] = ldsum;
    __syncthreads();
    if (tid == 0){
        float s = 0.f;
        #pragma unroll
        for (int k = 0; k < 8; k++) s += sred[k];
        atomicAdd(&out[(long)BB*CC*TLEN + b], s);
    }
}

// ---------------------------------------------------------------------------
extern "C" void kernel_launch(void* const* d_in, const int* in_sizes, int n_in,
                              void* d_out, int out_size){
    const float* x      = (const float*)d_in[0];
    const float* mask   = (const float*)d_in[1];
    const float* pre_w  = (const float*)d_in[2];
    const float* pre_b  = (const float*)d_in[3];
    const float* dw_w   = (const float*)d_in[4];
    const float* dw_b   = (const float*)d_in[5];
    const float* pw_w   = (const float*)d_in[6];
    const float* pw_b   = (const float*)d_in[7];
    const float* gamma1 = (const float*)d_in[8];
    const float* beta1  = (const float*)d_in[9];
    const float* gamma2 = (const float*)d_in[10];
    const float* beta2  = (const float*)d_in[11];
    const float* proj_w = (const float*)d_in[12];
    const float* proj_b = (const float*)d_in[13];
    float* out = (float*)d_out;

    cudaFuncSetAttribute(k_proj_mma, cudaFuncAttributeMaxDynamicSharedMemorySize,
                         PROJ_SMEM_BYTES);
    cudaFuncSetAttribute(k_pw_mma, cudaFuncAttributeMaxDynamicSharedMemorySize,
                         PW_SMEM_BYTES);
    cudaFuncSetAttribute(k_pre_mma, cudaFuncAttributeMaxDynamicSharedMemorySize,
                         PRE_SMEM_BYTES);

    k_prep_w<<<768, 256>>>(proj_w);
    k_prep_pw<<<192, 256>>>(pw_w);
    k_prep_pre<<<96, 256>>>(pre_w);
    k_init<<<4096, 256>>>(x, mask, out);
    k_pre_mma<<<dim3(TLEN/128, BB), 512, PRE_SMEM_BYTES>>>(x, pre_b);

    int dil = 1;
    for (int i = 0; i < 3; i++){
        k_convnorm<<<dim3(TLEN/4, BB), 256>>>(mask,
                                            dw_w + (long)i*FF*3, dw_b + (long)i*FF,
                                            gamma1 + (long)i*FF, beta1 + (long)i*FF, dil);
        k_pw_mma<<<dim3(TLEN/128, BB), 512, PW_SMEM_BYTES>>>(i,
                                            pw_b + (long)i*FF,
                                            gamma2 + (long)i*FF, beta2 + (long)i*FF,
                                            mask, (i == 2) ? 1 : 0);
        dil *= 3;
    }

    k_proj_mma<<<dim3(TLEN/NT, MROWS/MT, BB), 256, PROJ_SMEM_BYTES>>>(x, mask, proj_b, out);
}

// round 13
// speedup vs baseline: 4.3533x; 1.1713x over previous
#include <cuda_runtime.h>
#include <cuda_bf16.h>
#include <math.h>
#include <cstdint>

#define BB 16
#define CC 192
#define HALF 96
#define TLEN 2048
#define FF 256
#define NB 10
#define NJ 29        // 3*NB - 1

// ---- proj mma tiling (1-term: W bf16-rounded x h bf16-rounded) ----
#define MROWS 3072   // 96 ch * 32 padded rows
#define MT 128       // m-tile (4 channels)
#define NT 128       // t-tile
#define ASTR 272     // smem row stride bytes (128 bf16 + 16B pad)
#define BSTR 272
#define USTRIDE 129  // u smem row stride (floats), odd -> conflict-free

#define OFF_A    0            // 128*272 = 34816
#define OFF_BHI  34816        // 128*272
#define OFF_MASK 69632        // 128 floats
#define OFF_RED  70144        // 8 floats
#define PROJ_SMEM_BYTES 70272

// ---- pw mma tiling (M=256 full channels, N=128 t, K staged in 4x64) ----
#define PASTR 144              // 64 bf16 + 16B pad
#define PW_OFF_AHI 0
#define PW_OFF_ALO 36864
#define PW_OFF_BHI 73728
#define PW_OFF_BLO 92160
#define PW_SMEM_BYTES 110592
#define PW_USTR 260            // epilogue f32 row stride (words), 64 t per pass
#define PW_OFF_STAT 66560      // bytes; smean[64] | srstd[64]

// ---- pre mma tiling (M=256 f, N=128 t, K=96 whole) ----
#define PRE_STR 208            // 96 bf16 = 192B + 16B pad
#define PRE_OFF_AHI 0          // 256*208 = 53248
#define PRE_OFF_ALO 53248
#define PRE_OFF_BHI 106496     // 128*208 = 26624
#define PRE_OFF_BLO 133120
#define PRE_SMEM_BYTES 159744

// Scratch (allocation-free rule: __device__ globals). Layout: [b][t][f].
__device__ float g_h[(size_t)BB*TLEN*FF];
__device__ __nv_bfloat16 g_whi[(size_t)MROWS*FF];
__device__ __nv_bfloat16 g_hhi[(size_t)BB*TLEN*FF];
__device__ __nv_bfloat16 g_yhi[(size_t)BB*TLEN*FF];
__device__ __nv_bfloat16 g_ylo[(size_t)BB*TLEN*FF];
__device__ __nv_bfloat16 g_pwhi[(size_t)3*FF*FF];
__device__ __nv_bfloat16 g_pwlo[(size_t)3*FF*FF];
__device__ __nv_bfloat16 g_prehi[(size_t)FF*HALF];
__device__ __nv_bfloat16 g_prelo[(size_t)FF*HALF];

__device__ __forceinline__ float gelu_exact(float v){
    return 0.5f * v * (1.f + erff(v * 0.70710678118654752f));
}
__device__ __forceinline__ float softplus_fast(float v){
    return v > 20.f ? v : __logf(1.f + __expf(v));
}
__device__ __forceinline__ uint32_t smem_u32(const void* p){
    uint32_t a;
    asm("{ .reg .u64 t; cvta.to.shared.u64 t, %1; cvt.u32.u64 %0, t; }" : "=r"(a) : "l"(p));
    return a;
}
__device__ __forceinline__ void ldm4(uint32_t* r, uint32_t addr){
    asm volatile("ldmatrix.sync.aligned.m8n8.x4.shared.b16 {%0,%1,%2,%3}, [%4];"
        : "=r"(r[0]),"=r"(r[1]),"=r"(r[2]),"=r"(r[3]) : "r"(addr));
}
__device__ __forceinline__ void mma_bf16(float* d, const uint32_t* a, uint32_t b0, uint32_t b1){
    asm volatile("mma.sync.aligned.m16n8k16.row.col.f32.bf16.bf16.f32 "
        "{%0,%1,%2,%3}, {%4,%5,%6,%7}, {%8,%9}, {%0,%1,%2,%3};"
        : "+f"(d[0]),"+f"(d[1]),"+f"(d[2]),"+f"(d[3])
        : "r"(a[0]),"r"(a[1]),"r"(a[2]),"r"(a[3]), "r"(b0),"r"(b1));
}
__device__ __forceinline__ void cp16(uint32_t saddr, const void* gptr){
    asm volatile("cp.async.cg.shared.global [%0], [%1], 16;"
        :: "r"(saddr), "l"(gptr));
}
__device__ __forceinline__ void cp_wait_all(){
    asm volatile("cp.async.commit_group;");
    asm volatile("cp.async.wait_all;" ::: "memory");
}

// ---------------------------------------------------------------------------
// Prep kernels (one-time weight conversion)
// ---------------------------------------------------------------------------
__global__ void k_prep_w(const float* __restrict__ proj_w){
    long n = (long)MROWS*FF;
    for (long i = (long)blockIdx.x*blockDim.x + threadIdx.x; i < n;
         i += (long)gridDim.x*blockDim.x){
        int k = (int)(i & (FF-1));
        int r = (int)(i >> 8);
        int ch = r >> 5, j = r & 31;
        float w = (j < NJ) ? proj_w[((long)(ch*NJ + j))*FF + k] : 0.f;
        g_whi[i] = __float2bfloat16_rn(w);
    }
}
__global__ void k_prep_pw(const float* __restrict__ pw_w){
    long n = 3L*FF*FF;
    for (long i = (long)blockIdx.x*blockDim.x + threadIdx.x; i < n;
         i += (long)gridDim.x*blockDim.x){
        float w = pw_w[i];
        __nv_bfloat16 hi = __float2bfloat16_rn(w);
        g_pwhi[i] = hi;
        g_pwlo[i] = __float2bfloat16_rn(w - __bfloat162float(hi));
    }
}
__global__ void k_prep_pre(const float* __restrict__ pre_w){
    long n = (long)FF*HALF;
    for (long i = (long)blockIdx.x*blockDim.x + threadIdx.x; i < n;
         i += (long)gridDim.x*blockDim.x){
        float w = pre_w[i];
        __nv_bfloat16 hi = __float2bfloat16_rn(w);
        g_prehi[i] = hi;
        g_prelo[i] = __float2bfloat16_rn(w - __bfloat162float(hi));
    }
}

// ---------------------------------------------------------------------------
// Kernel 0: copy x0*mask into out[:, :96, :], zero logdet slots.
// ---------------------------------------------------------------------------
__global__ void k_init(const float* __restrict__ x, const float* __restrict__ mask,
                       float* __restrict__ out){
    long n = (long)BB * HALF * TLEN;
    for (long i = (long)blockIdx.x * blockDim.x + threadIdx.x; i < n;
         i += (long)gridDim.x * blockDim.x){
        int t = (int)(i % TLEN);
        long bc = i / TLEN;
        int c = (int)(bc % HALF);
        int b = (int)(bc / HALF);
        long src = (long)b*CC*TLEN + (long)c*TLEN + t;
        out[src] = x[src] * mask[(long)b*TLEN + t];
    }
    if (blockIdx.x == 0 && threadIdx.x < BB)
        out[(long)BB*CC*TLEN + threadIdx.x] = 0.f;
}

// ---------------------------------------------------------------------------
// Kernel 1: h = pre_w @ x0 + pre_b via ldmatrix+mma (bf16 3-term).
// ---------------------------------------------------------------------------
__global__ __launch_bounds__(512) void k_pre_mma(const float* __restrict__ x,
                                                 const float* __restrict__ pre_b){
    extern __shared__ char smem[];
    uint32_t sb = smem_u32(smem);
    int tid = threadIdx.x, lane = tid & 31, wid = tid >> 5;
    int t0 = blockIdx.x * 128;
    int b = blockIdx.y;

    for (int i = tid; i < FF*12; i += 512){
        int r = i / 12, g = i - r*12;
        uint32_t off = (uint32_t)(r*PRE_STR + g*16);
        cp16(sb + PRE_OFF_AHI + off, ((const uint4*)g_prehi) + (size_t)r*12 + g);
        cp16(sb + PRE_OFF_ALO + off, ((const uint4*)g_prelo) + (size_t)r*12 + g);
    }
    for (int i = tid; i < HALF*128; i += 512){
        int c = i >> 7, tt = i & 127;
        float v = x[(long)b*CC*TLEN + (long)c*TLEN + t0 + tt];
        __nv_bfloat16 hi = __float2bfloat16_rn(v);
        uint32_t off = (uint32_t)(tt*PRE_STR + c*2);
        *(__nv_bfloat16*)(smem + PRE_OFF_BHI + off) = hi;
        *(__nv_bfloat16*)(smem + PRE_OFF_BLO + off) =
            __float2bfloat16_rn(v - __bfloat162float(hi));
    }
    cp_wait_all();
    __syncthreads();

    int wm = wid & 7, wn = wid >> 3;
    float acc[2][8][4];
    #pragma unroll
    for (int mt = 0; mt < 2; mt++)
        #pragma unroll
        for (int nt = 0; nt < 8; nt++)
            #pragma unroll
            for (int q = 0; q < 4; q++) acc[mt][nt][q] = 0.f;

    uint32_t aoff = (uint32_t)((wm*32 + (lane & 15)) * PRE_STR + ((lane >> 4) * 8) * 2);
    uint32_t aH0 = sb + PRE_OFF_AHI + aoff, aH1 = aH0 + 16*PRE_STR;
    uint32_t aL0 = sb + PRE_OFF_ALO + aoff, aL1 = aL0 + 16*PRE_STR;
    uint32_t boffc = (uint32_t)((((lane >> 4) * 8) + (lane & 7)) * PRE_STR
                                + ((lane >> 3) & 1) * 16);
    uint32_t bHp[2], bLp[2];
    #pragma unroll
    for (int hf = 0; hf < 2; hf++){
        uint32_t rowo = (uint32_t)((wn*64 + hf*32) * PRE_STR);
        bHp[hf] = sb + PRE_OFF_BHI + rowo + boffc;
        bLp[hf] = sb + PRE_OFF_BLO + rowo + boffc;
    }

    #pragma unroll
    for (int k16 = 0; k16 < 6; k16++){
        uint32_t ko = (uint32_t)(k16 * 32);
        uint32_t Ah[2][4], Al[2][4];
        ldm4(Ah[0], aH0 + ko); ldm4(Ah[1], aH1 + ko);
        ldm4(Al[0], aL0 + ko); ldm4(Al[1], aL1 + ko);
        #pragma unroll
        for (int hf = 0; hf < 2; hf++){
            uint32_t Bh[2][4], Bl[2][4];
            ldm4(Bh[0], bHp[hf] + ko); ldm4(Bh[1], bHp[hf] + 16*PRE_STR + ko);
            ldm4(Bl[0], bLp[hf] + ko); ldm4(Bl[1], bLp[hf] + 16*PRE_STR + ko);
            #pragma unroll
            for (int mt = 0; mt < 2; mt++){
                #pragma unroll
                for (int nt = 0; nt < 4; nt++){
                    uint32_t h0 = Bh[nt>>1][(nt&1)*2], h1 = Bh[nt>>1][(nt&1)*2+1];
                    uint32_t l0 = Bl[nt>>1][(nt&1)*2], l1 = Bl[nt>>1][(nt&1)*2+1];
                    mma_bf16(acc[mt][hf*4+nt], Ah[mt], h0, h1);
                    mma_bf16(acc[mt][hf*4+nt], Ah[mt], l0, l1);
                    mma_bf16(acc[mt][hf*4+nt], Al[mt], h0, h1);
                }
            }
        }
    }

    float* us = (float*)smem;
    for (int p = 0; p < 2; p++){
        __syncthreads();
        if (wn == p){
            #pragma unroll
            for (int mt = 0; mt < 2; mt++){
                #pragma unroll
                for (int nt = 0; nt < 8; nt++){
                    int tl = nt*8 + (lane & 3)*2;
                    int m = wm*32 + mt*16 + (lane >> 2);
                    #pragma unroll
                    for (int hh = 0; hh < 2; hh++){
                        int o = m + hh*8;
                        float pb = pre_b[o];
                        us[tl*PW_USTR + o]     = acc[mt][nt][2*hh+0] + pb;
                        us[(tl+1)*PW_USTR + o] = acc[mt][nt][2*hh+1] + pb;
                    }
                }
            }
        }
        __syncthreads();
        long gbase = ((long)b*TLEN + t0 + p*64) * FF;
        for (int i = tid; i < 64*64; i += 512){
            int t = i >> 6, o4 = i & 63;
            *(float4*)&g_h[gbase + (long)t*FF + o4*4] = *(float4*)&us[t*PW_USTR + o4*4];
        }
    }
}

// ---------------------------------------------------------------------------
// Kernel 2 (per layer): depthwise dilated conv + channel_norm + GELU,
// 4 t-columns per CTA. Writes bf16 hi/lo of y.
// ---------------------------------------------------------------------------
__global__ __launch_bounds__(256) void k_convnorm(const float* __restrict__ mask,
                                                  const float* __restrict__ dw_w,
                                                  const float* __restrict__ dw_b,
                                                  const float* __restrict__ gamma,
                                                  const float* __restrict__ beta,
                                                  int dil){
    int t0 = blockIdx.x * 4, b = blockIdx.y, f = threadIdx.x;
    long base = (long)b*TLEN*FF;
    const float* mrow = mask + (long)b*TLEN;
    __shared__ float ss[8], ssq[8];

    float w0 = dw_w[f*3+0], w1 = dw_w[f*3+1], w2 = dw_w[f*3+2];
    float bias = dw_b[f], ga = gamma[f], be = beta[f];
    int w = threadIdx.x >> 5, l = threadIdx.x & 31;

    #pragma unroll
    for (int tt = 0; tt < 4; tt++){
        int t = t0 + tt;
        float vl = 0.f, vr = 0.f;
        float vc = g_h[base + (long)t*FF + f] * mrow[t];
        if (t - dil >= 0)    vl = g_h[base + (long)(t-dil)*FF + f] * mrow[t - dil];
        if (t + dil < TLEN)  vr = g_h[base + (long)(t+dil)*FF + f] * mrow[t + dil];
        float v = fmaf(w0, vl, fmaf(w1, vc, fmaf(w2, vr, bias)));

        float s = v, sq = v*v;
        #pragma unroll
        for (int o = 16; o; o >>= 1){
            s  += __shfl_xor_sync(0xFFFFFFFFu, s,  o);
            sq += __shfl_xor_sync(0xFFFFFFFFu, sq, o);
        }
        if (l == 0){ ss[w] = s; ssq[w] = sq; }
        __syncthreads();
        s = 0.f; sq = 0.f;
        #pragma unroll
        for (int k = 0; k < 8; k++){ s += ss[k]; sq += ssq[k]; }
        __syncthreads();

        float mean = s * (1.f/FF);
        float var  = sq * (1.f/FF) - mean*mean;
        float rstd = rsqrtf(var + 1e-5f);
        float nv = (v - mean) * rstd * ga + be;
        float yv = gelu_exact(nv);
        __nv_bfloat16 hi = __float2bfloat16_rn(yv);
        g_yhi[base + (long)t*FF + f] = hi;
        g_ylo[base + (long)t*FF + f] = __float2bfloat16_rn(yv - __bfloat162float(hi));
    }
}

// ---------------------------------------------------------------------------
// Kernel 3 (per layer): y2 = pw_w @ y + pw_b via ldmatrix+mma (bf16 3-term),
// fused channel_norm + GELU + residual into g_h. Last layer also emits
// bf16 (rounded) h*mask for the 1-term proj GEMM.
// ---------------------------------------------------------------------------
__global__ __launch_bounds__(512) void k_pw_mma(int lay,
                                                const float* __restrict__ pw_b,
                                                const float* __restrict__ gamma,
                                                const float* __restrict__ beta,
                                                const float* __restrict__ mask,
                                                int last){
    extern __shared__ char smem[];
    uint32_t sb = smem_u32(smem);
    int tid = threadIdx.x, lane = tid & 31, wid = tid >> 5;
    int t0 = blockIdx.x * 128;
    int b = blockIdx.y;
    int wm = wid & 7, wn = wid >> 3;

    float acc[2][8][4];
    #pragma unroll
    for (int mt = 0; mt < 2; mt++)
        #pragma unroll
        for (int nt = 0; nt < 8; nt++)
            #pragma unroll
            for (int q = 0; q < 4; q++) acc[mt][nt][q] = 0.f;

    uint32_t aoff = (uint32_t)((wm*32 + (lane & 15)) * PASTR + ((lane >> 4) * 8) * 2);
    uint32_t aH0 = sb + PW_OFF_AHI + aoff, aH1 = aH0 + 16*PASTR;
    uint32_t aL0 = sb + PW_OFF_ALO + aoff, aL1 = aL0 + 16*PASTR;
    uint32_t boffc = (uint32_t)((((lane >> 4) * 8) + (lane & 7)) * PASTR
                                + ((lane >> 3) & 1) * 16);
    uint32_t bHp[2], bLp[2];
    #pragma unroll
    for (int hf = 0; hf < 2; hf++){
        uint32_t rowo = (uint32_t)((wn*64 + hf*32) * PASTR);
        bHp[hf] = sb + PW_OFF_BHI + rowo + boffc;
        bLp[hf] = sb + PW_OFF_BLO + rowo + boffc;
    }

    for (int c0 = 0; c0 < 4; c0++){
        if (c0) __syncthreads();
        for (int i = tid; i < FF*8; i += 512){
            int r = i >> 3, g = i & 7;
            uint32_t off = (uint32_t)(r*PASTR + g*16);
            size_t s4 = ((size_t)(lay*FF + r))*32 + (size_t)c0*8 + g;
            cp16(sb + PW_OFF_AHI + off, ((const uint4*)g_pwhi) + s4);
            cp16(sb + PW_OFF_ALO + off, ((const uint4*)g_pwlo) + s4);
        }
        for (int i = tid; i < 128*8; i += 512){
            int r = i >> 3, g = i & 7;
            uint32_t off = (uint32_t)(r*PASTR + g*16);
            size_t s4 = ((size_t)b*TLEN + t0 + r)*32 + (size_t)c0*8 + g;
            cp16(sb + PW_OFF_BHI + off, ((const uint4*)g_yhi) + s4);
            cp16(sb + PW_OFF_BLO + off, ((const uint4*)g_ylo) + s4);
        }
        cp_wait_all();
        __syncthreads();

        #pragma unroll
        for (int k16 = 0; k16 < 4; k16++){
            uint32_t ko = (uint32_t)(k16 * 32);
            uint32_t Ah[2][4], Al[2][4];
            ldm4(Ah[0], aH0 + ko); ldm4(Ah[1], aH1 + ko);
            ldm4(Al[0], aL0 + ko); ldm4(Al[1], aL1 + ko);
            #pragma unroll
            for (int hf = 0; hf < 2; hf++){
                uint32_t Bh[2][4], Bl[2][4];
                ldm4(Bh[0], bHp[hf] + ko); ldm4(Bh[1], bHp[hf] + 16*PASTR + ko);
                ldm4(Bl[0], bLp[hf] + ko); ldm4(Bl[1], bLp[hf] + 16*PASTR + ko);
                #pragma unroll
                for (int mt = 0; mt < 2; mt++){
                    #pragma unroll
                    for (int nt = 0; nt < 4; nt++){
                        uint32_t h0 = Bh[nt>>1][(nt&1)*2], h1 = Bh[nt>>1][(nt&1)*2+1];
                        uint32_t l0 = Bl[nt>>1][(nt&1)*2], l1 = Bl[nt>>1][(nt&1)*2+1];
                        mma_bf16(acc[mt][hf*4+nt], Ah[mt], h0, h1);
                        mma_bf16(acc[mt][hf*4+nt], Ah[mt], l0, l1);
                        mma_bf16(acc[mt][hf*4+nt], Al[mt], h0, h1);
                    }
                }
            }
        }
    }

    // epilogue in two 64-t passes over the aliased smem buffer
    float* us = (float*)smem;
    float* smean = (float*)(smem + PW_OFF_STAT);
    float* srstd = smean + 64;

    for (int p = 0; p < 2; p++){
        __syncthreads();
        if (wn == p){
            #pragma unroll
            for (int mt = 0; mt < 2; mt++){
                #pragma unroll
                for (int nt = 0; nt < 8; nt++){
                    int tl = nt*8 + (lane & 3)*2;
                    int m = wm*32 + mt*16 + (lane >> 2);
                    #pragma unroll
                    for (int hh = 0; hh < 2; hh++){
                        int o = m + hh*8;
                        float pb = pw_b[o];
                        us[tl*PW_USTR + o]     = acc[mt][nt][2*hh+0] + pb;
                        us[(tl+1)*PW_USTR + o] = acc[mt][nt][2*hh+1] + pb;
                    }
                }
            }
        }
        __syncthreads();

        #pragma unroll
        for (int it = 0; it < 4; it++){
            int t = wid*4 + it;
            float s = 0.f, sq = 0.f;
            #pragma unroll
            for (int k = 0; k < 8; k++){
                float v = us[t*PW_USTR + lane + k*32];
                s += v; sq += v*v;
            }
            #pragma unroll
            for (int off = 16; off; off >>= 1){
                s  += __shfl_xor_sync(0xFFFFFFFFu, s,  off);
                sq += __shfl_xor_sync(0xFFFFFFFFu, sq, off);
            }
            if (lane == 0){
                float mean = s * (1.f/FF);
                smean[t] = mean;
                srstd[t] = rsqrtf(sq * (1.f/FF) - mean*mean + 1e-5f);
            }
        }
        __syncthreads();

        long gbase = ((long)b*TLEN + t0 + p*64) * FF;
        for (int i = tid; i < 64*64; i += 512){
            int t = i >> 6, o4 = i & 63;
            float4 u = *(float4*)&us[t*PW_USTR + o4*4];
            float mean = smean[t], rstd = srstd[t];
            const float4 ga = *(const float4*)&gamma[o4*4];
            const float4 be = *(const float4*)&beta[o4*4];
            long idx = gbase + (long)t*FF + o4*4;
            float4 hv = *(float4*)&g_h[idx];
            hv.x += gelu_exact((u.x - mean)*rstd*ga.x + be.x);
            hv.y += gelu_exact((u.y - mean)*rstd*ga.y + be.y);
            hv.z += gelu_exact((u.z - mean)*rstd*ga.z + be.z);
            hv.w += gelu_exact((u.w - mean)*rstd*ga.w + be.w);
            *(float4*)&g_h[idx] = hv;
            if (last){
                float mv = mask[(long)b*TLEN + t0 + p*64 + t];
                __nv_bfloat162 p0, p1;
                p0.x = __float2bfloat16_rn(hv.x*mv);
                p0.y = __float2bfloat16_rn(hv.y*mv);
                p1.x = __float2bfloat16_rn(hv.z*mv);
                p1.y = __float2bfloat16_rn(hv.w*mv);
                *(__nv_bfloat162*)&g_hhi[idx]   = p0;
                *(__nv_bfloat162*)&g_hhi[idx+2] = p1;
            }
        }
    }
}

// ---------------------------------------------------------------------------
// Kernel 4: 1-term bf16 GEMM (u = W @ h^T) via ldmatrix + mma.sync, fused
// with the RQ spline. CTA 256 thr / 8 warps (4m x 2n, n=64/warp).
// Tile M=128 x N=128 t, K=256 in 2 chunks. launch_bounds(256,2): full reg
// budget, no spills (regfile caps occupancy at 2 CTAs anyway).
// ---------------------------------------------------------------------------
__global__ __launch_bounds__(256, 2) void k_proj_mma(const float* __restrict__ x,
                                                     const float* __restrict__ mask,
                                                     const float* __restrict__ proj_b,
                                                     float* __restrict__ out){
    extern __shared__ char smem[];
    uint32_t sb = smem_u32(smem);
    int tid = threadIdx.x, lane = tid & 31, wid = tid >> 5;
    int t0 = blockIdx.x * NT;
    int mtile = blockIdx.y;
    int b = blockIdx.z;
    int m0 = mtile * MT;
    int ch0 = mtile * 4;

    float* smask = (float*)(smem + OFF_MASK);
    if (tid < NT) smask[tid] = mask[(long)b*TLEN + t0 + tid];

    float acc[2][8][4];
    #pragma unroll
    for (int mt = 0; mt < 2; mt++)
        #pragma unroll
        for (int nt = 0; nt < 8; nt++)
            #pragma unroll
            for (int q = 0; q < 4; q++) acc[mt][nt][q] = 0.f;

    int wm = wid & 3, wn = wid >> 2;
    uint32_t aoff = (uint32_t)((wm*32 + (lane & 15)) * ASTR + ((lane >> 4) * 8) * 2);
    uint32_t aH0 = sb + OFF_A + aoff, aH1 = aH0 + 16*ASTR;
    uint32_t boffc = (uint32_t)((((lane >> 4) * 8) + (lane & 7)) * BSTR
                                + ((lane >> 3) & 1) * 16);
    uint32_t bHp[2];
    #pragma unroll
    for (int hf = 0; hf < 2; hf++){
        uint32_t rowo = (uint32_t)((wn*64 + hf*32) * BSTR);
        bHp[hf] = sb + OFF_BHI + rowo + boffc;
    }

    for (int c = 0; c < 2; c++){
        if (c) __syncthreads();
        for (int i = tid; i < MT*16; i += 256){
            int r = i >> 4, g = i & 15;
            uint32_t off = (uint32_t)(r*ASTR + g*16);
            size_t s4 = ((size_t)(m0 + r))*32 + (size_t)c*16 + g;
            cp16(sb + OFF_A + off, ((const uint4*)g_whi) + s4);
        }
        for (int i = tid; i < NT*16; i += 256){
            int r = i >> 4, g = i & 15;
            uint32_t off = (uint32_t)(r*BSTR + g*16);
            size_t s4 = ((size_t)b*TLEN + t0 + r)*32 + (size_t)c*16 + g;
            cp16(sb + OFF_BHI + off, ((const uint4*)g_hhi) + s4);
        }
        cp_wait_all();
        __syncthreads();

        #pragma unroll
        for (int k16 = 0; k16 < 8; k16++){
            uint32_t ko = (uint32_t)(k16 * 32);
            uint32_t Ah[2][4];
            ldm4(Ah[0], aH0 + ko); ldm4(Ah[1], aH1 + ko);
            #pragma unroll
            for (int hf = 0; hf < 2; hf++){
                uint32_t Bh[2][4];
                ldm4(Bh[0], bHp[hf] + ko); ldm4(Bh[1], bHp[hf] + 16*BSTR + ko);
                #pragma unroll
                for (int mt = 0; mt < 2; mt++){
                    #pragma unroll
                    for (int nt = 0; nt < 4; nt++){
                        uint32_t h0 = Bh[nt>>1][(nt&1)*2], h1 = Bh[nt>>1][(nt&1)*2+1];
                        mma_bf16(acc[mt][hf*4+nt], Ah[mt], h0, h1);
                    }
                }
            }
        }
    }
    __syncthreads();

    // u -> smem (alias over A/B regions): us[row][t], stride 129 floats
    float* us = (float*)smem;
    #pragma unroll
    for (int mt = 0; mt < 2; mt++){
        #pragma unroll
        for (int g = 0; g < 8; g++){
            int r = wm*32 + mt*16 + (lane >> 2);
            int t = wn*64 + g*8 + (lane & 3)*2;
            #pragma unroll
            for (int hh = 0; hh < 2; hh++){
                int rr = r + hh*8;
                int j = rr & 31;
                int ch = ch0 + (rr >> 5);
                float pb = (j < NJ) ? proj_b[ch*NJ + j] : 0.f;
                us[rr*USTRIDE + t]     = (acc[mt][g][2*hh+0] + pb) * smask[t];
                us[rr*USTRIDE + t + 1] = (acc[mt][g][2*hh+1] + pb) * smask[t+1];
            }
        }
    }
    __syncthreads();

    // --- spline: 4 ch x 128 t = 512 evals, 2 per thread ---
    const float SCALE = 0.0625f;
    int chl = tid >> 6;
    int ch = ch0 + chl;
    float ldsum = 0.f;

    #pragma unroll
    for (int it = 0; it < 2; it++){
        int tl = (tid & 63) + it*64;
        const float* ub = us + (chl*32)*USTRIDE + tl;   // ub[j*USTRIDE]
        float x1v = x[(long)b*CC*TLEN + (long)(HALF + ch)*TLEN + t0 + tl];
        float mv  = smask[tl];

        float uw[10];
        #pragma unroll
        for (int j = 0; j < 10; j++) uw[j] = ub[j*USTRIDE] * SCALE;
        float mx = uw[0];
        #pragma unroll
        for (int j = 1; j < 10; j++) mx = fmaxf(mx, uw[j]);
        float ew[10]; float sw = 0.f;
        #pragma unroll
        for (int j = 0; j < 10; j++){ ew[j] = __expf(uw[j] - mx); sw += ew[j]; }
        float cw[11]; cw[0] = -5.f;
        {
            float inv = __frcp_rn(sw), cs = 0.f;
            #pragma unroll
            for (int j = 0; j < 9; j++){
                cs += fmaf(0.99f, ew[j]*inv, 0.001f);
                cw[j+1] = fmaf(10.f, cs, -5.f);
            }
            cw[10] = 5.f;
        }
        #pragma unroll
        for (int j = 0; j < 10; j++) uw[j] = ub[(10+j)*USTRIDE] * SCALE;
        mx = uw[0];
        #pragma unroll
        for (int j = 1; j < 10; j++) mx = fmaxf(mx, uw[j]);
        sw = 0.f;
        #pragma unroll
        for (int j = 0; j < 10; j++){ ew[j] = __expf(uw[j] - mx); sw += ew[j]; }
        float chh[11]; chh[0] = -5.f;
        {
            float inv = __frcp_rn(sw), cs = 0.f;
            #pragma unroll
            for (int j = 0; j < 9; j++){
                cs += fmaf(0.99f, ew[j]*inv, 0.001f);
                chh[j+1] = fmaf(10.f, cs, -5.f);
            }
            chh[10] = 5.f;
        }

        float xc = fminf(fmaxf(x1v, -5.f), 5.f);
        int idx = 0;
        #pragma unroll
        for (int j = 1; j <= 9; j++) idx += (xc >= cw[j]) ? 1 : 0;

        float cwl = cw[0], cwr = cw[1], chl2 = chh[0], chr = chh[1];
        #pragma unroll
        for (int j = 1; j < 10; j++){
            if (idx == j){ cwl = cw[j]; cwr = cw[j+1]; chl2 = chh[j]; chr = chh[j+1]; }
        }
        float d0 = (idx == 0) ? 1.f : 0.001f + softplus_fast(ub[(19 + idx)*USTRIDE]);
        float d1 = (idx == 9) ? 1.f : 0.001f + softplus_fast(ub[(20 + idx)*USTRIDE]);

        float wb = cwr - cwl, hb = chr - chl2;
        float inv_wb = __frcp_rn(wb);
        float delta = hb * inv_wb;
        float th = (xc - cwl) * inv_wb;
        float omt = 1.f - th;
        float t1m = th * omt;
        float denom = delta + (d0 + d1 - 2.f*delta) * t1m;
        float num = hb * (delta*th*th + d0*t1m);
        float yv = chl2 + num / denom;
        float dnum = delta*delta * (d1*th*th + 2.f*delta*t1m + d0*omt*omt);
        float lad = __logf(dnum) - 2.f*__logf(denom);

        bool inside = (x1v >= -5.f) && (x1v <= 5.f);
        float ov = inside ? yv : x1v;
        ldsum += (inside ? lad : 0.f) * mv;

        out[(long)b*CC*TLEN + (long)(HALF + ch)*TLEN + t0 + tl] = ov * mv;
    }

    // logdet reduction
    #pragma unroll
    for (int off = 16; off; off >>= 1)
        ldsum += __shfl_xor_sync(0xFFFFFFFFu, ldsum, off);
    float* sred = (float*)(smem + OFF_RED);
    if (lane == 0) sred[wid] = ldsum;
    __syncthreads();
    if (tid == 0){
        float s = 0.f;
        #pragma unroll
        for (int k = 0; k < 8; k++) s += sred[k];
        atomicAdd(&out[(long)BB*CC*TLEN + b], s);
    }
}

// ---------------------------------------------------------------------------
extern "C" void kernel_launch(void* const* d_in, const int* in_sizes, int n_in,
                              void* d_out, int out_size){
    const float* x      = (const float*)d_in[0];
    const float* mask   = (const float*)d_in[1];
    const float* pre_w  = (const float*)d_in[2];
    const float* pre_b  = (const float*)d_in[3];
    const float* dw_w   = (const float*)d_in[4];
    const float* dw_b   = (const float*)d_in[5];
    const float* pw_w   = (const float*)d_in[6];
    const float* pw_b   = (const float*)d_in[7];
    const float* gamma1 = (const float*)d_in[8];
    const float* beta1  = (const float*)d_in[9];
    const float* gamma2 = (const float*)d_in[10];
    const float* beta2  = (const float*)d_in[11];
    const float* proj_w = (const float*)d_in[12];
    const float* proj_b = (const float*)d_in[13];
    float* out = (float*)d_out;

    cudaFuncSetAttribute(k_proj_mma, cudaFuncAttributeMaxDynamicSharedMemorySize,
                         PROJ_SMEM_BYTES);
    cudaFuncSetAttribute(k_pw_mma, cudaFuncAttributeMaxDynamicSharedMemorySize,
                         PW_SMEM_BYTES);
    cudaFuncSetAttribute(k_pre_mma, cudaFuncAttributeMaxDynamicSharedMemorySize,
                         PRE_SMEM_BYTES);

    k_prep_w<<<768, 256>>>(proj_w);
    k_prep_pw<<<192, 256>>>(pw_w);
    k_prep_pre<<<96, 256>>>(pre_w);
    k_init<<<4096, 256>>>(x, mask, out);
    k_pre_mma<<<dim3(TLEN/128, BB), 512, PRE_SMEM_BYTES>>>(x, pre_b);

    int dil = 1;
    for (int i = 0; i < 3; i++){
        k_convnorm<<<dim3(TLEN/4, BB), 256>>>(mask,
                                            dw_w + (long)i*FF*3, dw_b + (long)i*FF,
                                            gamma1 + (long)i*FF, beta1 + (long)i*FF, dil);
        k_pw_mma<<<dim3(TLEN/128, BB), 512, PW_SMEM_BYTES>>>(i,
                                            pw_b + (long)i*FF,
                                            gamma2 + (long)i*FF, beta2 + (long)i*FF,
                                            mask, (i == 2) ? 1 : 0);
        dil *= 3;
    }

    k_proj_mma<<<dim3(TLEN/NT, MROWS/MT, BB), 256, PROJ_SMEM_BYTES>>>(x, mask, proj_b, out);
}

// round 15
// speedup vs baseline: 4.9569x; 1.1387x over previous
#include <cuda_runtime.h>
#include <cuda_bf16.h>
#include <math.h>
#include <cstdint>

#define BB 16
#define CC 192
#define HALF 96
#define TLEN 2048
#define FF 256
#define NB 10
#define NJ 29        // 3*NB - 1

// ---- proj mma tiling (1-term: W bf16-rounded x h bf16-rounded) ----
#define MROWS 3072   // 96 ch * 32 padded rows
#define MT 128       // m-tile (4 channels)
#define NT 128       // t-tile
#define ASTR 272     // smem row stride bytes (128 bf16 + 16B pad)
#define BSTR 272
#define USTRIDE 129  // u smem row stride (floats), odd -> conflict-free

#define OFF_A    0            // 128*272 = 34816
#define OFF_BHI  34816        // 128*272
#define OFF_MASK 69632        // 128 floats
#define OFF_RED  70144        // 8 floats
#define PROJ_SMEM_BYTES 70272

// ---- pw mma tiling (1-term; M=256 channels, N=128 t, K staged in 4x64) ----
#define PASTR 144              // 64 bf16 + 16B pad
#define PW_OFF_AHI 0           // 256*144 = 36864
#define PW_OFF_BHI 36864       // 128*144 = 18432
#define PW_USTR 260            // epilogue f32 row stride (words), 64 t per pass
#define PW_OFF_STAT 66560      // bytes; smean[64] | srstd[64]
#define PW_SMEM_BYTES 67584

// ---- pre mma tiling (M=256 f, N=128 t, K=96 whole) ----
#define PRE_STR 208            // 96 bf16 = 192B + 16B pad
#define PRE_OFF_AHI 0          // 256*208 = 53248
#define PRE_OFF_ALO 53248
#define PRE_OFF_BHI 106496     // 128*208 = 26624
#define PRE_OFF_BLO 133120
#define PRE_SMEM_BYTES 159744

// Scratch (allocation-free rule: __device__ globals). Layout: [b][t][f].
__device__ float g_h[(size_t)BB*TLEN*FF];
__device__ __nv_bfloat16 g_whi[(size_t)MROWS*FF];
__device__ __nv_bfloat16 g_hhi[(size_t)BB*TLEN*FF];
__device__ __nv_bfloat16 g_yhi[(size_t)BB*TLEN*FF];
__device__ __nv_bfloat16 g_pwhi[(size_t)3*FF*FF];
__device__ __nv_bfloat16 g_prehi[(size_t)FF*HALF];
__device__ __nv_bfloat16 g_prelo[(size_t)FF*HALF];

__device__ __forceinline__ float gelu_exact(float v){
    return 0.5f * v * (1.f + erff(v * 0.70710678118654752f));
}
__device__ __forceinline__ float softplus_fast(float v){
    return v > 20.f ? v : __logf(1.f + __expf(v));
}
__device__ __forceinline__ uint32_t smem_u32(const void* p){
    uint32_t a;
    asm("{ .reg .u64 t; cvta.to.shared.u64 t, %1; cvt.u32.u64 %0, t; }" : "=r"(a) : "l"(p));
    return a;
}
__device__ __forceinline__ void ldm4(uint32_t* r, uint32_t addr){
    asm volatile("ldmatrix.sync.aligned.m8n8.x4.shared.b16 {%0,%1,%2,%3}, [%4];"
        : "=r"(r[0]),"=r"(r[1]),"=r"(r[2]),"=r"(r[3]) : "r"(addr));
}
__device__ __forceinline__ void mma_bf16(float* d, const uint32_t* a, uint32_t b0, uint32_t b1){
    asm volatile("mma.sync.aligned.m16n8k16.row.col.f32.bf16.bf16.f32 "
        "{%0,%1,%2,%3}, {%4,%5,%6,%7}, {%8,%9}, {%0,%1,%2,%3};"
        : "+f"(d[0]),"+f"(d[1]),"+f"(d[2]),"+f"(d[3])
        : "r"(a[0]),"r"(a[1]),"r"(a[2]),"r"(a[3]), "r"(b0),"r"(b1));
}
__device__ __forceinline__ void cp16(uint32_t saddr, const void* gptr){
    asm volatile("cp.async.cg.shared.global [%0], [%1], 16;"
        :: "r"(saddr), "l"(gptr));
}
__device__ __forceinline__ void cp_wait_all(){
    asm volatile("cp.async.commit_group;");
    asm volatile("cp.async.wait_all;" ::: "memory");
}

// ---------------------------------------------------------------------------
// Prep kernels (one-time weight conversion)
// ---------------------------------------------------------------------------
__global__ void k_prep_w(const float* __restrict__ proj_w){
    long n = (long)MROWS*FF;
    for (long i = (long)blockIdx.x*blockDim.x + threadIdx.x; i < n;
         i += (long)gridDim.x*blockDim.x){
        int k = (int)(i & (FF-1));
        int r = (int)(i >> 8);
        int ch = r >> 5, j = r & 31;
        float w = (j < NJ) ? proj_w[((long)(ch*NJ + j))*FF + k] : 0.f;
        g_whi[i] = __float2bfloat16_rn(w);
    }
}
__global__ void k_prep_pw(const float* __restrict__ pw_w){
    long n = 3L*FF*FF;
    for (long i = (long)blockIdx.x*blockDim.x + threadIdx.x; i < n;
         i += (long)gridDim.x*blockDim.x){
        g_pwhi[i] = __float2bfloat16_rn(pw_w[i]);
    }
}
__global__ void k_prep_pre(const float* __restrict__ pre_w){
    long n = (long)FF*HALF;
    for (long i = (long)blockIdx.x*blockDim.x + threadIdx.x; i < n;
         i += (long)gridDim.x*blockDim.x){
        float w = pre_w[i];
        __nv_bfloat16 hi = __float2bfloat16_rn(w);
        g_prehi[i] = hi;
        g_prelo[i] = __float2bfloat16_rn(w - __bfloat162float(hi));
    }
}

// ---------------------------------------------------------------------------
// Kernel 0: copy x0*mask into out[:, :96, :] (float4, div-free), zero logdet.
// Grid: (TLEN/4/256 = 2, HALF, BB)
// ---------------------------------------------------------------------------
__global__ __launch_bounds__(256) void k_init(const float* __restrict__ x,
                                              const float* __restrict__ mask,
                                              float* __restrict__ out){
    int t4 = blockIdx.x * 256 + threadIdx.x;      // 0..511
    int c = blockIdx.y, b = blockIdx.z;
    long row = (long)b*CC*TLEN + (long)c*TLEN;
    float4 v = *(const float4*)&x[row + t4*4];
    const float4 m = *(const float4*)&mask[(long)b*TLEN + t4*4];
    v.x *= m.x; v.y *= m.y; v.z *= m.z; v.w *= m.w;
    *(float4*)&out[row + t4*4] = v;
    if (blockIdx.x == 0 && blockIdx.y == 0 && threadIdx.x == 0)
        out[(long)BB*CC*TLEN + b] = 0.f;
}

// ---------------------------------------------------------------------------
// Kernel 1: h = pre_w @ x0 + pre_b via ldmatrix+mma (bf16 3-term).
// ---------------------------------------------------------------------------
__global__ __launch_bounds__(512) void k_pre_mma(const float* __restrict__ x,
                                                 const float* __restrict__ pre_b){
    extern __shared__ char smem[];
    uint32_t sb = smem_u32(smem);
    int tid = threadIdx.x, lane = tid & 31, wid = tid >> 5;
    int t0 = blockIdx.x * 128;
    int b = blockIdx.y;

    for (int i = tid; i < FF*12; i += 512){
        int r = i / 12, g = i - r*12;
        uint32_t off = (uint32_t)(r*PRE_STR + g*16);
        cp16(sb + PRE_OFF_AHI + off, ((const uint4*)g_prehi) + (size_t)r*12 + g);
        cp16(sb + PRE_OFF_ALO + off, ((const uint4*)g_prelo) + (size_t)r*12 + g);
    }
    for (int i = tid; i < HALF*128; i += 512){
        int c = i >> 7, tt = i & 127;
        float v = x[(long)b*CC*TLEN + (long)c*TLEN + t0 + tt];
        __nv_bfloat16 hi = __float2bfloat16_rn(v);
        uint32_t off = (uint32_t)(tt*PRE_STR + c*2);
        *(__nv_bfloat16*)(smem + PRE_OFF_BHI + off) = hi;
        *(__nv_bfloat16*)(smem + PRE_OFF_BLO + off) =
            __float2bfloat16_rn(v - __bfloat162float(hi));
    }
    cp_wait_all();
    __syncthreads();

    int wm = wid & 7, wn = wid >> 3;
    float acc[2][8][4];
    #pragma unroll
    for (int mt = 0; mt < 2; mt++)
        #pragma unroll
        for (int nt = 0; nt < 8; nt++)
            #pragma unroll
            for (int q = 0; q < 4; q++) acc[mt][nt][q] = 0.f;

    uint32_t aoff = (uint32_t)((wm*32 + (lane & 15)) * PRE_STR + ((lane >> 4) * 8) * 2);
    uint32_t aH0 = sb + PRE_OFF_AHI + aoff, aH1 = aH0 + 16*PRE_STR;
    uint32_t aL0 = sb + PRE_OFF_ALO + aoff, aL1 = aL0 + 16*PRE_STR;
    uint32_t boffc = (uint32_t)((((lane >> 4) * 8) + (lane & 7)) * PRE_STR
                                + ((lane >> 3) & 1) * 16);
    uint32_t bHp[2], bLp[2];
    #pragma unroll
    for (int hf = 0; hf < 2; hf++){
        uint32_t rowo = (uint32_t)((wn*64 + hf*32) * PRE_STR);
        bHp[hf] = sb + PRE_OFF_BHI + rowo + boffc;
        bLp[hf] = sb + PRE_OFF_BLO + rowo + boffc;
    }

    #pragma unroll
    for (int k16 = 0; k16 < 6; k16++){
        uint32_t ko = (uint32_t)(k16 * 32);
        uint32_t Ah[2][4], Al[2][4];
        ldm4(Ah[0], aH0 + ko); ldm4(Ah[1], aH1 + ko);
        ldm4(Al[0], aL0 + ko); ldm4(Al[1], aL1 + ko);
        #pragma unroll
        for (int hf = 0; hf < 2; hf++){
            uint32_t Bh[2][4], Bl[2][4];
            ldm4(Bh[0], bHp[hf] + ko); ldm4(Bh[1], bHp[hf] + 16*PRE_STR + ko);
            ldm4(Bl[0], bLp[hf] + ko); ldm4(Bl[1], bLp[hf] + 16*PRE_STR + ko);
            #pragma unroll
            for (int mt = 0; mt < 2; mt++){
                #pragma unroll
                for (int nt = 0; nt < 4; nt++){
                    uint32_t h0 = Bh[nt>>1][(nt&1)*2], h1 = Bh[nt>>1][(nt&1)*2+1];
                    uint32_t l0 = Bl[nt>>1][(nt&1)*2], l1 = Bl[nt>>1][(nt&1)*2+1];
                    mma_bf16(acc[mt][hf*4+nt], Ah[mt], h0, h1);
                    mma_bf16(acc[mt][hf*4+nt], Ah[mt], l0, l1);
                    mma_bf16(acc[mt][hf*4+nt], Al[mt], h0, h1);
                }
            }
        }
    }

    float* us = (float*)smem;
    for (int p = 0; p < 2; p++){
        __syncthreads();
        if (wn == p){
            #pragma unroll
            for (int mt = 0; mt < 2; mt++){
                #pragma unroll
                for (int nt = 0; nt < 8; nt++){
                    int tl = nt*8 + (lane & 3)*2;
                    int m = wm*32 + mt*16 + (lane >> 2);
                    #pragma unroll
                    for (int hh = 0; hh < 2; hh++){
                        int o = m + hh*8;
                        float pb = pre_b[o];
                        us[tl*PW_USTR + o]     = acc[mt][nt][2*hh+0] + pb;
                        us[(tl+1)*PW_USTR + o] = acc[mt][nt][2*hh+1] + pb;
                    }
                }
            }
        }
        __syncthreads();
        long gbase = ((long)b*TLEN + t0 + p*64) * FF;
        for (int i = tid; i < 64*64; i += 512){
            int t = i >> 6, o4 = i & 63;
            *(float4*)&g_h[gbase + (long)t*FF + o4*4] = *(float4*)&us[t*PW_USTR + o4*4];
        }
    }
}

// ---------------------------------------------------------------------------
// Kernel 2 (per layer): depthwise dilated conv + channel_norm + GELU,
// 4 t-columns per CTA. Writes bf16 (rounded) y.
// ---------------------------------------------------------------------------
__global__ __launch_bounds__(256) void k_convnorm(const float* __restrict__ mask,
                                                  const float* __restrict__ dw_w,
                                                  const float* __restrict__ dw_b,
                                                  const float* __restrict__ gamma,
                                                  const float* __restrict__ beta,
                                                  int dil){
    int t0 = blockIdx.x * 4, b = blockIdx.y, f = threadIdx.x;
    long base = (long)b*TLEN*FF;
    const float* mrow = mask + (long)b*TLEN;
    __shared__ float ss[8], ssq[8];

    float w0 = dw_w[f*3+0], w1 = dw_w[f*3+1], w2 = dw_w[f*3+2];
    float bias = dw_b[f], ga = gamma[f], be = beta[f];
    int w = threadIdx.x >> 5, l = threadIdx.x & 31;

    #pragma unroll
    for (int tt = 0; tt < 4; tt++){
        int t = t0 + tt;
        float vl = 0.f, vr = 0.f;
        float vc = g_h[base + (long)t*FF + f] * mrow[t];
        if (t - dil >= 0)    vl = g_h[base + (long)(t-dil)*FF + f] * mrow[t - dil];
        if (t + dil < TLEN)  vr = g_h[base + (long)(t+dil)*FF + f] * mrow[t + dil];
        float v = fmaf(w0, vl, fmaf(w1, vc, fmaf(w2, vr, bias)));

        float s = v, sq = v*v;
        #pragma unroll
        for (int o = 16; o; o >>= 1){
            s  += __shfl_xor_sync(0xFFFFFFFFu, s,  o);
            sq += __shfl_xor_sync(0xFFFFFFFFu, sq, o);
        }
        if (l == 0){ ss[w] = s; ssq[w] = sq; }
        __syncthreads();
        s = 0.f; sq = 0.f;
        #pragma unroll
        for (int k = 0; k < 8; k++){ s += ss[k]; sq += ssq[k]; }
        __syncthreads();

        float mean = s * (1.f/FF);
        float var  = sq * (1.f/FF) - mean*mean;
        float rstd = rsqrtf(var + 1e-5f);
        float nv = (v - mean) * rstd * ga + be;
        g_yhi[base + (long)t*FF + f] = __float2bfloat16_rn(gelu_exact(nv));
    }
}

// ---------------------------------------------------------------------------
// Kernel 3 (per layer): y2 = pw_w @ y + pw_b via ldmatrix+mma (1-term bf16),
// fused channel_norm + GELU + residual into g_h. Last layer also emits
// bf16 (rounded) h*mask for the 1-term proj GEMM.
// ---------------------------------------------------------------------------
__global__ __launch_bounds__(512) void k_pw_mma(int lay,
                                                const float* __restrict__ pw_b,
                                                const float* __restrict__ gamma,
                                                const float* __restrict__ beta,
                                                const float* __restrict__ mask,
                                                int last){
    extern __shared__ char smem[];
    uint32_t sb = smem_u32(smem);
    int tid = threadIdx.x, lane = tid & 31, wid = tid >> 5;
    int t0 = blockIdx.x * 128;
    int b = blockIdx.y;
    int wm = wid & 7, wn = wid >> 3;

    float acc[2][8][4];
    #pragma unroll
    for (int mt = 0; mt < 2; mt++)
        #pragma unroll
        for (int nt = 0; nt < 8; nt++)
            #pragma unroll
            for (int q = 0; q < 4; q++) acc[mt][nt][q] = 0.f;

    uint32_t aoff = (uint32_t)((wm*32 + (lane & 15)) * PASTR + ((lane >> 4) * 8) * 2);
    uint32_t aH0 = sb + PW_OFF_AHI + aoff, aH1 = aH0 + 16*PASTR;
    uint32_t boffc = (uint32_t)((((lane >> 4) * 8) + (lane & 7)) * PASTR
                                + ((lane >> 3) & 1) * 16);
    uint32_t bHp[2];
    #pragma unroll
    for (int hf = 0; hf < 2; hf++){
        uint32_t rowo = (uint32_t)((wn*64 + hf*32) * PASTR);
        bHp[hf] = sb + PW_OFF_BHI + rowo + boffc;
    }

    for (int c0 = 0; c0 < 4; c0++){
        if (c0) __syncthreads();
        for (int i = tid; i < FF*8; i += 512){
            int r = i >> 3, g = i & 7;
            uint32_t off = (uint32_t)(r*PASTR + g*16);
            size_t s4 = ((size_t)(lay*FF + r))*32 + (size_t)c0*8 + g;
            cp16(sb + PW_OFF_AHI + off, ((const uint4*)g_pwhi) + s4);
        }
        for (int i = tid; i < 128*8; i += 512){
            int r = i >> 3, g = i & 7;
            uint32_t off = (uint32_t)(r*PASTR + g*16);
            size_t s4 = ((size_t)b*TLEN + t0 + r)*32 + (size_t)c0*8 + g;
            cp16(sb + PW_OFF_BHI + off, ((const uint4*)g_yhi) + s4);
        }
        cp_wait_all();
        __syncthreads();

        #pragma unroll
        for (int k16 = 0; k16 < 4; k16++){
            uint32_t ko = (uint32_t)(k16 * 32);
            uint32_t Ah[2][4];
            ldm4(Ah[0], aH0 + ko); ldm4(Ah[1], aH1 + ko);
            #pragma unroll
            for (int hf = 0; hf < 2; hf++){
                uint32_t Bh[2][4];
                ldm4(Bh[0], bHp[hf] + ko); ldm4(Bh[1], bHp[hf] + 16*PASTR + ko);
                #pragma unroll
                for (int mt = 0; mt < 2; mt++){
                    #pragma unroll
                    for (int nt = 0; nt < 4; nt++){
                        uint32_t h0 = Bh[nt>>1][(nt&1)*2], h1 = Bh[nt>>1][(nt&1)*2+1];
                        mma_bf16(acc[mt][hf*4+nt], Ah[mt], h0, h1);
                    }
                }
            }
        }
    }

    // epilogue in two 64-t passes over the aliased smem buffer
    float* us = (float*)smem;
    float* smean = (float*)(smem + PW_OFF_STAT);
    float* srstd = smean + 64;

    for (int p = 0; p < 2; p++){
        __syncthreads();
        if (wn == p){
            #pragma unroll
            for (int mt = 0; mt < 2; mt++){
                #pragma unroll
                for (int nt = 0; nt < 8; nt++){
                    int tl = nt*8 + (lane & 3)*2;
                    int m = wm*32 + mt*16 + (lane >> 2);
                    #pragma unroll
                    for (int hh = 0; hh < 2; hh++){
                        int o = m + hh*8;
                        float pb = pw_b[o];
                        us[tl*PW_USTR + o]     = acc[mt][nt][2*hh+0] + pb;
                        us[(tl+1)*PW_USTR + o] = acc[mt][nt][2*hh+1] + pb;
                    }
                }
            }
        }
        __syncthreads();

        #pragma unroll
        for (int it = 0; it < 4; it++){
            int t = wid*4 + it;
            float s = 0.f, sq = 0.f;
            #pragma unroll
            for (int k = 0; k < 8; k++){
                float v = us[t*PW_USTR + lane + k*32];
                s += v; sq += v*v;
            }
            #pragma unroll
            for (int off = 16; off; off >>= 1){
                s  += __shfl_xor_sync(0xFFFFFFFFu, s,  off);
                sq += __shfl_xor_sync(0xFFFFFFFFu, sq, off);
            }
            if (lane == 0){
                float mean = s * (1.f/FF);
                smean[t] = mean;
                srstd[t] = rsqrtf(sq * (1.f/FF) - mean*mean + 1e-5f);
            }
        }
        __syncthreads();

        long gbase = ((long)b*TLEN + t0 + p*64) * FF;
        for (int i = tid; i < 64*64; i += 512){
            int t = i >> 6, o4 = i & 63;
            float4 u = *(float4*)&us[t*PW_USTR + o4*4];
            float mean = smean[t], rstd = srstd[t];
            const float4 ga = *(const float4*)&gamma[o4*4];
            const float4 be = *(const float4*)&beta[o4*4];
            long idx = gbase + (long)t*FF + o4*4;
            float4 hv = *(float4*)&g_h[idx];
            hv.x += gelu_exact((u.x - mean)*rstd*ga.x + be.x);
            hv.y += gelu_exact((u.y - mean)*rstd*ga.y + be.y);
            hv.z += gelu_exact((u.z - mean)*rstd*ga.z + be.z);
            hv.w += gelu_exact((u.w - mean)*rstd*ga.w + be.w);
            *(float4*)&g_h[idx] = hv;
            if (last){
                float mv = mask[(long)b*TLEN + t0 + p*64 + t];
                __nv_bfloat162 p0, p1;
                p0.x = __float2bfloat16_rn(hv.x*mv);
                p0.y = __float2bfloat16_rn(hv.y*mv);
                p1.x = __float2bfloat16_rn(hv.z*mv);
                p1.y = __float2bfloat16_rn(hv.w*mv);
                *(__nv_bfloat162*)&g_hhi[idx]   = p0;
                *(__nv_bfloat162*)&g_hhi[idx+2] = p1;
            }
        }
    }
}

// ---------------------------------------------------------------------------
// Kernel 4: 1-term bf16 GEMM (u = W @ h^T) via ldmatrix + mma.sync, fused
// with the RQ spline. CTA 256 thr / 8 warps (4m x 2n, n=64/warp).
// Tile M=128 x N=128 t, K=256 in 2 chunks.
// ---------------------------------------------------------------------------
__global__ __launch_bounds__(256, 2) void k_proj_mma(const float* __restrict__ x,
                                                     const float* __restrict__ mask,
                                                     const float* __restrict__ proj_b,
                                                     float* __restrict__ out){
    extern __shared__ char smem[];
    uint32_t sb = smem_u32(smem);
    int tid = threadIdx.x, lane = tid & 31, wid = tid >> 5;
    int t0 = blockIdx.x * NT;
    int mtile = blockIdx.y;
    int b = blockIdx.z;
    int m0 = mtile * MT;
    int ch0 = mtile * 4;

    float* smask = (float*)(smem + OFF_MASK);
    if (tid < NT) smask[tid] = mask[(long)b*TLEN + t0 + tid];

    float acc[2][8][4];
    #pragma unroll
    for (int mt = 0; mt < 2; mt++)
        #pragma unroll
        for (int nt = 0; nt < 8; nt++)
            #pragma unroll
            for (int q = 0; q < 4; q++) acc[mt][nt][q] = 0.f;

    int wm = wid & 3, wn = wid >> 2;
    uint32_t aoff = (uint32_t)((wm*32 + (lane & 15)) * ASTR + ((lane >> 4) * 8) * 2);
    uint32_t aH0 = sb + OFF_A + aoff, aH1 = aH0 + 16*ASTR;
    uint32_t boffc = (uint32_t)((((lane >> 4) * 8) + (lane & 7)) * BSTR
                                + ((lane >> 3) & 1) * 16);
    uint32_t bHp[2];
    #pragma unroll
    for (int hf = 0; hf < 2; hf++){
        uint32_t rowo = (uint32_t)((wn*64 + hf*32) * BSTR);
        bHp[hf] = sb + OFF_BHI + rowo + boffc;
    }

    for (int c = 0; c < 2; c++){
        if (c) __syncthreads();
        for (int i = tid; i < MT*16; i += 256){
            int r = i >> 4, g = i & 15;
            uint32_t off = (uint32_t)(r*ASTR + g*16);
            size_t s4 = ((size_t)(m0 + r))*32 + (size_t)c*16 + g;
            cp16(sb + OFF_A + off, ((const uint4*)g_whi) + s4);
        }
        for (int i = tid; i < NT*16; i += 256){
            int r = i >> 4, g = i & 15;
            uint32_t off = (uint32_t)(r*BSTR + g*16);
            size_t s4 = ((size_t)b*TLEN + t0 + r)*32 + (size_t)c*16 + g;
            cp16(sb + OFF_BHI + off, ((const uint4*)g_hhi) + s4);
        }
        cp_wait_all();
        __syncthreads();

        #pragma unroll
        for (int k16 = 0; k16 < 8; k16++){
            uint32_t ko = (uint32_t)(k16 * 32);
            uint32_t Ah[2][4];
            ldm4(Ah[0], aH0 + ko); ldm4(Ah[1], aH1 + ko);
            #pragma unroll
            for (int hf = 0; hf < 2; hf++){
                uint32_t Bh[2][4];
                ldm4(Bh[0], bHp[hf] + ko); ldm4(Bh[1], bHp[hf] + 16*BSTR + ko);
                #pragma unroll
                for (int mt = 0; mt < 2; mt++){
                    #pragma unroll
                    for (int nt = 0; nt < 4; nt++){
                        uint32_t h0 = Bh[nt>>1][(nt&1)*2], h1 = Bh[nt>>1][(nt&1)*2+1];
                        mma_bf16(acc[mt][hf*4+nt], Ah[mt], h0, h1);
                    }
                }
            }
        }
    }
    __syncthreads();

    // u -> smem (alias over A/B regions): us[row][t], stride 129 floats
    float* us = (float*)smem;
    #pragma unroll
    for (int mt = 0; mt < 2; mt++){
        #pragma unroll
        for (int g = 0; g < 8; g++){
            int r = wm*32 + mt*16 + (lane >> 2);
            int t = wn*64 + g*8 + (lane & 3)*2;
            #pragma unroll
            for (int hh = 0; hh < 2; hh++){
                int rr = r + hh*8;
                int j = rr & 31;
                int ch = ch0 + (rr >> 5);
                float pb = (j < NJ) ? proj_b[ch*NJ + j] : 0.f;
                us[rr*USTRIDE + t]     = (acc[mt][g][2*hh+0] + pb) * smask[t];
                us[rr*USTRIDE + t + 1] = (acc[mt][g][2*hh+1] + pb) * smask[t+1];
            }
        }
    }
    __syncthreads();

    // --- spline: 4 ch x 128 t = 512 evals, 2 per thread ---
    const float SCALE = 0.0625f;
    int chl = tid >> 6;
    int ch = ch0 + chl;
    float ldsum = 0.f;

    #pragma unroll
    for (int it = 0; it < 2; it++){
        int tl = (tid & 63) + it*64;
        const float* ub = us + (chl*32)*USTRIDE + tl;   // ub[j*USTRIDE]
        float x1v = x[(long)b*CC*TLEN + (long)(HALF + ch)*TLEN + t0 + tl];
        float mv  = smask[tl];

        float uw[10];
        #pragma unroll
        for (int j = 0; j < 10; j++) uw[j] = ub[j*USTRIDE] * SCALE;
        float mx = uw[0];
        #pragma unroll
        for (int j = 1; j < 10; j++) mx = fmaxf(mx, uw[j]);
        float ew[10]; float sw = 0.f;
        #pragma unroll
        for (int j = 0; j < 10; j++){ ew[j] = __expf(uw[j] - mx); sw += ew[j]; }
        float cw[11]; cw[0] = -5.f;
        {
            float inv = __frcp_rn(sw), cs = 0.f;
            #pragma unroll
            for (int j = 0; j < 9; j++){
                cs += fmaf(0.99f, ew[j]*inv, 0.001f);
                cw[j+1] = fmaf(10.f, cs, -5.f);
            }
            cw[10] = 5.f;
        }
        #pragma unroll
        for (int j = 0; j < 10; j++) uw[j] = ub[(10+j)*USTRIDE] * SCALE;
        mx = uw[0];
        #pragma unroll
        for (int j = 1; j < 10; j++) mx = fmaxf(mx, uw[j]);
        sw = 0.f;
        #pragma unroll
        for (int j = 0; j < 10; j++){ ew[j] = __expf(uw[j] - mx); sw += ew[j]; }
        float chh[11]; chh[0] = -5.f;
        {
            float inv = __frcp_rn(sw), cs = 0.f;
            #pragma unroll
            for (int j = 0; j < 9; j++){
                cs += fmaf(0.99f, ew[j]*inv, 0.001f);
                chh[j+1] = fmaf(10.f, cs, -5.f);
            }
            chh[10] = 5.f;
        }

        float xc = fminf(fmaxf(x1v, -5.f), 5.f);
        int idx = 0;
        #pragma unroll
        for (int j = 1; j <= 9; j++) idx += (xc >= cw[j]) ? 1 : 0;

        float cwl = cw[0], cwr = cw[1], chl2 = chh[0], chr = chh[1];
        #pragma unroll
        for (int j = 1; j < 10; j++){
            if (idx == j){ cwl = cw[j]; cwr = cw[j+1]; chl2 = chh[j]; chr = chh[j+1]; }
        }
        float d0 = (idx == 0) ? 1.f : 0.001f + softplus_fast(ub[(19 + idx)*USTRIDE]);
        float d1 = (idx == 9) ? 1.f : 0.001f + softplus_fast(ub[(20 + idx)*USTRIDE]);

        float wb = cwr - cwl, hb = chr - chl2;
        float inv_wb = __frcp_rn(wb);
        float delta = hb * inv_wb;
        float th = (xc - cwl) * inv_wb;
        float omt = 1.f - th;
        float t1m = th * omt;
        float denom = delta + (d0 + d1 - 2.f*delta) * t1m;
        float num = hb * (delta*th*th + d0*t1m);
        float yv = chl2 + num / denom;
        float dnum = delta*delta * (d1*th*th + 2.f*delta*t1m + d0*omt*omt);
        float lad = __logf(dnum) - 2.f*__logf(denom);

        bool inside = (x1v >= -5.f) && (x1v <= 5.f);
        float ov = inside ? yv : x1v;
        ldsum += (inside ? lad : 0.f) * mv;

        out[(long)b*CC*TLEN + (long)(HALF + ch)*TLEN + t0 + tl] = ov * mv;
    }

    // logdet reduction
    #pragma unroll
    for (int off = 16; off; off >>= 1)
        ldsum += __shfl_xor_sync(0xFFFFFFFFu, ldsum, off);
    float* sred = (float*)(smem + OFF_RED);
    if (lane == 0) sred[wid] = ldsum;
    __syncthreads();
    if (tid == 0){
        float s = 0.f;
        #pragma unroll
        for (int k = 0; k < 8; k++) s += sred[k];
        atomicAdd(&out[(long)BB*CC*TLEN + b], s);
    }
}

// ---------------------------------------------------------------------------
extern "C" void kernel_launch(void* const* d_in, const int* in_sizes, int n_in,
                              void* d_out, int out_size){
    const float* x      = (const float*)d_in[0];
    const float* mask   = (const float*)d_in[1];
    const float* pre_w  = (const float*)d_in[2];
    const float* pre_b  = (const float*)d_in[3];
    const float* dw_w   = (const float*)d_in[4];
    const float* dw_b   = (const float*)d_in[5];
    const float* pw_w   = (const float*)d_in[6];
    const float* pw_b   = (const float*)d_in[7];
    const float* gamma1 = (const float*)d_in[8];
    const float* beta1  = (const float*)d_in[9];
    const float* gamma2 = (const float*)d_in[10];
    const float* beta2  = (const float*)d_in[11];
    const float* proj_w = (const float*)d_in[12];
    const float* proj_b = (const float*)d_in[13];
    float* out = (float*)d_out;

    cudaFuncSetAttribute(k_proj_mma, cudaFuncAttributeMaxDynamicSharedMemorySize,
                         PROJ_SMEM_BYTES);
    cudaFuncSetAttribute(k_pw_mma, cudaFuncAttributeMaxDynamicSharedMemorySize,
                         PW_SMEM_BYTES);
    cudaFuncSetAttribute(k_pre_mma, cudaFuncAttributeMaxDynamicSharedMemorySize,
                         PRE_SMEM_BYTES);

    k_prep_w<<<768, 256>>>(proj_w);
    k_prep_pw<<<192, 256>>>(pw_w);
    k_prep_pre<<<96, 256>>>(pre_w);
    k_init<<<dim3(2, HALF, BB), 256>>>(x, mask, out);
    k_pre_mma<<<dim3(TLEN/128, BB), 512, PRE_SMEM_BYTES>>>(x, pre_b);

    int dil = 1;
    for (int i = 0; i < 3; i++){
        k_convnorm<<<dim3(TLEN/4, BB), 256>>>(mask,
                                            dw_w + (long)i*FF*3, dw_b + (long)i*FF,
                                            gamma1 + (long)i*FF, beta1 + (long)i*FF, dil);
        k_pw_mma<<<dim3(TLEN/128, BB), 512, PW_SMEM_BYTES>>>(i,
                                            pw_b + (long)i*FF,
                                            gamma2 + (long)i*FF, beta2 + (long)i*FF,
                                            mask, (i == 2) ? 1 : 0);
        dil *= 3;
    }

    k_proj_mma<<<dim3(TLEN/NT, MROWS/MT, BB), 256, PROJ_SMEM_BYTES>>>(x, mask, proj_b, out);
}

// round 16
// speedup vs baseline: 5.1107x; 1.0310x over previous
#include <cuda_runtime.h>
#include <cuda_bf16.h>
#include <math.h>
#include <cstdint>

#define BB 16
#define CC 192
#define HALF 96
#define TLEN 2048
#define FF 256
#define NB 10
#define NJ 29        // 3*NB - 1

// ---- proj mma tiling (1-term, 4x64-k pipelined) ----
#define MROWS 3072   // 96 ch * 32 padded rows
#define MT 128       // m-tile (4 channels)
#define NT 128       // t-tile
#define PSTR 144     // smem row stride bytes (64 bf16 + 16B pad)
#define USTRIDE 129  // u smem row stride (floats)

#define PROJ_STG 36864        // per-slot: A 128*144 + B 128*144
#define OFF_MASK 73728        // 128 floats
#define OFF_RED  74240        // 8 floats
#define PROJ_SMEM_BYTES 74368

// ---- pw mma tiling (1-term; M=256, N=128 t, 4x64-k pipelined) ----
#define PW_STG 55296          // per-slot: A 256*144 + B 128*144
#define PW_USTR 260           // epilogue f32 row stride (words)
#define PW_OFF_STAT 110592    // bytes; smean[64] | srstd[64]
#define PW_SMEM_BYTES 111104

// ---- pre mma tiling (M=256 f, N=128 t, K=96 whole) ----
#define PRE_STR 208
#define PRE_OFF_AHI 0
#define PRE_OFF_ALO 53248
#define PRE_OFF_BHI 106496
#define PRE_OFF_BLO 133120
#define PRE_SMEM_BYTES 159744

// Scratch (allocation-free rule: __device__ globals). Layout: [b][t][f].
__device__ float g_h[(size_t)BB*TLEN*FF];
__device__ __nv_bfloat16 g_whi[(size_t)MROWS*FF];
__device__ __nv_bfloat16 g_hhi[(size_t)BB*TLEN*FF];
__device__ __nv_bfloat16 g_yhi[(size_t)BB*TLEN*FF];
__device__ __nv_bfloat16 g_pwhi[(size_t)3*FF*FF];
__device__ __nv_bfloat16 g_prehi[(size_t)FF*HALF];
__device__ __nv_bfloat16 g_prelo[(size_t)FF*HALF];

__device__ __forceinline__ float gelu_exact(float v){
    return 0.5f * v * (1.f + erff(v * 0.70710678118654752f));
}
__device__ __forceinline__ float softplus_fast(float v){
    return v > 20.f ? v : __logf(1.f + __expf(v));
}
__device__ __forceinline__ uint32_t smem_u32(const void* p){
    uint32_t a;
    asm("{ .reg .u64 t; cvta.to.shared.u64 t, %1; cvt.u32.u64 %0, t; }" : "=r"(a) : "l"(p));
    return a;
}
__device__ __forceinline__ void ldm4(uint32_t* r, uint32_t addr){
    asm volatile("ldmatrix.sync.aligned.m8n8.x4.shared.b16 {%0,%1,%2,%3}, [%4];"
        : "=r"(r[0]),"=r"(r[1]),"=r"(r[2]),"=r"(r[3]) : "r"(addr));
}
__device__ __forceinline__ void mma_bf16(float* d, const uint32_t* a, uint32_t b0, uint32_t b1){
    asm volatile("mma.sync.aligned.m16n8k16.row.col.f32.bf16.bf16.f32 "
        "{%0,%1,%2,%3}, {%4,%5,%6,%7}, {%8,%9}, {%0,%1,%2,%3};"
        : "+f"(d[0]),"+f"(d[1]),"+f"(d[2]),"+f"(d[3])
        : "r"(a[0]),"r"(a[1]),"r"(a[2]),"r"(a[3]), "r"(b0),"r"(b1));
}
__device__ __forceinline__ void cp16(uint32_t saddr, const void* gptr){
    asm volatile("cp.async.cg.shared.global [%0], [%1], 16;"
        :: "r"(saddr), "l"(gptr));
}
__device__ __forceinline__ void cp_commit(){
    asm volatile("cp.async.commit_group;");
}
__device__ __forceinline__ void cp_waitg1(){
    asm volatile("cp.async.wait_group 1;" ::: "memory");
}
__device__ __forceinline__ void cp_waitg0(){
    asm volatile("cp.async.wait_group 0;" ::: "memory");
}
__device__ __forceinline__ void cp_wait_all(){
    asm volatile("cp.async.commit_group;");
    asm volatile("cp.async.wait_all;" ::: "memory");
}

// ---------------------------------------------------------------------------
// Prep kernels (one-time weight conversion)
// ---------------------------------------------------------------------------
__global__ void k_prep_w(const float* __restrict__ proj_w){
    long n = (long)MROWS*FF;
    for (long i = (long)blockIdx.x*blockDim.x + threadIdx.x; i < n;
         i += (long)gridDim.x*blockDim.x){
        int k = (int)(i & (FF-1));
        int r = (int)(i >> 8);
        int ch = r >> 5, j = r & 31;
        float w = (j < NJ) ? proj_w[((long)(ch*NJ + j))*FF + k] : 0.f;
        g_whi[i] = __float2bfloat16_rn(w);
    }
}
__global__ void k_prep_pw(const float* __restrict__ pw_w){
    long n = 3L*FF*FF;
    for (long i = (long)blockIdx.x*blockDim.x + threadIdx.x; i < n;
         i += (long)gridDim.x*blockDim.x){
        g_pwhi[i] = __float2bfloat16_rn(pw_w[i]);
    }
}
__global__ void k_prep_pre(const float* __restrict__ pre_w){
    long n = (long)FF*HALF;
    for (long i = (long)blockIdx.x*blockDim.x + threadIdx.x; i < n;
         i += (long)gridDim.x*blockDim.x){
        float w = pre_w[i];
        __nv_bfloat16 hi = __float2bfloat16_rn(w);
        g_prehi[i] = hi;
        g_prelo[i] = __float2bfloat16_rn(w - __bfloat162float(hi));
    }
}

// ---------------------------------------------------------------------------
// Kernel 0: copy x0*mask into out[:, :96, :] (float4), zero logdet.
// ---------------------------------------------------------------------------
__global__ __launch_bounds__(256) void k_init(const float* __restrict__ x,
                                              const float* __restrict__ mask,
                                              float* __restrict__ out){
    int t4 = blockIdx.x * 256 + threadIdx.x;
    int c = blockIdx.y, b = blockIdx.z;
    long row = (long)b*CC*TLEN + (long)c*TLEN;
    float4 v = *(const float4*)&x[row + t4*4];
    const float4 m = *(const float4*)&mask[(long)b*TLEN + t4*4];
    v.x *= m.x; v.y *= m.y; v.z *= m.z; v.w *= m.w;
    *(float4*)&out[row + t4*4] = v;
    if (blockIdx.x == 0 && blockIdx.y == 0 && threadIdx.x == 0)
        out[(long)BB*CC*TLEN + b] = 0.f;
}

// ---------------------------------------------------------------------------
// Kernel 1: h = pre_w @ x0 + pre_b via ldmatrix+mma (bf16 3-term).
// ---------------------------------------------------------------------------
__global__ __launch_bounds__(512) void k_pre_mma(const float* __restrict__ x,
                                                 const float* __restrict__ pre_b){
    extern __shared__ char smem[];
    uint32_t sb = smem_u32(smem);
    int tid = threadIdx.x, lane = tid & 31, wid = tid >> 5;
    int t0 = blockIdx.x * 128;
    int b = blockIdx.y;

    for (int i = tid; i < FF*12; i += 512){
        int r = i / 12, g = i - r*12;
        uint32_t off = (uint32_t)(r*PRE_STR + g*16);
        cp16(sb + PRE_OFF_AHI + off, ((const uint4*)g_prehi) + (size_t)r*12 + g);
        cp16(sb + PRE_OFF_ALO + off, ((const uint4*)g_prelo) + (size_t)r*12 + g);
    }
    for (int i = tid; i < HALF*128; i += 512){
        int c = i >> 7, tt = i & 127;
        float v = x[(long)b*CC*TLEN + (long)c*TLEN + t0 + tt];
        __nv_bfloat16 hi = __float2bfloat16_rn(v);
        uint32_t off = (uint32_t)(tt*PRE_STR + c*2);
        *(__nv_bfloat16*)(smem + PRE_OFF_BHI + off) = hi;
        *(__nv_bfloat16*)(smem + PRE_OFF_BLO + off) =
            __float2bfloat16_rn(v - __bfloat162float(hi));
    }
    cp_wait_all();
    __syncthreads();

    int wm = wid & 7, wn = wid >> 3;
    float acc[2][8][4];
    #pragma unroll
    for (int mt = 0; mt < 2; mt++)
        #pragma unroll
        for (int nt = 0; nt < 8; nt++)
            #pragma unroll
            for (int q = 0; q < 4; q++) acc[mt][nt][q] = 0.f;

    uint32_t aoff = (uint32_t)((wm*32 + (lane & 15)) * PRE_STR + ((lane >> 4) * 8) * 2);
    uint32_t aH0 = sb + PRE_OFF_AHI + aoff, aH1 = aH0 + 16*PRE_STR;
    uint32_t aL0 = sb + PRE_OFF_ALO + aoff, aL1 = aL0 + 16*PRE_STR;
    uint32_t boffc = (uint32_t)((((lane >> 4) * 8) + (lane & 7)) * PRE_STR
                                + ((lane >> 3) & 1) * 16);
    uint32_t bHp[2], bLp[2];
    #pragma unroll
    for (int hf = 0; hf < 2; hf++){
        uint32_t rowo = (uint32_t)((wn*64 + hf*32) * PRE_STR);
        bHp[hf] = sb + PRE_OFF_BHI + rowo + boffc;
        bLp[hf] = sb + PRE_OFF_BLO + rowo + boffc;
    }

    #pragma unroll
    for (int k16 = 0; k16 < 6; k16++){
        uint32_t ko = (uint32_t)(k16 * 32);
        uint32_t Ah[2][4], Al[2][4];
        ldm4(Ah[0], aH0 + ko); ldm4(Ah[1], aH1 + ko);
        ldm4(Al[0], aL0 + ko); ldm4(Al[1], aL1 + ko);
        #pragma unroll
        for (int hf = 0; hf < 2; hf++){
            uint32_t Bh[2][4], Bl[2][4];
            ldm4(Bh[0], bHp[hf] + ko); ldm4(Bh[1], bHp[hf] + 16*PRE_STR + ko);
            ldm4(Bl[0], bLp[hf] + ko); ldm4(Bl[1], bLp[hf] + 16*PRE_STR + ko);
            #pragma unroll
            for (int mt = 0; mt < 2; mt++){
                #pragma unroll
                for (int nt = 0; nt < 4; nt++){
                    uint32_t h0 = Bh[nt>>1][(nt&1)*2], h1 = Bh[nt>>1][(nt&1)*2+1];
                    uint32_t l0 = Bl[nt>>1][(nt&1)*2], l1 = Bl[nt>>1][(nt&1)*2+1];
                    mma_bf16(acc[mt][hf*4+nt], Ah[mt], h0, h1);
                    mma_bf16(acc[mt][hf*4+nt], Ah[mt], l0, l1);
                    mma_bf16(acc[mt][hf*4+nt], Al[mt], h0, h1);
                }
            }
        }
    }

    float* us = (float*)smem;
    for (int p = 0; p < 2; p++){
        __syncthreads();
        if (wn == p){
            #pragma unroll
            for (int mt = 0; mt < 2; mt++){
                #pragma unroll
                for (int nt = 0; nt < 8; nt++){
                    int tl = nt*8 + (lane & 3)*2;
                    int m = wm*32 + mt*16 + (lane >> 2);
                    #pragma unroll
                    for (int hh = 0; hh < 2; hh++){
                        int o = m + hh*8;
                        float pb = pre_b[o];
                        us[tl*PW_USTR + o]     = acc[mt][nt][2*hh+0] + pb;
                        us[(tl+1)*PW_USTR + o] = acc[mt][nt][2*hh+1] + pb;
                    }
                }
            }
        }
        __syncthreads();
        long gbase = ((long)b*TLEN + t0 + p*64) * FF;
        for (int i = tid; i < 64*64; i += 512){
            int t = i >> 6, o4 = i & 63;
            *(float4*)&g_h[gbase + (long)t*FF + o4*4] = *(float4*)&us[t*PW_USTR + o4*4];
        }
    }
}

// ---------------------------------------------------------------------------
// Kernel 2 (per layer): depthwise dilated conv + channel_norm + GELU,
// 4 t-columns per CTA. Writes bf16 (rounded) y.
// ---------------------------------------------------------------------------
__global__ __launch_bounds__(256) void k_convnorm(const float* __restrict__ mask,
                                                  const float* __restrict__ dw_w,
                                                  const float* __restrict__ dw_b,
                                                  const float* __restrict__ gamma,
                                                  const float* __restrict__ beta,
                                                  int dil){
    int t0 = blockIdx.x * 4, b = blockIdx.y, f = threadIdx.x;
    long base = (long)b*TLEN*FF;
    const float* mrow = mask + (long)b*TLEN;
    __shared__ float ss[8], ssq[8];

    float w0 = dw_w[f*3+0], w1 = dw_w[f*3+1], w2 = dw_w[f*3+2];
    float bias = dw_b[f], ga = gamma[f], be = beta[f];
    int w = threadIdx.x >> 5, l = threadIdx.x & 31;

    #pragma unroll
    for (int tt = 0; tt < 4; tt++){
        int t = t0 + tt;
        float vl = 0.f, vr = 0.f;
        float vc = g_h[base + (long)t*FF + f] * mrow[t];
        if (t - dil >= 0)    vl = g_h[base + (long)(t-dil)*FF + f] * mrow[t - dil];
        if (t + dil < TLEN)  vr = g_h[base + (long)(t+dil)*FF + f] * mrow[t + dil];
        float v = fmaf(w0, vl, fmaf(w1, vc, fmaf(w2, vr, bias)));

        float s = v, sq = v*v;
        #pragma unroll
        for (int o = 16; o; o >>= 1){
            s  += __shfl_xor_sync(0xFFFFFFFFu, s,  o);
            sq += __shfl_xor_sync(0xFFFFFFFFu, sq, o);
        }
        if (l == 0){ ss[w] = s; ssq[w] = sq; }
        __syncthreads();
        s = 0.f; sq = 0.f;
        #pragma unroll
        for (int k = 0; k < 8; k++){ s += ss[k]; sq += ssq[k]; }
        __syncthreads();

        float mean = s * (1.f/FF);
        float var  = sq * (1.f/FF) - mean*mean;
        float rstd = rsqrtf(var + 1e-5f);
        float nv = (v - mean) * rstd * ga + be;
        g_yhi[base + (long)t*FF + f] = __float2bfloat16_rn(gelu_exact(nv));
    }
}

// ---------------------------------------------------------------------------
// Kernel 3 (per layer): y2 = pw_w @ y + pw_b via ldmatrix+mma (1-term bf16),
// 2-deep pipelined staging over 4 k-chunks of 64. Fused channel_norm + GELU
// + residual into g_h; last layer emits bf16 h*mask for proj.
// ---------------------------------------------------------------------------
__global__ __launch_bounds__(512) void k_pw_mma(int lay,
                                                const float* __restrict__ pw_b,
                                                const float* __restrict__ gamma,
                                                const float* __restrict__ beta,
                                                const float* __restrict__ mask,
                                                int last){
    extern __shared__ char smem[];
    uint32_t sb = smem_u32(smem);
    int tid = threadIdx.x, lane = tid & 31, wid = tid >> 5;
    int t0 = blockIdx.x * 128;
    int b = blockIdx.y;
    int wm = wid & 7, wn = wid >> 3;

    float acc[2][8][4];
    #pragma unroll
    for (int mt = 0; mt < 2; mt++)
        #pragma unroll
        for (int nt = 0; nt < 8; nt++)
            #pragma unroll
            for (int q = 0; q < 4; q++) acc[mt][nt][q] = 0.f;

    const uint4* srcA = ((const uint4*)g_pwhi) + (size_t)lay*FF*32;
    const uint4* srcB = ((const uint4*)g_yhi) + ((size_t)b*TLEN + t0)*32;

    // issue stages 0,1
    #pragma unroll
    for (int s = 0; s < 2; s++){
        uint32_t ab = sb + s*PW_STG, bb = ab + 36864;
        for (int i = tid; i < FF*8; i += 512){
            int r = i >> 3, g = i & 7;
            cp16(ab + (uint32_t)(r*PSTR + g*16), srcA + (size_t)r*32 + s*8 + g);
        }
        for (int i = tid; i < 128*8; i += 512){
            int r = i >> 3, g = i & 7;
            cp16(bb + (uint32_t)(r*PSTR + g*16), srcB + (size_t)r*32 + s*8 + g);
        }
        cp_commit();
    }

    uint32_t aoff = (uint32_t)((wm*32 + (lane & 15)) * PSTR + ((lane >> 4) * 8) * 2);
    uint32_t boffc = (uint32_t)((((lane >> 4) * 8) + (lane & 7)) * PSTR
                                + ((lane >> 3) & 1) * 16);

    #pragma unroll
    for (int s = 0; s < 4; s++){
        if (s < 3) cp_waitg1(); else cp_waitg0();
        __syncthreads();
        uint32_t ab = sb + (s & 1)*PW_STG, bb = ab + 36864;
        uint32_t aH0 = ab + aoff, aH1 = aH0 + 16*PSTR;
        uint32_t bH0 = bb + (uint32_t)((wn*64) * PSTR) + boffc;
        uint32_t bH1 = bb + (uint32_t)((wn*64 + 32) * PSTR) + boffc;

        #pragma unroll
        for (int k16 = 0; k16 < 4; k16++){
            uint32_t ko = (uint32_t)(k16 * 32);
            uint32_t Ah[2][4];
            ldm4(Ah[0], aH0 + ko); ldm4(Ah[1], aH1 + ko);
            #pragma unroll
            for (int hf = 0; hf < 2; hf++){
                uint32_t base = hf ? bH1 : bH0;
                uint32_t Bh[2][4];
                ldm4(Bh[0], base + ko); ldm4(Bh[1], base + 16*PSTR + ko);
                #pragma unroll
                for (int mt = 0; mt < 2; mt++){
                    #pragma unroll
                    for (int nt = 0; nt < 4; nt++){
                        uint32_t h0 = Bh[nt>>1][(nt&1)*2], h1 = Bh[nt>>1][(nt&1)*2+1];
                        mma_bf16(acc[mt][hf*4+nt], Ah[mt], h0, h1);
                    }
                }
            }
        }
        __syncthreads();
        if (s < 2){
            int sn = s + 2;
            uint32_t ab2 = sb + (s & 1)*PW_STG, bb2 = ab2 + 36864;
            for (int i = tid; i < FF*8; i += 512){
                int r = i >> 3, g = i & 7;
                cp16(ab2 + (uint32_t)(r*PSTR + g*16), srcA + (size_t)r*32 + sn*8 + g);
            }
            for (int i = tid; i < 128*8; i += 512){
                int r = i >> 3, g = i & 7;
                cp16(bb2 + (uint32_t)(r*PSTR + g*16), srcB + (size_t)r*32 + sn*8 + g);
            }
            cp_commit();
        }
    }

    // epilogue in two 64-t passes over the aliased smem buffer
    float* us = (float*)smem;
    float* smean = (float*)(smem + PW_OFF_STAT);
    float* srstd = smean + 64;

    for (int p = 0; p < 2; p++){
        __syncthreads();
        if (wn == p){
            #pragma unroll
            for (int mt = 0; mt < 2; mt++){
                #pragma unroll
                for (int nt = 0; nt < 8; nt++){
                    int tl = nt*8 + (lane & 3)*2;
                    int m = wm*32 + mt*16 + (lane >> 2);
                    #pragma unroll
                    for (int hh = 0; hh < 2; hh++){
                        int o = m + hh*8;
                        float pb = pw_b[o];
                        us[tl*PW_USTR + o]     = acc[mt][nt][2*hh+0] + pb;
                        us[(tl+1)*PW_USTR + o] = acc[mt][nt][2*hh+1] + pb;
                    }
                }
            }
        }
        __syncthreads();

        #pragma unroll
        for (int it = 0; it < 4; it++){
            int t = wid*4 + it;
            float s = 0.f, sq = 0.f;
            #pragma unroll
            for (int k = 0; k < 8; k++){
                float v = us[t*PW_USTR + lane + k*32];
                s += v; sq += v*v;
            }
            #pragma unroll
            for (int off = 16; off; off >>= 1){
                s  += __shfl_xor_sync(0xFFFFFFFFu, s,  off);
                sq += __shfl_xor_sync(0xFFFFFFFFu, sq, off);
            }
            if (lane == 0){
                float mean = s * (1.f/FF);
                smean[t] = mean;
                srstd[t] = rsqrtf(sq * (1.f/FF) - mean*mean + 1e-5f);
            }
        }
        __syncthreads();

        long gbase = ((long)b*TLEN + t0 + p*64) * FF;
        for (int i = tid; i < 64*64; i += 512){
            int t = i >> 6, o4 = i & 63;
            float4 u = *(float4*)&us[t*PW_USTR + o4*4];
            float mean = smean[t], rstd = srstd[t];
            const float4 ga = *(const float4*)&gamma[o4*4];
            const float4 be = *(const float4*)&beta[o4*4];
            long idx = gbase + (long)t*FF + o4*4;
            float4 hv = *(float4*)&g_h[idx];
            hv.x += gelu_exact((u.x - mean)*rstd*ga.x + be.x);
            hv.y += gelu_exact((u.y - mean)*rstd*ga.y + be.y);
            hv.z += gelu_exact((u.z - mean)*rstd*ga.z + be.z);
            hv.w += gelu_exact((u.w - mean)*rstd*ga.w + be.w);
            *(float4*)&g_h[idx] = hv;
            if (last){
                float mv = mask[(long)b*TLEN + t0 + p*64 + t];
                __nv_bfloat162 p0, p1;
                p0.x = __float2bfloat16_rn(hv.x*mv);
                p0.y = __float2bfloat16_rn(hv.y*mv);
                p1.x = __float2bfloat16_rn(hv.z*mv);
                p1.y = __float2bfloat16_rn(hv.w*mv);
                *(__nv_bfloat162*)&g_hhi[idx]   = p0;
                *(__nv_bfloat162*)&g_hhi[idx+2] = p1;
            }
        }
    }
}

// ---------------------------------------------------------------------------
// Kernel 4: 1-term bf16 GEMM (u = W @ h^T), 2-deep pipelined staging over
// 4 k-chunks of 64, fused with the RQ spline. CTA 256 thr / 8 warps.
// ---------------------------------------------------------------------------
__global__ __launch_bounds__(256, 2) void k_proj_mma(const float* __restrict__ x,
                                                     const float* __restrict__ mask,
                                                     const float* __restrict__ proj_b,
                                                     float* __restrict__ out){
    extern __shared__ char smem[];
    uint32_t sb = smem_u32(smem);
    int tid = threadIdx.x, lane = tid & 31, wid = tid >> 5;
    int t0 = blockIdx.x * NT;
    int mtile = blockIdx.y;
    int b = blockIdx.z;
    int m0 = mtile * MT;
    int ch0 = mtile * 4;

    float* smask = (float*)(smem + OFF_MASK);
    if (tid < NT) smask[tid] = mask[(long)b*TLEN + t0 + tid];

    float acc[2][8][4];
    #pragma unroll
    for (int mt = 0; mt < 2; mt++)
        #pragma unroll
        for (int nt = 0; nt < 8; nt++)
            #pragma unroll
            for (int q = 0; q < 4; q++) acc[mt][nt][q] = 0.f;

    int wm = wid & 3, wn = wid >> 2;
    const uint4* srcA = ((const uint4*)g_whi) + (size_t)m0*32;
    const uint4* srcB = ((const uint4*)g_hhi) + ((size_t)b*TLEN + t0)*32;

    // issue stages 0,1
    #pragma unroll
    for (int s = 0; s < 2; s++){
        uint32_t ab = sb + s*PROJ_STG, bb = ab + 18432;
        for (int i = tid; i < 128*8; i += 256){
            int r = i >> 3, g = i & 7;
            cp16(ab + (uint32_t)(r*PSTR + g*16), srcA + (size_t)r*32 + s*8 + g);
        }
        for (int i = tid; i < 128*8; i += 256){
            int r = i >> 3, g = i & 7;
            cp16(bb + (uint32_t)(r*PSTR + g*16), srcB + (size_t)r*32 + s*8 + g);
        }
        cp_commit();
    }

    uint32_t aoff = (uint32_t)((wm*32 + (lane & 15)) * PSTR + ((lane >> 4) * 8) * 2);
    uint32_t boffc = (uint32_t)((((lane >> 4) * 8) + (lane & 7)) * PSTR
                                + ((lane >> 3) & 1) * 16);

    #pragma unroll
    for (int s = 0; s < 4; s++){
        if (s < 3) cp_waitg1(); else cp_waitg0();
        __syncthreads();
        uint32_t ab = sb + (s & 1)*PROJ_STG, bb = ab + 18432;
        uint32_t aH0 = ab + aoff, aH1 = aH0 + 16*PSTR;
        uint32_t bB[2];
        bB[0] = bb + (uint32_t)((wn*64) * PSTR) + boffc;
        bB[1] = bb + (uint32_t)((wn*64 + 32) * PSTR) + boffc;

        #pragma unroll
        for (int k16 = 0; k16 < 4; k16++){
            uint32_t ko = (uint32_t)(k16 * 32);
            uint32_t Ah[2][4];
            ldm4(Ah[0], aH0 + ko); ldm4(Ah[1], aH1 + ko);
            #pragma unroll
            for (int hf = 0; hf < 2; hf++){
                uint32_t Bh[2][4];
                ldm4(Bh[0], bB[hf] + ko); ldm4(Bh[1], bB[hf] + 16*PSTR + ko);
                #pragma unroll
                for (int mt = 0; mt < 2; mt++){
                    #pragma unroll
                    for (int nt = 0; nt < 4; nt++){
                        uint32_t h0 = Bh[nt>>1][(nt&1)*2], h1 = Bh[nt>>1][(nt&1)*2+1];
                        mma_bf16(acc[mt][hf*4+nt], Ah[mt], h0, h1);
                    }
                }
            }
        }
        __syncthreads();
        if (s < 2){
            int sn = s + 2;
            uint32_t ab2 = sb + (s & 1)*PROJ_STG, bb2 = ab2 + 18432;
            for (int i = tid; i < 128*8; i += 256){
                int r = i >> 3, g = i & 7;
                cp16(ab2 + (uint32_t)(r*PSTR + g*16), srcA + (size_t)r*32 + sn*8 + g);
            }
            for (int i = tid; i < 128*8; i += 256){
                int r = i >> 3, g = i & 7;
                cp16(bb2 + (uint32_t)(r*PSTR + g*16), srcB + (size_t)r*32 + sn*8 + g);
            }
            cp_commit();
        }
    }

    // u -> smem (alias over staging buffers): us[row][t], stride 129 floats
    float* us = (float*)smem;
    #pragma unroll
    for (int mt = 0; mt < 2; mt++){
        #pragma unroll
        for (int g = 0; g < 8; g++){
            int r = wm*32 + mt*16 + (lane >> 2);
            int t = wn*64 + g*8 + (lane & 3)*2;
            #pragma unroll
            for (int hh = 0; hh < 2; hh++){
                int rr = r + hh*8;
                int j = rr & 31;
                int ch = ch0 + (rr >> 5);
                float pb = (j < NJ) ? proj_b[ch*NJ + j] : 0.f;
                us[rr*USTRIDE + t]     = (acc[mt][g][2*hh+0] + pb) * smask[t];
                us[rr*USTRIDE + t + 1] = (acc[mt][g][2*hh+1] + pb) * smask[t+1];
            }
        }
    }
    __syncthreads();

    // --- spline: 4 ch x 128 t = 512 evals, 2 per thread ---
    const float SCALE = 0.0625f;
    int chl = tid >> 6;
    int ch = ch0 + chl;
    float ldsum = 0.f;

    #pragma unroll
    for (int it = 0; it < 2; it++){
        int tl = (tid & 63) + it*64;
        const float* ub = us + (chl*32)*USTRIDE + tl;   // ub[j*USTRIDE]
        float x1v = x[(long)b*CC*TLEN + (long)(HALF + ch)*TLEN + t0 + tl];
        float mv  = smask[tl];

        float uw[10];
        #pragma unroll
        for (int j = 0; j < 10; j++) uw[j] = ub[j*USTRIDE] * SCALE;
        float mx = uw[0];
        #pragma unroll
        for (int j = 1; j < 10; j++) mx = fmaxf(mx, uw[j]);
        float ew[10]; float sw = 0.f;
        #pragma unroll
        for (int j = 0; j < 10; j++){ ew[j] = __expf(uw[j] - mx); sw += ew[j]; }
        float cw[11]; cw[0] = -5.f;
        {
            float inv = __frcp_rn(sw), cs = 0.f;
            #pragma unroll
            for (int j = 0; j < 9; j++){
                cs += fmaf(0.99f, ew[j]*inv, 0.001f);
                cw[j+1] = fmaf(10.f, cs, -5.f);
            }
            cw[10] = 5.f;
        }
        #pragma unroll
        for (int j = 0; j < 10; j++) uw[j] = ub[(10+j)*USTRIDE] * SCALE;
        mx = uw[0];
        #pragma unroll
        for (int j = 1; j < 10; j++) mx = fmaxf(mx, uw[j]);
        sw = 0.f;
        #pragma unroll
        for (int j = 0; j < 10; j++){ ew[j] = __expf(uw[j] - mx); sw += ew[j]; }
        float chh[11]; chh[0] = -5.f;
        {
            float inv = __frcp_rn(sw), cs = 0.f;
            #pragma unroll
            for (int j = 0; j < 9; j++){
                cs += fmaf(0.99f, ew[j]*inv, 0.001f);
                chh[j+1] = fmaf(10.f, cs, -5.f);
            }
            chh[10] = 5.f;
        }

        float xc = fminf(fmaxf(x1v, -5.f), 5.f);
        int idx = 0;
        #pragma unroll
        for (int j = 1; j <= 9; j++) idx += (xc >= cw[j]) ? 1 : 0;

        float cwl = cw[0], cwr = cw[1], chl2 = chh[0], chr = chh[1];
        #pragma unroll
        for (int j = 1; j < 10; j++){
            if (idx == j){ cwl = cw[j]; cwr = cw[j+1]; chl2 = chh[j]; chr = chh[j+1]; }
        }
        float d0 = (idx == 0) ? 1.f : 0.001f + softplus_fast(ub[(19 + idx)*USTRIDE]);
        float d1 = (idx == 9) ? 1.f : 0.001f + softplus_fast(ub[(20 + idx)*USTRIDE]);

        float wb = cwr - cwl, hb = chr - chl2;
        float inv_wb = __frcp_rn(wb);
        float delta = hb * inv_wb;
        float th = (xc - cwl) * inv_wb;
        float omt = 1.f - th;
        float t1m = th * omt;
        float denom = delta + (d0 + d1 - 2.f*delta) * t1m;
        float num = hb * (delta*th*th + d0*t1m);
        float yv = chl2 + num / denom;
        float dnum = delta*delta * (d1*th*th + 2.f*delta*t1m + d0*omt*omt);
        float lad = __logf(dnum) - 2.f*__logf(denom);

        bool inside = (x1v >= -5.f) && (x1v <= 5.f);
        float ov = inside ? yv : x1v;
        ldsum += (inside ? lad : 0.f) * mv;

        out[(long)b*CC*TLEN + (long)(HALF + ch)*TLEN + t0 + tl] = ov * mv;
    }

    // logdet reduction
    #pragma unroll
    for (int off = 16; off; off >>= 1)
        ldsum += __shfl_xor_sync(0xFFFFFFFFu, ldsum, off);
    float* sred = (float*)(smem + OFF_RED);
    if (lane == 0) sred[wid] = ldsum;
    __syncthreads();
    if (tid == 0){
        float s = 0.f;
        #pragma unroll
        for (int k = 0; k < 8; k++) s += sred[k];
        atomicAdd(&out[(long)BB*CC*TLEN + b], s);
    }
}

// ---------------------------------------------------------------------------
extern "C" void kernel_launch(void* const* d_in, const int* in_sizes, int n_in,
                              void* d_out, int out_size){
    const float* x      = (const float*)d_in[0];
    const float* mask   = (const float*)d_in[1];
    const float* pre_w  = (const float*)d_in[2];
    const float* pre_b  = (const float*)d_in[3];
    const float* dw_w   = (const float*)d_in[4];
    const float* dw_b   = (const float*)d_in[5];
    const float* pw_w   = (const float*)d_in[6];
    const float* pw_b   = (const float*)d_in[7];
    const float* gamma1 = (const float*)d_in[8];
    const float* beta1  = (const float*)d_in[9];
    const float* gamma2 = (const float*)d_in[10];
    const float* beta2  = (const float*)d_in[11];
    const float* proj_w = (const float*)d_in[12];
    const float* proj_b = (const float*)d_in[13];
    float* out = (float*)d_out;

    cudaFuncSetAttribute(k_proj_mma, cudaFuncAttributeMaxDynamicSharedMemorySize,
                         PROJ_SMEM_BYTES);
    cudaFuncSetAttribute(k_pw_mma, cudaFuncAttributeMaxDynamicSharedMemorySize,
                         PW_SMEM_BYTES);
    cudaFuncSetAttribute(k_pre_mma, cudaFuncAttributeMaxDynamicSharedMemorySize,
                         PRE_SMEM_BYTES);

    k_prep_w<<<768, 256>>>(proj_w);
    k_prep_pw<<<192, 256>>>(pw_w);
    k_prep_pre<<<96, 256>>>(pre_w);
    k_init<<<dim3(2, HALF, BB), 256>>>(x, mask, out);
    k_pre_mma<<<dim3(TLEN/128, BB), 512, PRE_SMEM_BYTES>>>(x, pre_b);

    int dil = 1;
    for (int i = 0; i < 3; i++){
        k_convnorm<<<dim3(TLEN/4, BB), 256>>>(mask,
                                            dw_w + (long)i*FF*3, dw_b + (long)i*FF,
                                            gamma1 + (long)i*FF, beta1 + (long)i*FF, dil);
        k_pw_mma<<<dim3(TLEN/128, BB), 512, PW_SMEM_BYTES>>>(i,
                                            pw_b + (long)i*FF,
                                            gamma2 + (long)i*FF, beta2 + (long)i*FF,
                                            mask, (i == 2) ? 1 : 0);
        dil *= 3;
    }

    k_proj_mma<<<dim3(TLEN/NT, MROWS/MT, BB), 256, PROJ_SMEM_BYTES>>>(x, mask, proj_b, out);
}